// round 8
// baseline (speedup 1.0000x reference)
#include <cuda_runtime.h>
#include <math.h>

#define B_   32
#define T_   512
#define D_   1024
#define H_   1024
#define R_   64
#define FH   4096
#define NCTA 128

// ---------------- scratch (device globals: allocation-free) ----------------
__device__ __align__(16) float g_xw[(size_t)T_ * FH * B_];   // 256 MB: [t][k][b]
__device__ __align__(16) float g_hs[(size_t)B_ * T_ * H_];   //  64 MB: [b][t][h]
__device__ __align__(16) float g_xa[(size_t)T_ * R_ * B_];   //   4 MB: [t][r][b]
__device__ __align__(16) float g_hT[2][H_ * B_];             // h double buffer [j][b]
__device__ __align__(16) float g_s[R_ * B_];                 // mLSTM s = xa*q  [r][b]
__device__ unsigned g_bar_count = 0;
__device__ unsigned g_bar_gen   = 0;

// ---------------- software grid barrier (grid == NCTA, all resident) -------
__device__ __forceinline__ void grid_sync() {
    __syncthreads();
    if (threadIdx.x == 0) {
        volatile unsigned* vgen = &g_bar_gen;
        unsigned gen = *vgen;
        __threadfence();
        if (atomicAdd(&g_bar_count, 1u) == (unsigned)(gridDim.x - 1)) {
            atomicExch(&g_bar_count, 0u);
            __threadfence();
            atomicAdd(&g_bar_gen, 1u);
        } else {
            while (*vgen == gen) { }
        }
        __threadfence();
    }
    __syncthreads();
}

__device__ __forceinline__ float sigmoidf_(float x) {
    return 1.0f / (1.0f + __expf(-x));
}

// ---------------- feedforward GEMM: out[t][k][b] = bias[k] + sum_d X[b][t][d]*W[k][d]
// X = external x (use_hs=0) or g_hs (use_hs=1). out = g_xw (out_sel=0) or g_xa (1).
__global__ void __launch_bounds__(128) ffn_gemm(
    const float* __restrict__ Xext, int use_hs,
    const float* __restrict__ W, const float* __restrict__ bias,
    int Nk, int out_sel)
{
    const float* X  = use_hs ? g_hs : Xext;
    float*      out = out_sel ? g_xa : g_xw;

    const int t  = blockIdx.y;
    const int k0 = blockIdx.x * 64;

    __shared__ __align__(16) float sX[32][36];   // [d][b], padded row for 16B align
    __shared__ __align__(16) float sW[32][68];   // [d][k]

    const int tid = threadIdx.x;
    const int b4  = (tid & 7) * 4;
    const int k4  = (tid >> 3) * 4;

    float acc[4][4];
#pragma unroll
    for (int i = 0; i < 4; i++)
#pragma unroll
        for (int jx = 0; jx < 4; jx++) acc[i][jx] = 0.f;

    for (int d0 = 0; d0 < 1024; d0 += 32) {
#pragma unroll
        for (int i = 0; i < 2; i++) {                 // 32b x 32d of X
            int qq = tid + i * 128;
            int br = qq >> 3, ds = (qq & 7) * 4;
            float4 v = *(const float4*)(X + ((size_t)br * T_ + t) * 1024 + d0 + ds);
            sX[ds + 0][br] = v.x; sX[ds + 1][br] = v.y;
            sX[ds + 2][br] = v.z; sX[ds + 3][br] = v.w;
        }
#pragma unroll
        for (int i = 0; i < 4; i++) {                 // 64k x 32d of W
            int qq = tid + i * 128;
            int kr = qq >> 3, ds = (qq & 7) * 4;
            float4 v = *(const float4*)(W + (size_t)(k0 + kr) * 1024 + d0 + ds);
            sW[ds + 0][kr] = v.x; sW[ds + 1][kr] = v.y;
            sW[ds + 2][kr] = v.z; sW[ds + 3][kr] = v.w;
        }
        __syncthreads();
#pragma unroll
        for (int d = 0; d < 32; d++) {
            float4 xv = *(const float4*)&sX[d][b4];
            float4 wv = *(const float4*)&sW[d][k4];
            float xs[4] = {xv.x, xv.y, xv.z, xv.w};
            float ws[4] = {wv.x, wv.y, wv.z, wv.w};
#pragma unroll
            for (int i = 0; i < 4; i++)
#pragma unroll
                for (int jx = 0; jx < 4; jx++)
                    acc[i][jx] = fmaf(ws[i], xs[jx], acc[i][jx]);
        }
        __syncthreads();
    }
#pragma unroll
    for (int i = 0; i < 4; i++) {
        float bb = bias ? __ldg(&bias[k0 + k4 + i]) : 0.f;
        float4 r = make_float4(acc[i][0] + bb, acc[i][1] + bb,
                               acc[i][2] + bb, acc[i][3] + bb);
        *(float4*)(out + ((size_t)t * Nk + (k0 + k4 + i)) * B_ + b4) = r;
    }
}

// ---------------- sLSTM scan: persistent, 128 CTAs x 256 thr, warp = one j --
__global__ void __launch_bounds__(256, 1) slstm_scan(
    const float* __restrict__ U, const float* __restrict__ bU,
    const float* __restrict__ alpha)
{
    const int tid = threadIdx.x, w = tid >> 5, lane = tid & 31;
    const int j = blockIdx.x * 8 + w;
    __shared__ __align__(16) float sh[256 * B_];

    __stcg(&g_hT[0][blockIdx.x * 256 + tid], 0.f);
    __threadfence();
    grid_sync();

    float c = 0.f;
    const float alph = __ldg(&alpha[j]);
    const float bi = __ldg(&bU[j]),        bf = __ldg(&bU[H_ + j]);
    const float bo = __ldg(&bU[2*H_ + j]), bg = __ldg(&bU[3*H_ + j]);
    const float* Ui = U + (size_t)j * H_;
    const float* Uf = U + (size_t)(H_ + j) * H_;
    const float* Uo = U + (size_t)(2*H_ + j) * H_;
    const float* Ug = U + (size_t)(3*H_ + j) * H_;

    int p = 0;
    for (int t = 0; t < T_; t++) {
        const float* xwt = g_xw + (size_t)t * FH * B_;
        float ai = __ldg(xwt + j * B_ + lane) + bi;
        float af = __ldg(xwt + (H_ + j) * B_ + lane) + bf;
        float ao = __ldg(xwt + (2*H_ + j) * B_ + lane) + bo;
        float ag = __ldg(xwt + (3*H_ + j) * B_ + lane) + bg;

        for (int c0 = 0; c0 < H_; c0 += 256) {
            const float4* src = (const float4*)(&g_hT[p][c0 * B_]);
            float4* dst = (float4*)sh;
#pragma unroll
            for (int i = 0; i < 8; i++)
                dst[tid + i * 256] = __ldcg(src + tid + i * 256);
            __syncthreads();
#pragma unroll 4
            for (int jj = 0; jj < 256; jj += 4) {
                float4 ui = __ldg((const float4*)(Ui + c0 + jj));
                float4 uf = __ldg((const float4*)(Uf + c0 + jj));
                float4 uo = __ldg((const float4*)(Uo + c0 + jj));
                float4 ug = __ldg((const float4*)(Ug + c0 + jj));
                float h0 = sh[(jj + 0) * B_ + lane];
                float h1 = sh[(jj + 1) * B_ + lane];
                float h2 = sh[(jj + 2) * B_ + lane];
                float h3 = sh[(jj + 3) * B_ + lane];
                ai = fmaf(ui.x, h0, ai); ai = fmaf(ui.y, h1, ai);
                ai = fmaf(ui.z, h2, ai); ai = fmaf(ui.w, h3, ai);
                af = fmaf(uf.x, h0, af); af = fmaf(uf.y, h1, af);
                af = fmaf(uf.z, h2, af); af = fmaf(uf.w, h3, af);
                ao = fmaf(uo.x, h0, ao); ao = fmaf(uo.y, h1, ao);
                ao = fmaf(uo.z, h2, ao); ao = fmaf(uo.w, h3, ao);
                ag = fmaf(ug.x, h0, ag); ag = fmaf(ug.y, h1, ag);
                ag = fmaf(ug.z, h2, ag); ag = fmaf(ug.w, h3, ag);
            }
            __syncthreads();
        }
        float iv = sigmoidf_(ai), fv = sigmoidf_(af), ov = sigmoidf_(ao);
        float gv = tanhf(ag);
        c = alph * (fv * c + iv * gv);
        float h = ov * tanhf(c);
        __stcg(&g_hT[p ^ 1][j * B_ + lane], h);
        g_hs[((size_t)lane * T_ + t) * H_ + j] = h;
        __threadfence();
        grid_sync();
        p ^= 1;
    }
}

// ---------------- mLSTM scan: same + low-rank mix (2 barriers/step) --------
__global__ void __launch_bounds__(256, 1) mlstm_scan(
    const float* __restrict__ U, const float* __restrict__ bU,
    const float* __restrict__ Bm, const float* __restrict__ P,
    float* __restrict__ out)
{
    const int tid = threadIdx.x, w = tid >> 5, lane = tid & 31;
    const int j = blockIdx.x * 8 + w;
    const int rq = blockIdx.x & 63;      // this CTA's r-row of q
    const int bh = blockIdx.x >> 6;      // batch half (0/1)
    __shared__ __align__(16) float sh[256 * B_];
    __shared__ float shq[256];

    __stcg(&g_hT[0][blockIdx.x * 256 + tid], 0.f);
    __threadfence();
    grid_sync();

    float c = 0.f;
    const float bi = __ldg(&bU[j]),        bf = __ldg(&bU[H_ + j]);
    const float bo = __ldg(&bU[2*H_ + j]), bg = __ldg(&bU[3*H_ + j]);
    const float* Ui = U + (size_t)j * H_;
    const float* Uf = U + (size_t)(H_ + j) * H_;
    const float* Uo = U + (size_t)(2*H_ + j) * H_;
    const float* Ug = U + (size_t)(3*H_ + j) * H_;
    const float* Bmr = Bm + (size_t)rq * H_;
    const float* Pj  = P + (size_t)j * R_;
    const int bq  = bh * 16 + (tid & 15);
    const int seg = tid >> 4;            // valid for tid<128: 0..7 (32 jj each)

    int p = 0;
    for (int t = 0; t < T_; t++) {
        const float* xwt = g_xw + (size_t)t * FH * B_;
        float ai = __ldg(xwt + j * B_ + lane) + bi;
        float af = __ldg(xwt + (H_ + j) * B_ + lane) + bf;
        float ao = __ldg(xwt + (2*H_ + j) * B_ + lane) + bo;
        float ag = __ldg(xwt + (3*H_ + j) * B_ + lane) + bg;
        float qpart = 0.f;

        for (int c0 = 0; c0 < H_; c0 += 256) {
            const float4* src = (const float4*)(&g_hT[p][c0 * B_]);
            float4* dst = (float4*)sh;
#pragma unroll
            for (int i = 0; i < 8; i++)
                dst[tid + i * 256] = __ldcg(src + tid + i * 256);
            __syncthreads();
#pragma unroll 4
            for (int jj = 0; jj < 256; jj += 4) {
                float4 ui = __ldg((const float4*)(Ui + c0 + jj));
                float4 uf = __ldg((const float4*)(Uf + c0 + jj));
                float4 uo = __ldg((const float4*)(Uo + c0 + jj));
                float4 ug = __ldg((const float4*)(Ug + c0 + jj));
                float h0 = sh[(jj + 0) * B_ + lane];
                float h1 = sh[(jj + 1) * B_ + lane];
                float h2 = sh[(jj + 2) * B_ + lane];
                float h3 = sh[(jj + 3) * B_ + lane];
                ai = fmaf(ui.x, h0, ai); ai = fmaf(ui.y, h1, ai);
                ai = fmaf(ui.z, h2, ai); ai = fmaf(ui.w, h3, ai);
                af = fmaf(uf.x, h0, af); af = fmaf(uf.y, h1, af);
                af = fmaf(uf.z, h2, af); af = fmaf(uf.w, h3, af);
                ao = fmaf(uo.x, h0, ao); ao = fmaf(uo.y, h1, ao);
                ao = fmaf(uo.z, h2, ao); ao = fmaf(uo.w, h3, ao);
                ag = fmaf(ug.x, h0, ag); ag = fmaf(ug.y, h1, ag);
                ag = fmaf(ug.z, h2, ag); ag = fmaf(ug.w, h3, ag);
            }
            if (tid < 128) {             // q[bq][rq] partial over this chunk
                const float* bmrow = Bmr + c0 + seg * 32;
#pragma unroll
                for (int e = 0; e < 32; e += 4) {
                    float4 bm = __ldg((const float4*)(bmrow + e));
                    int base = (seg * 32 + e) * B_ + bq;
                    qpart = fmaf(bm.x, sh[base          ], qpart);
                    qpart = fmaf(bm.y, sh[base +     B_ ], qpart);
                    qpart = fmaf(bm.z, sh[base + 2 * B_ ], qpart);
                    qpart = fmaf(bm.w, sh[base + 3 * B_ ], qpart);
                }
            }
            __syncthreads();
        }
        // gates (before smem reuse)
        float iv = sigmoidf_(ai), fv = sigmoidf_(af), ov = sigmoidf_(ao);
        float gv = tanhf(ag);

        // reduce q, compute s = xa * q, publish
        shq[tid] = qpart;
        __syncthreads();
        if (tid < 16) {
            float q = 0.f;
#pragma unroll
            for (int s2 = 0; s2 < 8; s2++) q += shq[tid + 16 * s2];
            int bb = bh * 16 + tid;
            float xav = __ldg(&g_xa[((size_t)t * R_ + rq) * B_ + bb]);
            __stcg(&g_s[rq * B_ + bb], xav * q);
        }
        __threadfence();
        grid_sync();

        // phase B: mix = s @ P^T on this warp's j
        {
            float4* d4 = (float4*)sh;
            const float4* s4 = (const float4*)g_s;
            d4[tid]       = __ldcg(s4 + tid);
            d4[tid + 256] = __ldcg(s4 + tid + 256);
            __syncthreads();
        }
        float mix = 0.f;
#pragma unroll
        for (int r = 0; r < R_; r += 4) {
            float4 pv = __ldg((const float4*)(Pj + r));
            mix = fmaf(pv.x, sh[(r + 0) * B_ + lane], mix);
            mix = fmaf(pv.y, sh[(r + 1) * B_ + lane], mix);
            mix = fmaf(pv.z, sh[(r + 2) * B_ + lane], mix);
            mix = fmaf(pv.w, sh[(r + 3) * B_ + lane], mix);
        }
        c = fv * c + iv * gv + 0.1f * mix;
        float h = ov * tanhf(c);
        __stcg(&g_hT[p ^ 1][j * B_ + lane], h);
        out[((size_t)lane * T_ + t) * H_ + j] = h;
        __threadfence();
        grid_sync();
        p ^= 1;
    }
}

// ---------------- launch -----------------------------------------------------
extern "C" void kernel_launch(void* const* d_in, const int* in_sizes, int n_in,
                              void* d_out, int out_size)
{
    (void)in_sizes; (void)n_in; (void)out_size;
    const float* x     = (const float*)d_in[0];
    const float* Ws    = (const float*)d_in[1];
    const float* bWs   = (const float*)d_in[2];
    const float* Us    = (const float*)d_in[3];
    const float* bUs   = (const float*)d_in[4];
    const float* alpha = (const float*)d_in[5];
    const float* Wm    = (const float*)d_in[6];
    const float* bWm   = (const float*)d_in[7];
    const float* Um    = (const float*)d_in[8];
    const float* bUm   = (const float*)d_in[9];
    const float* A     = (const float*)d_in[10];
    const float* Bm    = (const float*)d_in[11];
    const float* P     = (const float*)d_in[12];

    dim3 gBig(FH / 64, T_);
    ffn_gemm<<<gBig, 128>>>(x, 0, Ws, bWs, FH, 0);            // xw (sLSTM)
    slstm_scan<<<NCTA, 256>>>(Us, bUs, alpha);                 // -> g_hs
    ffn_gemm<<<gBig, 128>>>(nullptr, 1, Wm, bWm, FH, 0);       // xw (mLSTM)
    ffn_gemm<<<dim3(1, T_), 128>>>(nullptr, 1, A, nullptr, R_, 1); // xa
    mlstm_scan<<<NCTA, 256>>>(Um, bUm, Bm, P, (float*)d_out);  // -> out
}

// round 9
// speedup vs baseline: 1.4399x; 1.4399x over previous
#include <cuda_runtime.h>
#include <math.h>

#define B_   32
#define T_   512
#define D_   1024
#define H_   1024
#define R_   64
#define FH   4096
#define NCTA 128

// ---------------- scratch (device globals: allocation-free) ----------------
__device__ __align__(16) float g_xw[(size_t)T_ * FH * B_];   // 256 MB: [t][k][b]
__device__ __align__(16) float g_hs[(size_t)B_ * T_ * H_];   //  64 MB: [b][t][h]
__device__ __align__(16) float g_xa[(size_t)T_ * R_ * B_];   //   4 MB: [t][r][b]
__device__ __align__(16) float g_hT[2][H_ * B_];             // h double buffer [j][b]
__device__ __align__(16) float g_s[R_ * B_];                 // mLSTM s = xa*q  [r][b]
__device__ unsigned g_bar_count = 0;
__device__ unsigned g_bar_gen   = 0;

// ---------------- software grid barrier (grid == NCTA, all resident) -------
__device__ __forceinline__ void grid_sync() {
    __syncthreads();
    if (threadIdx.x == 0) {
        volatile unsigned* vgen = &g_bar_gen;
        unsigned gen = *vgen;
        __threadfence();
        if (atomicAdd(&g_bar_count, 1u) == (unsigned)(gridDim.x - 1)) {
            atomicExch(&g_bar_count, 0u);
            __threadfence();
            atomicAdd(&g_bar_gen, 1u);
        } else {
            while (*vgen == gen) { }
        }
        __threadfence();
    }
    __syncthreads();
}

__device__ __forceinline__ float sigmoidf_(float x) {
    return 1.0f / (1.0f + __expf(-x));
}
__device__ __forceinline__ float tanhf_(float x) {
    // 1 - 2/(e^{2x}+1): monotone, saturates correctly for |x| large
    float e = __expf(2.0f * x);
    return 1.0f - 2.0f / (e + 1.0f);
}

// ============================================================================
// Big feedforward GEMM: out[t][k][b] = bias[k] + sum_d X[b][t][d] * W[k][d]
// BM=32 (all b), BN=256 (k), BK=16, 256 threads, double-buffered smem.
// Thread tile: 1 b x 32 k (warp-uniform B fragments). Output is b-coalesced.
// ============================================================================
__global__ void __launch_bounds__(256) ffn_gemm2(
    const float* __restrict__ Xext, int use_hs,
    const float* __restrict__ W, const float* __restrict__ bias)
{
    const float* X = use_hs ? g_hs : Xext;
    const int t  = blockIdx.y;
    const int k0 = blockIdx.x * 256;

    __shared__ __align__(16) float As[2][16][34];    // [buf][d][b]
    __shared__ __align__(16) float Bs[2][16][260];   // [buf][d][k]

    const int tid  = threadIdx.x;
    const int lane = tid & 31;            // b
    const int wkg  = tid >> 5;            // 0..7 -> k slice wkg*32

    // staging maps
    const int bA  = (tid >> 2) & 31;      // tid<128: b row
    const int dqA = tid & 3;
    const int krb = tid >> 2;             // 0..63
    const int dqB = tid & 3;

    const float* Xrow = X + ((size_t)bA * T_ + t) * 1024;

    float4 rA;
    float4 rB[4];

    // ---- load stage 0
    if (tid < 128) rA = *(const float4*)(Xrow + dqA * 4);
#pragma unroll
    for (int i = 0; i < 4; i++)
        rB[i] = *(const float4*)(W + (size_t)(k0 + krb + i * 64) * 1024 + dqB * 4);

    // store stage 0
    if (tid < 128) {
        As[0][dqA * 4 + 0][bA] = rA.x; As[0][dqA * 4 + 1][bA] = rA.y;
        As[0][dqA * 4 + 2][bA] = rA.z; As[0][dqA * 4 + 3][bA] = rA.w;
    }
#pragma unroll
    for (int i = 0; i < 4; i++) {
        Bs[0][dqB * 4 + 0][krb + i * 64] = rB[i].x;
        Bs[0][dqB * 4 + 1][krb + i * 64] = rB[i].y;
        Bs[0][dqB * 4 + 2][krb + i * 64] = rB[i].z;
        Bs[0][dqB * 4 + 3][krb + i * 64] = rB[i].w;
    }
    __syncthreads();

    float acc[32];
#pragma unroll
    for (int i = 0; i < 32; i++) acc[i] = 0.f;

    for (int s = 0; s < 64; s++) {
        const int cur = s & 1;
        const int d0n = (s + 1) * 16;
        if (s < 63) {
            if (tid < 128) rA = *(const float4*)(Xrow + d0n + dqA * 4);
#pragma unroll
            for (int i = 0; i < 4; i++)
                rB[i] = *(const float4*)(W + (size_t)(k0 + krb + i * 64) * 1024 + d0n + dqB * 4);
        }
#pragma unroll
        for (int d = 0; d < 16; d++) {
            float av = As[cur][d][lane];
            const float* brow = &Bs[cur][d][wkg * 32];
            float4 q0 = *(const float4*)(brow +  0);
            float4 q1 = *(const float4*)(brow +  4);
            float4 q2 = *(const float4*)(brow +  8);
            float4 q3 = *(const float4*)(brow + 12);
            float4 q4 = *(const float4*)(brow + 16);
            float4 q5 = *(const float4*)(brow + 20);
            float4 q6 = *(const float4*)(brow + 24);
            float4 q7 = *(const float4*)(brow + 28);
            acc[ 0] = fmaf(av, q0.x, acc[ 0]); acc[ 1] = fmaf(av, q0.y, acc[ 1]);
            acc[ 2] = fmaf(av, q0.z, acc[ 2]); acc[ 3] = fmaf(av, q0.w, acc[ 3]);
            acc[ 4] = fmaf(av, q1.x, acc[ 4]); acc[ 5] = fmaf(av, q1.y, acc[ 5]);
            acc[ 6] = fmaf(av, q1.z, acc[ 6]); acc[ 7] = fmaf(av, q1.w, acc[ 7]);
            acc[ 8] = fmaf(av, q2.x, acc[ 8]); acc[ 9] = fmaf(av, q2.y, acc[ 9]);
            acc[10] = fmaf(av, q2.z, acc[10]); acc[11] = fmaf(av, q2.w, acc[11]);
            acc[12] = fmaf(av, q3.x, acc[12]); acc[13] = fmaf(av, q3.y, acc[13]);
            acc[14] = fmaf(av, q3.z, acc[14]); acc[15] = fmaf(av, q3.w, acc[15]);
            acc[16] = fmaf(av, q4.x, acc[16]); acc[17] = fmaf(av, q4.y, acc[17]);
            acc[18] = fmaf(av, q4.z, acc[18]); acc[19] = fmaf(av, q4.w, acc[19]);
            acc[20] = fmaf(av, q5.x, acc[20]); acc[21] = fmaf(av, q5.y, acc[21]);
            acc[22] = fmaf(av, q5.z, acc[22]); acc[23] = fmaf(av, q5.w, acc[23]);
            acc[24] = fmaf(av, q6.x, acc[24]); acc[25] = fmaf(av, q6.y, acc[25]);
            acc[26] = fmaf(av, q6.z, acc[26]); acc[27] = fmaf(av, q6.w, acc[27]);
            acc[28] = fmaf(av, q7.x, acc[28]); acc[29] = fmaf(av, q7.y, acc[29]);
            acc[30] = fmaf(av, q7.z, acc[30]); acc[31] = fmaf(av, q7.w, acc[31]);
        }
        if (s < 63) {
            const int nxt = cur ^ 1;
            if (tid < 128) {
                As[nxt][dqA * 4 + 0][bA] = rA.x; As[nxt][dqA * 4 + 1][bA] = rA.y;
                As[nxt][dqA * 4 + 2][bA] = rA.z; As[nxt][dqA * 4 + 3][bA] = rA.w;
            }
#pragma unroll
            for (int i = 0; i < 4; i++) {
                Bs[nxt][dqB * 4 + 0][krb + i * 64] = rB[i].x;
                Bs[nxt][dqB * 4 + 1][krb + i * 64] = rB[i].y;
                Bs[nxt][dqB * 4 + 2][krb + i * 64] = rB[i].z;
                Bs[nxt][dqB * 4 + 3][krb + i * 64] = rB[i].w;
            }
            __syncthreads();
        }
    }

    // epilogue: b-coalesced stores into [t][k][b]
#pragma unroll
    for (int kk = 0; kk < 32; kk++) {
        int k = k0 + wkg * 32 + kk;
        g_xw[((size_t)t * FH + k) * B_ + lane] = acc[kk] + __ldg(&bias[k]);
    }
}

// ---------------- small GEMM for xa (Nk=64): out[t][r][b] -------------------
__global__ void __launch_bounds__(128) xa_gemm(
    const float* __restrict__ A)
{
    const float* X = g_hs;
    float* out = g_xa;
    const int t = blockIdx.y;

    __shared__ __align__(16) float sX[32][36];
    __shared__ __align__(16) float sW[32][68];

    const int tid = threadIdx.x;
    const int b4  = (tid & 7) * 4;
    const int k4  = (tid >> 3) * 4;

    float acc[4][4];
#pragma unroll
    for (int i = 0; i < 4; i++)
#pragma unroll
        for (int jx = 0; jx < 4; jx++) acc[i][jx] = 0.f;

    for (int d0 = 0; d0 < 1024; d0 += 32) {
#pragma unroll
        for (int i = 0; i < 2; i++) {
            int qq = tid + i * 128;
            int br = qq >> 3, ds = (qq & 7) * 4;
            float4 v = *(const float4*)(X + ((size_t)br * T_ + t) * 1024 + d0 + ds);
            sX[ds + 0][br] = v.x; sX[ds + 1][br] = v.y;
            sX[ds + 2][br] = v.z; sX[ds + 3][br] = v.w;
        }
#pragma unroll
        for (int i = 0; i < 4; i++) {
            int qq = tid + i * 128;
            int kr = qq >> 3, ds = (qq & 7) * 4;
            float4 v = *(const float4*)(A + (size_t)kr * 1024 + d0 + ds);
            sW[ds + 0][kr] = v.x; sW[ds + 1][kr] = v.y;
            sW[ds + 2][kr] = v.z; sW[ds + 3][kr] = v.w;
        }
        __syncthreads();
#pragma unroll
        for (int d = 0; d < 32; d++) {
            float4 xv = *(const float4*)&sX[d][b4];
            float4 wv = *(const float4*)&sW[d][k4];
            float xs[4] = {xv.x, xv.y, xv.z, xv.w};
            float ws[4] = {wv.x, wv.y, wv.z, wv.w};
#pragma unroll
            for (int i = 0; i < 4; i++)
#pragma unroll
                for (int jx = 0; jx < 4; jx++)
                    acc[i][jx] = fmaf(ws[i], xs[jx], acc[i][jx]);
        }
        __syncthreads();
    }
#pragma unroll
    for (int i = 0; i < 4; i++) {
        float4 r = make_float4(acc[i][0], acc[i][1], acc[i][2], acc[i][3]);
        *(float4*)(out + ((size_t)t * R_ + (k4 + i)) * B_ + b4) = r;
    }
}

// ============================================================================
// sLSTM scan v2: 128 CTAs x 512 thr. Warp = (j, gate-pair). gsel=0: {i,f},
// gsel=1: {o,g}. Register-prefetched h staging; gate exchange via smem.
// ============================================================================
__global__ void __launch_bounds__(512, 1) slstm_scan(
    const float* __restrict__ U, const float* __restrict__ bU,
    const float* __restrict__ alpha)
{
    const int tid = threadIdx.x, w = tid >> 5, lane = tid & 31;
    const int jl = w >> 1, gsel = w & 1;
    const int j = blockIdx.x * 8 + jl;

    __shared__ __align__(16) float sh[256 * B_];     // 32 KB chunk [jj][b]
    __shared__ float ex[8][2][32];

    int gid = blockIdx.x * 512 + tid;
    if (gid < H_ * B_) __stcg(&g_hT[0][gid], 0.f);
    __threadfence();
    grid_sync();

    const int r0 = gsel ? (2 * H_ + j) : j;
    const int r1 = gsel ? (3 * H_ + j) : (H_ + j);
    const float bb0 = __ldg(&bU[r0]);
    const float bb1 = __ldg(&bU[r1]);
    const float* Ua = U + (size_t)r0 * H_;
    const float* Ub = U + (size_t)r1 * H_;
    const float alph = __ldg(&alpha[j]);

    float c = 0.f;
    int p = 0;
    for (int t = 0; t < T_; t++) {
        const float* xwt = g_xw + (size_t)t * FH * B_;
        float a0 = __ldg(xwt + r0 * B_ + lane) + bb0;
        float a1 = __ldg(xwt + r1 * B_ + lane) + bb1;

        const float4* hsrc = (const float4*)(&g_hT[p][0]);
        float4 rg[4];
#pragma unroll
        for (int i = 0; i < 4; i++) rg[i] = __ldcg(hsrc + tid + i * 512);

        for (int c0 = 0; c0 < 4; c0++) {
            __syncthreads();
            float4* d4 = (float4*)sh;
#pragma unroll
            for (int i = 0; i < 4; i++) d4[tid + i * 512] = rg[i];
            __syncthreads();
            if (c0 < 3) {
#pragma unroll
                for (int i = 0; i < 4; i++)
                    rg[i] = __ldcg(hsrc + (c0 + 1) * 2048 + tid + i * 512);
            }
            const float* UA = Ua + c0 * 256;
            const float* UB = Ub + c0 * 256;
#pragma unroll 4
            for (int jj = 0; jj < 256; jj += 4) {
                float4 u0 = __ldg((const float4*)(UA + jj));
                float4 u1 = __ldg((const float4*)(UB + jj));
                float h0 = sh[(jj + 0) * B_ + lane];
                float h1 = sh[(jj + 1) * B_ + lane];
                float h2 = sh[(jj + 2) * B_ + lane];
                float h3 = sh[(jj + 3) * B_ + lane];
                a0 = fmaf(u0.x, h0, a0); a0 = fmaf(u0.y, h1, a0);
                a0 = fmaf(u0.z, h2, a0); a0 = fmaf(u0.w, h3, a0);
                a1 = fmaf(u1.x, h0, a1); a1 = fmaf(u1.y, h1, a1);
                a1 = fmaf(u1.z, h2, a1); a1 = fmaf(u1.w, h3, a1);
            }
        }
        if (gsel) { ex[jl][0][lane] = a0; ex[jl][1][lane] = a1; }
        __syncthreads();
        if (!gsel) {
            float iv = sigmoidf_(a0), fv = sigmoidf_(a1);
            float ov = sigmoidf_(ex[jl][0][lane]);
            float gv = tanhf_(ex[jl][1][lane]);
            c = alph * (fv * c + iv * gv);
            float h = ov * tanhf_(c);
            __stcg(&g_hT[p ^ 1][j * B_ + lane], h);
            g_hs[((size_t)lane * T_ + t) * H_ + j] = h;
        }
        __threadfence();
        grid_sync();
        p ^= 1;
    }
}

// ============================================================================
// mLSTM scan v2: same structure + low-rank mix (2 grid barriers per step)
// ============================================================================
__global__ void __launch_bounds__(512, 1) mlstm_scan(
    const float* __restrict__ U, const float* __restrict__ bU,
    const float* __restrict__ Bm, const float* __restrict__ P,
    float* __restrict__ out)
{
    const int tid = threadIdx.x, w = tid >> 5, lane = tid & 31;
    const int jl = w >> 1, gsel = w & 1;
    const int j = blockIdx.x * 8 + jl;
    const int rq = blockIdx.x & 63;       // this CTA's r-row of q
    const int bh = blockIdx.x >> 6;       // batch half (0/1)

    __shared__ __align__(16) float sh[256 * B_];
    __shared__ float ex[8][2][32];
    __shared__ float shq[128];

    int gid = blockIdx.x * 512 + tid;
    if (gid < H_ * B_) __stcg(&g_hT[0][gid], 0.f);
    __threadfence();
    grid_sync();

    const int r0 = gsel ? (2 * H_ + j) : j;
    const int r1 = gsel ? (3 * H_ + j) : (H_ + j);
    const float bb0 = __ldg(&bU[r0]);
    const float bb1 = __ldg(&bU[r1]);
    const float* Ua = U + (size_t)r0 * H_;
    const float* Ub = U + (size_t)r1 * H_;
    const float* Bmr = Bm + (size_t)rq * H_;
    const float* Pj  = P + (size_t)j * R_;
    const int bq  = bh * 16 + (tid & 15);
    const int seg = tid >> 4;             // tid<128: 0..7

    float c = 0.f;
    int p = 0;
    for (int t = 0; t < T_; t++) {
        const float* xwt = g_xw + (size_t)t * FH * B_;
        float a0 = __ldg(xwt + r0 * B_ + lane) + bb0;
        float a1 = __ldg(xwt + r1 * B_ + lane) + bb1;
        float qpart = 0.f;

        const float4* hsrc = (const float4*)(&g_hT[p][0]);
        float4 rg[4];
#pragma unroll
        for (int i = 0; i < 4; i++) rg[i] = __ldcg(hsrc + tid + i * 512);

        for (int c0 = 0; c0 < 4; c0++) {
            __syncthreads();
            float4* d4 = (float4*)sh;
#pragma unroll
            for (int i = 0; i < 4; i++) d4[tid + i * 512] = rg[i];
            __syncthreads();
            if (c0 < 3) {
#pragma unroll
                for (int i = 0; i < 4; i++)
                    rg[i] = __ldcg(hsrc + (c0 + 1) * 2048 + tid + i * 512);
            }
            const float* UA = Ua + c0 * 256;
            const float* UB = Ub + c0 * 256;
#pragma unroll 4
            for (int jj = 0; jj < 256; jj += 4) {
                float4 u0 = __ldg((const float4*)(UA + jj));
                float4 u1 = __ldg((const float4*)(UB + jj));
                float h0 = sh[(jj + 0) * B_ + lane];
                float h1 = sh[(jj + 1) * B_ + lane];
                float h2 = sh[(jj + 2) * B_ + lane];
                float h3 = sh[(jj + 3) * B_ + lane];
                a0 = fmaf(u0.x, h0, a0); a0 = fmaf(u0.y, h1, a0);
                a0 = fmaf(u0.z, h2, a0); a0 = fmaf(u0.w, h3, a0);
                a1 = fmaf(u1.x, h0, a1); a1 = fmaf(u1.y, h1, a1);
                a1 = fmaf(u1.z, h2, a1); a1 = fmaf(u1.w, h3, a1);
            }
            if (tid < 128) {              // q[bq][rq] partial over this chunk
                const float* bmrow = Bmr + c0 * 256 + seg * 32;
#pragma unroll
                for (int e = 0; e < 32; e += 4) {
                    float4 bm = __ldg((const float4*)(bmrow + e));
                    int base = (seg * 32 + e) * B_ + bq;
                    qpart = fmaf(bm.x, sh[base         ], qpart);
                    qpart = fmaf(bm.y, sh[base +     B_], qpart);
                    qpart = fmaf(bm.z, sh[base + 2 * B_], qpart);
                    qpart = fmaf(bm.w, sh[base + 3 * B_], qpart);
                }
            }
        }
        // publish odd-warp gates + q partials, then chip-wide s
        if (gsel) { ex[jl][0][lane] = a0; ex[jl][1][lane] = a1; }
        if (tid < 128) shq[tid] = qpart;
        __syncthreads();
        if (tid < 16) {
            float q = 0.f;
#pragma unroll
            for (int s2 = 0; s2 < 8; s2++) q += shq[tid + 16 * s2];
            int bb = bh * 16 + tid;
            float xav = __ldg(&g_xa[((size_t)t * R_ + rq) * B_ + bb]);
            __stcg(&g_s[rq * B_ + bb], xav * q);
        }
        __threadfence();
        grid_sync();

        // stage s (2048 floats) into sh, then compute mix + update
        {
            float4* d4 = (float4*)sh;
            d4[tid] = __ldcg(((const float4*)g_s) + tid);
            __syncthreads();
        }
        if (!gsel) {
            float mix = 0.f;
#pragma unroll
            for (int r = 0; r < R_; r += 4) {
                float4 pv = __ldg((const float4*)(Pj + r));
                mix = fmaf(pv.x, sh[(r + 0) * B_ + lane], mix);
                mix = fmaf(pv.y, sh[(r + 1) * B_ + lane], mix);
                mix = fmaf(pv.z, sh[(r + 2) * B_ + lane], mix);
                mix = fmaf(pv.w, sh[(r + 3) * B_ + lane], mix);
            }
            float iv = sigmoidf_(a0), fv = sigmoidf_(a1);
            float ov = sigmoidf_(ex[jl][0][lane]);
            float gv = tanhf_(ex[jl][1][lane]);
            c = fv * c + iv * gv + 0.1f * mix;
            float h = ov * tanhf_(c);
            __stcg(&g_hT[p ^ 1][j * B_ + lane], h);
            out[((size_t)lane * T_ + t) * H_ + j] = h;
        }
        __threadfence();
        grid_sync();
        p ^= 1;
    }
}

// ---------------- launch -----------------------------------------------------
extern "C" void kernel_launch(void* const* d_in, const int* in_sizes, int n_in,
                              void* d_out, int out_size)
{
    (void)in_sizes; (void)n_in; (void)out_size;
    const float* x     = (const float*)d_in[0];
    const float* Ws    = (const float*)d_in[1];
    const float* bWs   = (const float*)d_in[2];
    const float* Us    = (const float*)d_in[3];
    const float* bUs   = (const float*)d_in[4];
    const float* alpha = (const float*)d_in[5];
    const float* Wm    = (const float*)d_in[6];
    const float* bWm   = (const float*)d_in[7];
    const float* Um    = (const float*)d_in[8];
    const float* bUm   = (const float*)d_in[9];
    const float* A     = (const float*)d_in[10];
    const float* Bm    = (const float*)d_in[11];
    const float* P     = (const float*)d_in[12];

    dim3 gBig(FH / 256, T_);
    ffn_gemm2<<<gBig, 256>>>(x, 0, Ws, bWs);              // xw (sLSTM)
    slstm_scan<<<NCTA, 512>>>(Us, bUs, alpha);            // -> g_hs
    ffn_gemm2<<<gBig, 256>>>(nullptr, 1, Wm, bWm);        // xw (mLSTM)
    xa_gemm<<<dim3(1, T_), 128>>>(A);                     // xa
    mlstm_scan<<<NCTA, 512>>>(Um, bUm, Bm, P, (float*)d_out);
}

// round 11
// speedup vs baseline: 2.6040x; 1.8084x over previous
#include <cuda_runtime.h>
#include <math.h>

#define B_   32
#define T_   512
#define D_   1024
#define H_   1024
#define R_   64
#define FH   4096
#define NCTA 128

// dynamic smem layout (floats): U_s[32768] | h_s[16384]  (196608 bytes)
#define SMEM_SCAN_BYTES (49152 * 4)

// ---------------- scratch (device globals: allocation-free) ----------------
__device__ __align__(16) float g_xw[(size_t)T_ * FH * B_];   // 256 MB: [t][k][b]
__device__ __align__(16) float g_hs[(size_t)B_ * T_ * H_];   //  64 MB: [b][t][h]
__device__ __align__(16) float g_xa[(size_t)T_ * R_ * B_];   //   4 MB: [t][r][b]
__device__ __align__(16) float g_hT[2][H_ * B_];             // h double buffer [j][b]
__device__ __align__(16) float g_s[R_ * B_];                 // mLSTM s = xa*q  [r][b]
__device__ unsigned g_bar_count = 0;
__device__ unsigned g_bar_gen   = 0;

// ---------------- software grid barrier (grid == NCTA, all resident) -------
__device__ __forceinline__ void grid_sync() {
    __syncthreads();
    if (threadIdx.x == 0) {
        volatile unsigned* vgen = &g_bar_gen;
        unsigned gen = *vgen;
        __threadfence();
        if (atomicAdd(&g_bar_count, 1u) == (unsigned)(NCTA - 1)) {
            atomicExch(&g_bar_count, 0u);
            __threadfence();
            atomicAdd(&g_bar_gen, 1u);
        } else {
            while (*vgen == gen) { }
        }
        __threadfence();
    }
    __syncthreads();
}

__device__ __forceinline__ float sigmoidf_(float x) {
    return 1.0f / (1.0f + __expf(-x));
}
__device__ __forceinline__ float tanhf_(float x) {
    float e = __expf(2.0f * x);
    return 1.0f - 2.0f / (e + 1.0f);
}

// ============================================================================
// Big feedforward GEMM: out[t][k][b] = bias[k] + sum_d X[b][t][d] * W[k][d]
// BM=32 (all b), BN=256 (k), BK=16, 256 threads, double-buffered smem.
// ============================================================================
__global__ void __launch_bounds__(256) ffn_gemm2(
    const float* __restrict__ Xext, int use_hs,
    const float* __restrict__ W, const float* __restrict__ bias)
{
    const float* X = use_hs ? g_hs : Xext;
    const int t  = blockIdx.y;
    const int k0 = blockIdx.x * 256;

    __shared__ __align__(16) float As[2][16][34];
    __shared__ __align__(16) float Bs[2][16][260];

    const int tid  = threadIdx.x;
    const int lane = tid & 31;
    const int wkg  = tid >> 5;

    const int bA  = (tid >> 2) & 31;
    const int dqA = tid & 3;
    const int krb = tid >> 2;
    const int dqB = tid & 3;

    const float* Xrow = X + ((size_t)bA * T_ + t) * 1024;

    float4 rA;
    float4 rB[4];

    if (tid < 128) rA = *(const float4*)(Xrow + dqA * 4);
#pragma unroll
    for (int i = 0; i < 4; i++)
        rB[i] = *(const float4*)(W + (size_t)(k0 + krb + i * 64) * 1024 + dqB * 4);

    if (tid < 128) {
        As[0][dqA * 4 + 0][bA] = rA.x; As[0][dqA * 4 + 1][bA] = rA.y;
        As[0][dqA * 4 + 2][bA] = rA.z; As[0][dqA * 4 + 3][bA] = rA.w;
    }
#pragma unroll
    for (int i = 0; i < 4; i++) {
        Bs[0][dqB * 4 + 0][krb + i * 64] = rB[i].x;
        Bs[0][dqB * 4 + 1][krb + i * 64] = rB[i].y;
        Bs[0][dqB * 4 + 2][krb + i * 64] = rB[i].z;
        Bs[0][dqB * 4 + 3][krb + i * 64] = rB[i].w;
    }
    __syncthreads();

    float acc[32];
#pragma unroll
    for (int i = 0; i < 32; i++) acc[i] = 0.f;

    for (int s = 0; s < 64; s++) {
        const int cur = s & 1;
        const int d0n = (s + 1) * 16;
        if (s < 63) {
            if (tid < 128) rA = *(const float4*)(Xrow + d0n + dqA * 4);
#pragma unroll
            for (int i = 0; i < 4; i++)
                rB[i] = *(const float4*)(W + (size_t)(k0 + krb + i * 64) * 1024 + d0n + dqB * 4);
        }
#pragma unroll
        for (int d = 0; d < 16; d++) {
            float av = As[cur][d][lane];
            const float* brow = &Bs[cur][d][wkg * 32];
            float4 q0 = *(const float4*)(brow +  0);
            float4 q1 = *(const float4*)(brow +  4);
            float4 q2 = *(const float4*)(brow +  8);
            float4 q3 = *(const float4*)(brow + 12);
            float4 q4 = *(const float4*)(brow + 16);
            float4 q5 = *(const float4*)(brow + 20);
            float4 q6 = *(const float4*)(brow + 24);
            float4 q7 = *(const float4*)(brow + 28);
            acc[ 0] = fmaf(av, q0.x, acc[ 0]); acc[ 1] = fmaf(av, q0.y, acc[ 1]);
            acc[ 2] = fmaf(av, q0.z, acc[ 2]); acc[ 3] = fmaf(av, q0.w, acc[ 3]);
            acc[ 4] = fmaf(av, q1.x, acc[ 4]); acc[ 5] = fmaf(av, q1.y, acc[ 5]);
            acc[ 6] = fmaf(av, q1.z, acc[ 6]); acc[ 7] = fmaf(av, q1.w, acc[ 7]);
            acc[ 8] = fmaf(av, q2.x, acc[ 8]); acc[ 9] = fmaf(av, q2.y, acc[ 9]);
            acc[10] = fmaf(av, q2.z, acc[10]); acc[11] = fmaf(av, q2.w, acc[11]);
            acc[12] = fmaf(av, q3.x, acc[12]); acc[13] = fmaf(av, q3.y, acc[13]);
            acc[14] = fmaf(av, q3.z, acc[14]); acc[15] = fmaf(av, q3.w, acc[15]);
            acc[16] = fmaf(av, q4.x, acc[16]); acc[17] = fmaf(av, q4.y, acc[17]);
            acc[18] = fmaf(av, q4.z, acc[18]); acc[19] = fmaf(av, q4.w, acc[19]);
            acc[20] = fmaf(av, q5.x, acc[20]); acc[21] = fmaf(av, q5.y, acc[21]);
            acc[22] = fmaf(av, q5.z, acc[22]); acc[23] = fmaf(av, q5.w, acc[23]);
            acc[24] = fmaf(av, q6.x, acc[24]); acc[25] = fmaf(av, q6.y, acc[25]);
            acc[26] = fmaf(av, q6.z, acc[26]); acc[27] = fmaf(av, q6.w, acc[27]);
            acc[28] = fmaf(av, q7.x, acc[28]); acc[29] = fmaf(av, q7.y, acc[29]);
            acc[30] = fmaf(av, q7.z, acc[30]); acc[31] = fmaf(av, q7.w, acc[31]);
        }
        if (s < 63) {
            const int nxt = cur ^ 1;
            if (tid < 128) {
                As[nxt][dqA * 4 + 0][bA] = rA.x; As[nxt][dqA * 4 + 1][bA] = rA.y;
                As[nxt][dqA * 4 + 2][bA] = rA.z; As[nxt][dqA * 4 + 3][bA] = rA.w;
            }
#pragma unroll
            for (int i = 0; i < 4; i++) {
                Bs[nxt][dqB * 4 + 0][krb + i * 64] = rB[i].x;
                Bs[nxt][dqB * 4 + 1][krb + i * 64] = rB[i].y;
                Bs[nxt][dqB * 4 + 2][krb + i * 64] = rB[i].z;
                Bs[nxt][dqB * 4 + 3][krb + i * 64] = rB[i].w;
            }
            __syncthreads();
        }
    }

#pragma unroll
    for (int kk = 0; kk < 32; kk++) {
        int k = k0 + wkg * 32 + kk;
        g_xw[((size_t)t * FH + k) * B_ + lane] = acc[kk] + __ldg(&bias[k]);
    }
}

// ---------------- small GEMM for xa: out[t][r][b] ---------------------------
__global__ void __launch_bounds__(128) xa_gemm(const float* __restrict__ A)
{
    const float* X = g_hs;
    float* out = g_xa;
    const int t = blockIdx.y;

    __shared__ __align__(16) float sX[32][36];
    __shared__ __align__(16) float sW[32][68];

    const int tid = threadIdx.x;
    const int b4  = (tid & 7) * 4;
    const int k4  = (tid >> 3) * 4;

    float acc[4][4];
#pragma unroll
    for (int i = 0; i < 4; i++)
#pragma unroll
        for (int jx = 0; jx < 4; jx++) acc[i][jx] = 0.f;

    for (int d0 = 0; d0 < 1024; d0 += 32) {
#pragma unroll
        for (int i = 0; i < 2; i++) {
            int qq = tid + i * 128;
            int br = qq >> 3, ds = (qq & 7) * 4;
            float4 v = *(const float4*)(X + ((size_t)br * T_ + t) * 1024 + d0 + ds);
            sX[ds + 0][br] = v.x; sX[ds + 1][br] = v.y;
            sX[ds + 2][br] = v.z; sX[ds + 3][br] = v.w;
        }
#pragma unroll
        for (int i = 0; i < 4; i++) {
            int qq = tid + i * 128;
            int kr = qq >> 3, ds = (qq & 7) * 4;
            float4 v = *(const float4*)(A + (size_t)kr * 1024 + d0 + ds);
            sW[ds + 0][kr] = v.x; sW[ds + 1][kr] = v.y;
            sW[ds + 2][kr] = v.z; sW[ds + 3][kr] = v.w;
        }
        __syncthreads();
#pragma unroll
        for (int d = 0; d < 32; d++) {
            float4 xv = *(const float4*)&sX[d][b4];
            float4 wv = *(const float4*)&sW[d][k4];
            float xs[4] = {xv.x, xv.y, xv.z, xv.w};
            float ws[4] = {wv.x, wv.y, wv.z, wv.w};
#pragma unroll
            for (int i = 0; i < 4; i++)
#pragma unroll
                for (int jx = 0; jx < 4; jx++)
                    acc[i][jx] = fmaf(ws[i], xs[jx], acc[i][jx]);
        }
        __syncthreads();
    }
#pragma unroll
    for (int i = 0; i < 4; i++) {
        float4 r = make_float4(acc[i][0], acc[i][1], acc[i][2], acc[i][3]);
        *(float4*)(out + ((size_t)t * R_ + (k4 + i)) * B_ + b4) = r;
    }
}

// ============================================================================
// Scan v3 helpers (U resident in smem, register-tiled 4x4, K-split 8)
// thread: ks = tid>>6 (K-split), ty = (tid>>3)&7 (row-quad), tx = tid&7 (b-quad)
// U_s[k*32 + rowidx] where rowidx = jl*4 + gate; h_s[kloc*32 + b]
// red (aliases h_s): red[(ks*32+row)*33 + b]
// ============================================================================
#define FMA16(u, hv)                                                     \
    acc[0][0] = fmaf(u.x, hv.x, acc[0][0]);                              \
    acc[0][1] = fmaf(u.x, hv.y, acc[0][1]);                              \
    acc[0][2] = fmaf(u.x, hv.z, acc[0][2]);                              \
    acc[0][3] = fmaf(u.x, hv.w, acc[0][3]);                              \
    acc[1][0] = fmaf(u.y, hv.x, acc[1][0]);                              \
    acc[1][1] = fmaf(u.y, hv.y, acc[1][1]);                              \
    acc[1][2] = fmaf(u.y, hv.z, acc[1][2]);                              \
    acc[1][3] = fmaf(u.y, hv.w, acc[1][3]);                              \
    acc[2][0] = fmaf(u.z, hv.x, acc[2][0]);                              \
    acc[2][1] = fmaf(u.z, hv.y, acc[2][1]);                              \
    acc[2][2] = fmaf(u.z, hv.z, acc[2][2]);                              \
    acc[2][3] = fmaf(u.z, hv.w, acc[2][3]);                              \
    acc[3][0] = fmaf(u.w, hv.x, acc[3][0]);                              \
    acc[3][1] = fmaf(u.w, hv.y, acc[3][1]);                              \
    acc[3][2] = fmaf(u.w, hv.z, acc[3][2]);                              \
    acc[3][3] = fmaf(u.w, hv.w, acc[3][3]);

// load U (transposed) into smem once: U_s[k*32 + rowidx]
__device__ __forceinline__ void load_U_smem(float* U_s, const float* U, int jb, int tid) {
    const int row = tid & 31;
    const int g = row & 3, jl = row >> 2;
    const float* Urow = U + (size_t)(g * H_ + jb + jl) * H_;
    for (int k0 = (tid >> 5) * 4; k0 < H_; k0 += 64) {
        float4 v = *(const float4*)(Urow + k0);
        U_s[(k0 + 0) * 32 + row] = v.x;
        U_s[(k0 + 1) * 32 + row] = v.y;
        U_s[(k0 + 2) * 32 + row] = v.z;
        U_s[(k0 + 3) * 32 + row] = v.w;
    }
}

// ============================================================================
// sLSTM scan v3
// ============================================================================
__global__ void __launch_bounds__(512, 1) slstm_scan(
    const float* __restrict__ U, const float* __restrict__ bU,
    const float* __restrict__ alpha)
{
    extern __shared__ __align__(16) float smem_dyn[];
    float* U_s = smem_dyn;           // 32768 floats
    float* h_s = smem_dyn + 32768;   // 16384 floats (chunk of 512 k)
    float* red = h_s;                // alias (8448 floats)

    const int tid = threadIdx.x;
    const int ks = tid >> 6, ty = (tid >> 3) & 7, tx = tid & 7;
    const int jb = blockIdx.x * 8;

    load_U_smem(U_s, U, jb, tid);

    int gid = blockIdx.x * 512 + tid;
    if (gid < H_ * B_) __stcg(&g_hT[0][gid], 0.f);
    __threadfence();
    grid_sync();

    // state threads (tid<256): sj = j-local, sb = b
    const int sj = tid >> 5, sb = tid & 31;
    const int jglob = jb + sj;
    float c = 0.f;
    float balph = 0.f, bi = 0.f, bf = 0.f, bo = 0.f, bg = 0.f;
    if (tid < 256) {
        balph = __ldg(&alpha[jglob]);
        bi = __ldg(&bU[jglob]);
        bf = __ldg(&bU[H_ + jglob]);
        bo = __ldg(&bU[2 * H_ + jglob]);
        bg = __ldg(&bU[3 * H_ + jglob]);
    }

    int p = 0;
    for (int t = 0; t < T_; t++) {
        float xi = 0.f, xf = 0.f, xo = 0.f, xg = 0.f;
        if (tid < 256) {
            const float* xwt = g_xw + (size_t)t * FH * B_;
            xi = __ldg(xwt + (size_t)jglob * B_ + sb);
            xf = __ldg(xwt + (size_t)(H_ + jglob) * B_ + sb);
            xo = __ldg(xwt + (size_t)(2 * H_ + jglob) * B_ + sb);
            xg = __ldg(xwt + (size_t)(3 * H_ + jglob) * B_ + sb);
        }

        const float4* hsrc = (const float4*)(&g_hT[p][0]);
        float4 rg[8];
#pragma unroll
        for (int i = 0; i < 8; i++) rg[i] = __ldcg(hsrc + tid + i * 512);
        {
            float4* d4 = (float4*)h_s;
#pragma unroll
            for (int i = 0; i < 8; i++) d4[tid + i * 512] = rg[i];
        }
        __syncthreads();
#pragma unroll
        for (int i = 0; i < 8; i++) rg[i] = __ldcg(hsrc + 4096 + tid + i * 512);

        float acc[4][4];
#pragma unroll
        for (int i = 0; i < 4; i++)
#pragma unroll
            for (int jx = 0; jx < 4; jx++) acc[i][jx] = 0.f;

        // chunk 0
        {
            const float* Ub = U_s + (size_t)(ks * 64) * 32 + 4 * ty;
            const float* Hb = h_s + (size_t)(ks * 64) * 32 + 4 * tx;
#pragma unroll 8
            for (int kk = 0; kk < 64; kk++) {
                float4 u  = *(const float4*)(Ub + kk * 32);
                float4 hv = *(const float4*)(Hb + kk * 32);
                FMA16(u, hv)
            }
        }
        __syncthreads();
        {
            float4* d4 = (float4*)h_s;
#pragma unroll
            for (int i = 0; i < 8; i++) d4[tid + i * 512] = rg[i];
        }
        __syncthreads();
        // chunk 1
        {
            const float* Ub = U_s + (size_t)(512 + ks * 64) * 32 + 4 * ty;
            const float* Hb = h_s + (size_t)(ks * 64) * 32 + 4 * tx;
#pragma unroll 8
            for (int kk = 0; kk < 64; kk++) {
                float4 u  = *(const float4*)(Ub + kk * 32);
                float4 hv = *(const float4*)(Hb + kk * 32);
                FMA16(u, hv)
            }
        }
        __syncthreads();
        // write partials
#pragma unroll
        for (int i = 0; i < 4; i++) {
            float* rr = red + (size_t)(ks * 32 + 4 * ty + i) * 33 + 4 * tx;
            rr[0] = acc[i][0]; rr[1] = acc[i][1];
            rr[2] = acc[i][2]; rr[3] = acc[i][3];
        }
        __syncthreads();
        if (tid < 256) {
            float s0 = 0.f, s1 = 0.f, s2 = 0.f, s3 = 0.f;
#pragma unroll
            for (int k2 = 0; k2 < 8; k2++) {
                const float* rr = red + (size_t)k2 * 32 * 33 + sb;
                s0 += rr[(sj * 4 + 0) * 33];
                s1 += rr[(sj * 4 + 1) * 33];
                s2 += rr[(sj * 4 + 2) * 33];
                s3 += rr[(sj * 4 + 3) * 33];
            }
            float iv = sigmoidf_(xi + bi + s0);
            float fv = sigmoidf_(xf + bf + s1);
            float ov = sigmoidf_(xo + bo + s2);
            float gv = tanhf_(xg + bg + s3);
            c = balph * (fv * c + iv * gv);
            float h = ov * tanhf_(c);
            __stcg(&g_hT[p ^ 1][jglob * B_ + sb], h);
            g_hs[((size_t)sb * T_ + t) * H_ + jglob] = h;
        }
        __threadfence();
        grid_sync();
        p ^= 1;
    }
}

// ============================================================================
// mLSTM scan v3: + low-rank mix (q folded into chunk loop; 2 barriers/step)
// ============================================================================
__global__ void __launch_bounds__(512, 1) mlstm_scan(
    const float* __restrict__ U, const float* __restrict__ bU,
    const float* __restrict__ Bm, const float* __restrict__ P,
    float* __restrict__ out)
{
    extern __shared__ __align__(16) float smem_dyn[];
    float* U_s = smem_dyn;
    float* h_s = smem_dyn + 32768;
    float* red = h_s;
    float* s_s = h_s;                // alias (2048 floats, after barrier)

    __shared__ float Bm_s[1024];
    __shared__ float q_s[8][16];

    const int tid = threadIdx.x;
    const int ks = tid >> 6, ty = (tid >> 3) & 7, tx = tid & 7;
    const int jb = blockIdx.x * 8;
    const int rq = blockIdx.x & 63;       // this CTA's r-row of q
    const int bh = blockIdx.x >> 6;       // batch half

    load_U_smem(U_s, U, jb, tid);
    // stage this CTA's Bm row
    {
        const float* Bmr = Bm + (size_t)rq * H_;
        for (int i = tid; i < 256; i += 512)
            *(float4*)&Bm_s[i * 4] = __ldg((const float4*)(Bmr + i * 4));
    }

    int gid = blockIdx.x * 512 + tid;
    if (gid < H_ * B_) __stcg(&g_hT[0][gid], 0.f);
    __threadfence();
    grid_sync();

    const int sj = tid >> 5, sb = tid & 31;
    const int jglob = jb + sj;
    float c = 0.f;
    float bi = 0.f, bf = 0.f, bo = 0.f, bg = 0.f;
    if (tid < 256) {
        bi = __ldg(&bU[jglob]);
        bf = __ldg(&bU[H_ + jglob]);
        bo = __ldg(&bU[2 * H_ + jglob]);
        bg = __ldg(&bU[3 * H_ + jglob]);
    }
    const float* Pj = P + (size_t)jglob * R_;
    // q threads (tid<128): qb = batch index (within half), qk = k-segment
    const int qb = tid & 15, qk = tid >> 4;

    int p = 0;
    for (int t = 0; t < T_; t++) {
        float xi = 0.f, xf = 0.f, xo = 0.f, xg = 0.f;
        if (tid < 256) {
            const float* xwt = g_xw + (size_t)t * FH * B_;
            xi = __ldg(xwt + (size_t)jglob * B_ + sb);
            xf = __ldg(xwt + (size_t)(H_ + jglob) * B_ + sb);
            xo = __ldg(xwt + (size_t)(2 * H_ + jglob) * B_ + sb);
            xg = __ldg(xwt + (size_t)(3 * H_ + jglob) * B_ + sb);
        }

        const float4* hsrc = (const float4*)(&g_hT[p][0]);
        float4 rg[8];
#pragma unroll
        for (int i = 0; i < 8; i++) rg[i] = __ldcg(hsrc + tid + i * 512);
        {
            float4* d4 = (float4*)h_s;
#pragma unroll
            for (int i = 0; i < 8; i++) d4[tid + i * 512] = rg[i];
        }
        __syncthreads();
#pragma unroll
        for (int i = 0; i < 8; i++) rg[i] = __ldcg(hsrc + 4096 + tid + i * 512);

        float acc[4][4];
#pragma unroll
        for (int i = 0; i < 4; i++)
#pragma unroll
            for (int jx = 0; jx < 4; jx++) acc[i][jx] = 0.f;
        float qpart = 0.f;

        // chunk 0
        {
            const float* Ub = U_s + (size_t)(ks * 64) * 32 + 4 * ty;
            const float* Hb = h_s + (size_t)(ks * 64) * 32 + 4 * tx;
#pragma unroll 8
            for (int kk = 0; kk < 64; kk++) {
                float4 u  = *(const float4*)(Ub + kk * 32);
                float4 hv = *(const float4*)(Hb + kk * 32);
                FMA16(u, hv)
            }
        }
        if (tid < 128) {                   // q partial on chunk 0
            const int bcol = bh * 16 + qb;
#pragma unroll 4
            for (int k4 = 0; k4 < 64; k4 += 4) {
                float4 bm = *(const float4*)&Bm_s[qk * 64 + k4];
                const float* hb = h_s + (size_t)(qk * 64 + k4) * 32 + bcol;
                qpart = fmaf(bm.x, hb[0],  qpart);
                qpart = fmaf(bm.y, hb[32], qpart);
                qpart = fmaf(bm.z, hb[64], qpart);
                qpart = fmaf(bm.w, hb[96], qpart);
            }
        }
        __syncthreads();
        {
            float4* d4 = (float4*)h_s;
#pragma unroll
            for (int i = 0; i < 8; i++) d4[tid + i * 512] = rg[i];
        }
        __syncthreads();
        // chunk 1
        {
            const float* Ub = U_s + (size_t)(512 + ks * 64) * 32 + 4 * ty;
            const float* Hb = h_s + (size_t)(ks * 64) * 32 + 4 * tx;
#pragma unroll 8
            for (int kk = 0; kk < 64; kk++) {
                float4 u  = *(const float4*)(Ub + kk * 32);
                float4 hv = *(const float4*)(Hb + kk * 32);
                FMA16(u, hv)
            }
        }
        if (tid < 128) {                   // q partial on chunk 1
            const int bcol = bh * 16 + qb;
#pragma unroll 4
            for (int k4 = 0; k4 < 64; k4 += 4) {
                float4 bm = *(const float4*)&Bm_s[512 + qk * 64 + k4];
                const float* hb = h_s + (size_t)(qk * 64 + k4) * 32 + bcol;
                qpart = fmaf(bm.x, hb[0],  qpart);
                qpart = fmaf(bm.y, hb[32], qpart);
                qpart = fmaf(bm.z, hb[64], qpart);
                qpart = fmaf(bm.w, hb[96], qpart);
            }
        }
        __syncthreads();
        // write partials + q
#pragma unroll
        for (int i = 0; i < 4; i++) {
            float* rr = red + (size_t)(ks * 32 + 4 * ty + i) * 33 + 4 * tx;
            rr[0] = acc[i][0]; rr[1] = acc[i][1];
            rr[2] = acc[i][2]; rr[3] = acc[i][3];
        }
        if (tid < 128) q_s[qk][qb] = qpart;
        __syncthreads();

        // gate pre-activations (kept in regs across the barrier)
        float a0 = 0.f, a1 = 0.f, a2 = 0.f, a3 = 0.f;
        if (tid < 256) {
#pragma unroll
            for (int k2 = 0; k2 < 8; k2++) {
                const float* rr = red + (size_t)k2 * 32 * 33 + sb;
                a0 += rr[(sj * 4 + 0) * 33];
                a1 += rr[(sj * 4 + 1) * 33];
                a2 += rr[(sj * 4 + 2) * 33];
                a3 += rr[(sj * 4 + 3) * 33];
            }
            a0 += xi + bi; a1 += xf + bf; a2 += xo + bo; a3 += xg + bg;
        }
        if (tid < 16) {
            float q = 0.f;
#pragma unroll
            for (int s2 = 0; s2 < 8; s2++) q += q_s[s2][tid];
            int bb = bh * 16 + tid;
            float xav = __ldg(&g_xa[((size_t)t * R_ + rq) * B_ + bb]);
            __stcg(&g_s[rq * B_ + bb], xav * q);
        }
        __threadfence();
        grid_sync();

        // stage s (2048 floats) and compute mix + update
        ((float4*)s_s)[tid] = __ldcg(((const float4*)g_s) + tid);
        __syncthreads();
        if (tid < 256) {
            float mix = 0.f;
#pragma unroll
            for (int r = 0; r < R_; r += 4) {
                float4 pv = __ldg((const float4*)(Pj + r));
                mix = fmaf(pv.x, s_s[(r + 0) * B_ + sb], mix);
                mix = fmaf(pv.y, s_s[(r + 1) * B_ + sb], mix);
                mix = fmaf(pv.z, s_s[(r + 2) * B_ + sb], mix);
                mix = fmaf(pv.w, s_s[(r + 3) * B_ + sb], mix);
            }
            float iv = sigmoidf_(a0), fv = sigmoidf_(a1);
            float ov = sigmoidf_(a2), gv = tanhf_(a3);
            c = fv * c + iv * gv + 0.1f * mix;
            float h = ov * tanhf_(c);
            __stcg(&g_hT[p ^ 1][jglob * B_ + sb], h);
            out[((size_t)sb * T_ + t) * H_ + jglob] = h;
        }
        __threadfence();
        grid_sync();
        p ^= 1;
    }
}

// ---------------- launch -----------------------------------------------------
extern "C" void kernel_launch(void* const* d_in, const int* in_sizes, int n_in,
                              void* d_out, int out_size)
{
    (void)in_sizes; (void)n_in; (void)out_size;
    const float* x     = (const float*)d_in[0];
    const float* Ws    = (const float*)d_in[1];
    const float* bWs   = (const float*)d_in[2];
    const float* Us    = (const float*)d_in[3];
    const float* bUs   = (const float*)d_in[4];
    const float* alpha = (const float*)d_in[5];
    const float* Wm    = (const float*)d_in[6];
    const float* bWm   = (const float*)d_in[7];
    const float* Um    = (const float*)d_in[8];
    const float* bUm   = (const float*)d_in[9];
    const float* A     = (const float*)d_in[10];
    const float* Bm    = (const float*)d_in[11];
    const float* P     = (const float*)d_in[12];

    cudaError_t e1 = cudaFuncSetAttribute(
        slstm_scan, cudaFuncAttributeMaxDynamicSharedMemorySize, SMEM_SCAN_BYTES);
    cudaError_t e2 = cudaFuncSetAttribute(
        mlstm_scan, cudaFuncAttributeMaxDynamicSharedMemorySize, SMEM_SCAN_BYTES);
    (void)e1; (void)e2;

    dim3 gBig(FH / 256, T_);
    ffn_gemm2<<<gBig, 256>>>(x, 0, Ws, bWs);                    // xw (sLSTM)
    slstm_scan<<<NCTA, 512, SMEM_SCAN_BYTES>>>(Us, bUs, alpha); // -> g_hs
    xa_gemm<<<dim3(1, T_), 128>>>(A);                           // xa
    ffn_gemm2<<<gBig, 256>>>(nullptr, 1, Wm, bWm);              // xw (mLSTM)
    mlstm_scan<<<NCTA, 512, SMEM_SCAN_BYTES>>>(Um, bUm, Bm, P, (float*)d_out);
}

// round 13
// speedup vs baseline: 3.5573x; 1.3661x over previous
#include <cuda_runtime.h>
#include <cuda_bf16.h>
#include <math.h>
#include <stdint.h>

#define B_   32
#define T_   512
#define D_   1024
#define H_   1024
#define R_   64
#define FH   4096
#define NCTA 128

// scan dynamic smem (floats): U_s[32768] | h_s[16384]
#define SMEM_SCAN_BYTES (49152 * 4)
// mma gemm dynamic smem: 2 buffers x 32 KB
#define SMEM_GEMM_BYTES 65536

// ---------------- scratch (device globals: allocation-free) ----------------
__device__ __align__(16) float g_xw[(size_t)T_ * FH * B_];   // [t][k][b]
__device__ __align__(16) float g_hs[(size_t)B_ * T_ * H_];   // [b][t][h]
__device__ __align__(16) float g_xa[(size_t)T_ * R_ * B_];   // [t][r][b]
__device__ __align__(16) float g_hT[2][H_ * B_];             // h dbl buf [j][b]
__device__ __align__(16) float g_s[R_ * B_];                 // [r][b]
__device__ unsigned g_bar_count = 0;
__device__ unsigned g_bar_gen   = 0;

// ---------------- software grid barrier (scan kernels, grid == NCTA) -------
__device__ __forceinline__ void grid_sync() {
    __syncthreads();
    if (threadIdx.x == 0) {
        volatile unsigned* vgen = &g_bar_gen;
        unsigned gen = *vgen;
        __threadfence();
        if (atomicAdd(&g_bar_count, 1u) == (unsigned)(NCTA - 1)) {
            atomicExch(&g_bar_count, 0u);
            __threadfence();
            atomicAdd(&g_bar_gen, 1u);
        } else {
            while (*vgen == gen) { }
        }
        __threadfence();
    }
    __syncthreads();
}

__device__ __forceinline__ float sigmoidf_(float x) {
    return 1.0f / (1.0f + __expf(-x));
}
__device__ __forceinline__ float tanhf_(float x) {
    float e = __expf(2.0f * x);
    return 1.0f - 2.0f / (e + 1.0f);
}

// ---- fp32 -> bf16 hi/lo split (packed bf16x2; x -> low half, y -> high) ----
__device__ __forceinline__ void split2(float x, float y, uint32_t& hp, uint32_t& lp) {
    uint32_t h;
    asm("cvt.rn.bf16x2.f32 %0, %1, %2;" : "=r"(h) : "f"(y), "f"(x));
    float xh = __uint_as_float(h << 16);
    float yh = __uint_as_float(h & 0xFFFF0000u);
    float xl = x - xh, yl = y - yh;
    uint32_t l;
    asm("cvt.rn.bf16x2.f32 %0, %1, %2;" : "=r"(l) : "f"(yl), "f"(xl));
    hp = h; lp = l;
}

// ---- warp mma m16n8k16 bf16, fp32 accumulate ----
__device__ __forceinline__ void mma_bf16(float* c, const uint32_t* a, const uint32_t* b) {
    asm volatile(
        "mma.sync.aligned.m16n8k16.row.col.f32.bf16.bf16.f32 "
        "{%0,%1,%2,%3}, {%4,%5,%6,%7}, {%8,%9}, {%0,%1,%2,%3};"
        : "+f"(c[0]), "+f"(c[1]), "+f"(c[2]), "+f"(c[3])
        : "r"(a[0]), "r"(a[1]), "r"(a[2]), "r"(a[3]), "r"(b[0]), "r"(b[1]));
}

// ============================================================================
// HMMA feedforward GEMM: g_xw[t][k][b] = bias[k] + X2d[m] . W[k],  m = t*32+b
// CTA tile 128m x 128n, BK=32, 8 warps (2m x 4n), warp tile 64x32.
// bf16 hi/lo split, 3 products, fp32 accum. Smem holds fragments directly:
//   per buffer (u32): AH[2048] | AL[2048] | BH[2048] | BL[2048]  (32 KB)
//   A slot: ((ktile*8+mtile)*4 + reg)*32 + lane      (reg = (row>=8) + 2*(k>=8))
//   B slot: 4096 + ((ktile*16+ntile)*2 + reg)*32 + lane  (reg = (k>=8))
// ============================================================================
__global__ void __launch_bounds__(256, 1) ffn_gemm_mma(
    const float* __restrict__ Aext, int a_is_hs,
    const float* __restrict__ W, const float* __restrict__ bias)
{
    extern __shared__ __align__(16) uint32_t smemu[];
    const float* A0 = a_is_hs ? g_hs : Aext;

    const int tid = threadIdx.x;
    const int wid = tid >> 5, lane = tid & 31;
    const int n0 = blockIdx.x * 128;
    const int m0 = blockIdx.y * 128;
    const int wm = wid >> 2, wn = wid & 3;

    // ---- staging role: tid<128 stages A row tid; tid>=128 stages B row tid-128
    const int isB = (tid >= 128);
    const int r   = isB ? (tid - 128) : tid;
    const float* srow;
    if (isB) {
        srow = W + (size_t)(n0 + r) * 1024;
    } else {
        int m = m0 + r;
        srow = A0 + ((size_t)(m & 31) * T_ + (m >> 5)) * 1024;
    }
    uint32_t sts_off[4];
#pragma unroll
    for (int k2 = 0; k2 < 4; k2++) {
        int ktile = k2 >> 1, kb = k2 & 1;
        if (isB) {
            int ntile = r >> 3, g = r & 7;
            sts_off[k2] = 4096u + (uint32_t)(((ktile * 16 + ntile) * 2 + kb) * 32 + g * 4);
        } else {
            int mtile = r >> 4, gp = r & 15;
            int rb0 = gp >> 3, g = gp & 7;
            sts_off[k2] = (uint32_t)(((ktile * 8 + mtile) * 4 + rb0 + 2 * kb) * 32 + g * 4);
        }
    }

    // ---- prologue: stage chunk 0 into buffer 0
    {
#pragma unroll
        for (int k2 = 0; k2 < 4; k2++) {
            float4 v0 = __ldg((const float4*)(srow + k2 * 8));
            float4 v1 = __ldg((const float4*)(srow + k2 * 8 + 4));
            uint32_t h0, h1, h2, h3, l0, l1, l2, l3;
            split2(v0.x, v0.y, h0, l0); split2(v0.z, v0.w, h1, l1);
            split2(v1.x, v1.y, h2, l2); split2(v1.z, v1.w, h3, l3);
            uint32_t* q = smemu + sts_off[k2];
            *(uint4*)q            = make_uint4(h0, h1, h2, h3);
            *(uint4*)(q + 2048)   = make_uint4(l0, l1, l2, l3);
        }
    }
    __syncthreads();

    float acc[4][4][4];
#pragma unroll
    for (int mt = 0; mt < 4; mt++)
#pragma unroll
        for (int nt = 0; nt < 4; nt++)
#pragma unroll
            for (int e = 0; e < 4; e++) acc[mt][nt][e] = 0.f;

    for (int c = 0; c < 32; c++) {
        const uint32_t* buf = smemu + (c & 1) * 8192;
        float4 pend[8];
        if (c < 31) {
            const float* sp = srow + (c + 1) * 32;
#pragma unroll
            for (int k2 = 0; k2 < 4; k2++) {
                pend[2 * k2]     = __ldg((const float4*)(sp + k2 * 8));
                pend[2 * k2 + 1] = __ldg((const float4*)(sp + k2 * 8 + 4));
            }
        }
        // ---- compute: 2 k-tiles of 16
#pragma unroll
        for (int kt = 0; kt < 2; kt++) {
            uint32_t aH[4][4], aL[4][4], bH[4][2], bL[4][2];
#pragma unroll
            for (int mt = 0; mt < 4; mt++) {
                const uint32_t* p = buf + ((kt * 8 + wm * 4 + mt) * 4) * 32 + lane;
#pragma unroll
                for (int rr = 0; rr < 4; rr++) {
                    aH[mt][rr] = p[rr * 32];
                    aL[mt][rr] = p[rr * 32 + 2048];
                }
            }
#pragma unroll
            for (int nt = 0; nt < 4; nt++) {
                const uint32_t* p = buf + 4096 + ((kt * 16 + wn * 4 + nt) * 2) * 32 + lane;
                bH[nt][0] = p[0];    bH[nt][1] = p[32];
                bL[nt][0] = p[2048]; bL[nt][1] = p[2080];
            }
#pragma unroll
            for (int mt = 0; mt < 4; mt++)
#pragma unroll
                for (int nt = 0; nt < 4; nt++) {
                    mma_bf16(acc[mt][nt], aH[mt], bH[nt]);
                    mma_bf16(acc[mt][nt], aH[mt], bL[nt]);
                    mma_bf16(acc[mt][nt], aL[mt], bH[nt]);
                }
        }
        // ---- convert + store chunk c+1 into the other buffer
        if (c < 31) {
            uint32_t* nb = smemu + ((c + 1) & 1) * 8192;
#pragma unroll
            for (int k2 = 0; k2 < 4; k2++) {
                uint32_t h0, h1, h2, h3, l0, l1, l2, l3;
                split2(pend[2*k2].x,   pend[2*k2].y,   h0, l0);
                split2(pend[2*k2].z,   pend[2*k2].w,   h1, l1);
                split2(pend[2*k2+1].x, pend[2*k2+1].y, h2, l2);
                split2(pend[2*k2+1].z, pend[2*k2+1].w, h3, l3);
                uint32_t* q = nb + sts_off[k2];
                *(uint4*)q          = make_uint4(h0, h1, h2, h3);
                *(uint4*)(q + 2048) = make_uint4(l0, l1, l2, l3);
            }
        }
        __syncthreads();
    }

    // ---- epilogue: acc[mt][nt] c-fragment -> g_xw[t][k][b] + bias
    const int g = lane >> 2, cc = lane & 3;
#pragma unroll
    for (int mt = 0; mt < 4; mt++) {
#pragma unroll
        for (int nt = 0; nt < 4; nt++) {
            int mA = m0 + wm * 64 + mt * 16 + g;
            int mB = mA + 8;
            int k0 = n0 + wn * 32 + nt * 8 + 2 * cc;
            float b0 = __ldg(&bias[k0]);
            float b1 = __ldg(&bias[k0 + 1]);
            size_t oA = ((size_t)(mA >> 5) * FH) * B_ + (mA & 31);
            size_t oB = ((size_t)(mB >> 5) * FH) * B_ + (mB & 31);
            g_xw[oA + (size_t)k0 * B_]       = acc[mt][nt][0] + b0;
            g_xw[oA + (size_t)(k0 + 1) * B_] = acc[mt][nt][1] + b1;
            g_xw[oB + (size_t)k0 * B_]       = acc[mt][nt][2] + b0;
            g_xw[oB + (size_t)(k0 + 1) * B_] = acc[mt][nt][3] + b1;
        }
    }
}

// ---------------- small GEMM for xa: out[t][r][b] (fp32) --------------------
__global__ void __launch_bounds__(128) xa_gemm(const float* __restrict__ A)
{
    const float* X = g_hs;
    float* out = g_xa;
    const int t = blockIdx.y;

    __shared__ __align__(16) float sX[32][36];
    __shared__ __align__(16) float sW[32][68];

    const int tid = threadIdx.x;
    const int b4  = (tid & 7) * 4;
    const int k4  = (tid >> 3) * 4;

    float acc[4][4];
#pragma unroll
    for (int i = 0; i < 4; i++)
#pragma unroll
        for (int jx = 0; jx < 4; jx++) acc[i][jx] = 0.f;

    for (int d0 = 0; d0 < 1024; d0 += 32) {
#pragma unroll
        for (int i = 0; i < 2; i++) {
            int qq = tid + i * 128;
            int br = qq >> 3, ds = (qq & 7) * 4;
            float4 v = *(const float4*)(X + ((size_t)br * T_ + t) * 1024 + d0 + ds);
            sX[ds + 0][br] = v.x; sX[ds + 1][br] = v.y;
            sX[ds + 2][br] = v.z; sX[ds + 3][br] = v.w;
        }
#pragma unroll
        for (int i = 0; i < 4; i++) {
            int qq = tid + i * 128;
            int kr = qq >> 3, ds = (qq & 7) * 4;
            float4 v = *(const float4*)(A + (size_t)kr * 1024 + d0 + ds);
            sW[ds + 0][kr] = v.x; sW[ds + 1][kr] = v.y;
            sW[ds + 2][kr] = v.z; sW[ds + 3][kr] = v.w;
        }
        __syncthreads();
#pragma unroll
        for (int d = 0; d < 32; d++) {
            float4 xv = *(const float4*)&sX[d][b4];
            float4 wv = *(const float4*)&sW[d][k4];
            float xs[4] = {xv.x, xv.y, xv.z, xv.w};
            float ws[4] = {wv.x, wv.y, wv.z, wv.w};
#pragma unroll
            for (int i = 0; i < 4; i++)
#pragma unroll
                for (int jx = 0; jx < 4; jx++)
                    acc[i][jx] = fmaf(ws[i], xs[jx], acc[i][jx]);
        }
        __syncthreads();
    }
#pragma unroll
    for (int i = 0; i < 4; i++) {
        float4 r = make_float4(acc[i][0], acc[i][1], acc[i][2], acc[i][3]);
        *(float4*)(out + ((size_t)t * R_ + (k4 + i)) * B_ + b4) = r;
    }
}

// ============================================================================
// Scan v3 (R11, passing): U resident in smem, reg-tiled 4x4, K-split 8
// ============================================================================
#define FMA16(u, hv)                                                     \
    acc[0][0] = fmaf(u.x, hv.x, acc[0][0]);                              \
    acc[0][1] = fmaf(u.x, hv.y, acc[0][1]);                              \
    acc[0][2] = fmaf(u.x, hv.z, acc[0][2]);                              \
    acc[0][3] = fmaf(u.x, hv.w, acc[0][3]);                              \
    acc[1][0] = fmaf(u.y, hv.x, acc[1][0]);                              \
    acc[1][1] = fmaf(u.y, hv.y, acc[1][1]);                              \
    acc[1][2] = fmaf(u.y, hv.z, acc[1][2]);                              \
    acc[1][3] = fmaf(u.y, hv.w, acc[1][3]);                              \
    acc[2][0] = fmaf(u.z, hv.x, acc[2][0]);                              \
    acc[2][1] = fmaf(u.z, hv.y, acc[2][1]);                              \
    acc[2][2] = fmaf(u.z, hv.z, acc[2][2]);                              \
    acc[2][3] = fmaf(u.z, hv.w, acc[2][3]);                              \
    acc[3][0] = fmaf(u.w, hv.x, acc[3][0]);                              \
    acc[3][1] = fmaf(u.w, hv.y, acc[3][1]);                              \
    acc[3][2] = fmaf(u.w, hv.z, acc[3][2]);                              \
    acc[3][3] = fmaf(u.w, hv.w, acc[3][3]);

__device__ __forceinline__ void load_U_smem(float* U_s, const float* U, int jb, int tid) {
    const int row = tid & 31;
    const int g = row & 3, jl = row >> 2;
    const float* Urow = U + (size_t)(g * H_ + jb + jl) * H_;
    for (int k0 = (tid >> 5) * 4; k0 < H_; k0 += 64) {
        float4 v = *(const float4*)(Urow + k0);
        U_s[(k0 + 0) * 32 + row] = v.x;
        U_s[(k0 + 1) * 32 + row] = v.y;
        U_s[(k0 + 2) * 32 + row] = v.z;
        U_s[(k0 + 3) * 32 + row] = v.w;
    }
}

__global__ void __launch_bounds__(512, 1) slstm_scan(
    const float* __restrict__ U, const float* __restrict__ bU,
    const float* __restrict__ alpha)
{
    extern __shared__ __align__(16) float smem_dyn[];
    float* U_s = smem_dyn;
    float* h_s = smem_dyn + 32768;
    float* red = h_s;

    const int tid = threadIdx.x;
    const int ks = tid >> 6, ty = (tid >> 3) & 7, tx = tid & 7;
    const int jb = blockIdx.x * 8;

    load_U_smem(U_s, U, jb, tid);

    int gid = blockIdx.x * 512 + tid;
    if (gid < H_ * B_) __stcg(&g_hT[0][gid], 0.f);
    __threadfence();
    grid_sync();

    const int sj = tid >> 5, sb = tid & 31;
    const int jglob = jb + sj;
    float c = 0.f;
    float balph = 0.f, bi = 0.f, bf = 0.f, bo = 0.f, bg = 0.f;
    if (tid < 256) {
        balph = __ldg(&alpha[jglob]);
        bi = __ldg(&bU[jglob]);
        bf = __ldg(&bU[H_ + jglob]);
        bo = __ldg(&bU[2 * H_ + jglob]);
        bg = __ldg(&bU[3 * H_ + jglob]);
    }

    int p = 0;
    for (int t = 0; t < T_; t++) {
        float xi = 0.f, xf = 0.f, xo = 0.f, xg = 0.f;
        if (tid < 256) {
            const float* xwt = g_xw + (size_t)t * FH * B_;
            xi = __ldg(xwt + (size_t)jglob * B_ + sb);
            xf = __ldg(xwt + (size_t)(H_ + jglob) * B_ + sb);
            xo = __ldg(xwt + (size_t)(2 * H_ + jglob) * B_ + sb);
            xg = __ldg(xwt + (size_t)(3 * H_ + jglob) * B_ + sb);
        }

        const float4* hsrc = (const float4*)(&g_hT[p][0]);
        float4 rg[8];
#pragma unroll
        for (int i = 0; i < 8; i++) rg[i] = __ldcg(hsrc + tid + i * 512);
        {
            float4* d4 = (float4*)h_s;
#pragma unroll
            for (int i = 0; i < 8; i++) d4[tid + i * 512] = rg[i];
        }
        __syncthreads();
#pragma unroll
        for (int i = 0; i < 8; i++) rg[i] = __ldcg(hsrc + 4096 + tid + i * 512);

        float acc[4][4];
#pragma unroll
        for (int i = 0; i < 4; i++)
#pragma unroll
            for (int jx = 0; jx < 4; jx++) acc[i][jx] = 0.f;

        {
            const float* Ub = U_s + (size_t)(ks * 64) * 32 + 4 * ty;
            const float* Hb = h_s + (size_t)(ks * 64) * 32 + 4 * tx;
#pragma unroll 8
            for (int kk = 0; kk < 64; kk++) {
                float4 u  = *(const float4*)(Ub + kk * 32);
                float4 hv = *(const float4*)(Hb + kk * 32);
                FMA16(u, hv)
            }
        }
        __syncthreads();
        {
            float4* d4 = (float4*)h_s;
#pragma unroll
            for (int i = 0; i < 8; i++) d4[tid + i * 512] = rg[i];
        }
        __syncthreads();
        {
            const float* Ub = U_s + (size_t)(512 + ks * 64) * 32 + 4 * ty;
            const float* Hb = h_s + (size_t)(ks * 64) * 32 + 4 * tx;
#pragma unroll 8
            for (int kk = 0; kk < 64; kk++) {
                float4 u  = *(const float4*)(Ub + kk * 32);
                float4 hv = *(const float4*)(Hb + kk * 32);
                FMA16(u, hv)
            }
        }
        __syncthreads();
#pragma unroll
        for (int i = 0; i < 4; i++) {
            float* rr = red + (size_t)(ks * 32 + 4 * ty + i) * 33 + 4 * tx;
            rr[0] = acc[i][0]; rr[1] = acc[i][1];
            rr[2] = acc[i][2]; rr[3] = acc[i][3];
        }
        __syncthreads();
        if (tid < 256) {
            float s0 = 0.f, s1 = 0.f, s2 = 0.f, s3 = 0.f;
#pragma unroll
            for (int k2 = 0; k2 < 8; k2++) {
                const float* rr = red + (size_t)k2 * 32 * 33 + sb;
                s0 += rr[(sj * 4 + 0) * 33];
                s1 += rr[(sj * 4 + 1) * 33];
                s2 += rr[(sj * 4 + 2) * 33];
                s3 += rr[(sj * 4 + 3) * 33];
            }
            float iv = sigmoidf_(xi + bi + s0);
            float fv = sigmoidf_(xf + bf + s1);
            float ov = sigmoidf_(xo + bo + s2);
            float gv = tanhf_(xg + bg + s3);
            c = balph * (fv * c + iv * gv);
            float h = ov * tanhf_(c);
            __stcg(&g_hT[p ^ 1][jglob * B_ + sb], h);
            g_hs[((size_t)sb * T_ + t) * H_ + jglob] = h;
        }
        __threadfence();
        grid_sync();
        p ^= 1;
    }
}

__global__ void __launch_bounds__(512, 1) mlstm_scan(
    const float* __restrict__ U, const float* __restrict__ bU,
    const float* __restrict__ Bm, const float* __restrict__ P,
    float* __restrict__ out)
{
    extern __shared__ __align__(16) float smem_dyn[];
    float* U_s = smem_dyn;
    float* h_s = smem_dyn + 32768;
    float* red = h_s;
    float* s_s = h_s;

    __shared__ float Bm_s[1024];
    __shared__ float q_s[8][16];

    const int tid = threadIdx.x;
    const int ks = tid >> 6, ty = (tid >> 3) & 7, tx = tid & 7;
    const int jb = blockIdx.x * 8;
    const int rq = blockIdx.x & 63;
    const int bh = blockIdx.x >> 6;

    load_U_smem(U_s, U, jb, tid);
    {
        const float* Bmr = Bm + (size_t)rq * H_;
        for (int i = tid; i < 256; i += 512)
            *(float4*)&Bm_s[i * 4] = __ldg((const float4*)(Bmr + i * 4));
    }

    int gid = blockIdx.x * 512 + tid;
    if (gid < H_ * B_) __stcg(&g_hT[0][gid], 0.f);
    __threadfence();
    grid_sync();

    const int sj = tid >> 5, sb = tid & 31;
    const int jglob = jb + sj;
    float c = 0.f;
    float bi = 0.f, bf = 0.f, bo = 0.f, bg = 0.f;
    if (tid < 256) {
        bi = __ldg(&bU[jglob]);
        bf = __ldg(&bU[H_ + jglob]);
        bo = __ldg(&bU[2 * H_ + jglob]);
        bg = __ldg(&bU[3 * H_ + jglob]);
    }
    const float* Pj = P + (size_t)jglob * R_;
    const int qb = tid & 15, qk = tid >> 4;

    int p = 0;
    for (int t = 0; t < T_; t++) {
        float xi = 0.f, xf = 0.f, xo = 0.f, xg = 0.f;
        if (tid < 256) {
            const float* xwt = g_xw + (size_t)t * FH * B_;
            xi = __ldg(xwt + (size_t)jglob * B_ + sb);
            xf = __ldg(xwt + (size_t)(H_ + jglob) * B_ + sb);
            xo = __ldg(xwt + (size_t)(2 * H_ + jglob) * B_ + sb);
            xg = __ldg(xwt + (size_t)(3 * H_ + jglob) * B_ + sb);
        }

        const float4* hsrc = (const float4*)(&g_hT[p][0]);
        float4 rg[8];
#pragma unroll
        for (int i = 0; i < 8; i++) rg[i] = __ldcg(hsrc + tid + i * 512);
        {
            float4* d4 = (float4*)h_s;
#pragma unroll
            for (int i = 0; i < 8; i++) d4[tid + i * 512] = rg[i];
        }
        __syncthreads();
#pragma unroll
        for (int i = 0; i < 8; i++) rg[i] = __ldcg(hsrc + 4096 + tid + i * 512);

        float acc[4][4];
#pragma unroll
        for (int i = 0; i < 4; i++)
#pragma unroll
            for (int jx = 0; jx < 4; jx++) acc[i][jx] = 0.f;
        float qpart = 0.f;

        {
            const float* Ub = U_s + (size_t)(ks * 64) * 32 + 4 * ty;
            const float* Hb = h_s + (size_t)(ks * 64) * 32 + 4 * tx;
#pragma unroll 8
            for (int kk = 0; kk < 64; kk++) {
                float4 u  = *(const float4*)(Ub + kk * 32);
                float4 hv = *(const float4*)(Hb + kk * 32);
                FMA16(u, hv)
            }
        }
        if (tid < 128) {
            const int bcol = bh * 16 + qb;
#pragma unroll 4
            for (int k4 = 0; k4 < 64; k4 += 4) {
                float4 bm = *(const float4*)&Bm_s[qk * 64 + k4];
                const float* hb = h_s + (size_t)(qk * 64 + k4) * 32 + bcol;
                qpart = fmaf(bm.x, hb[0],  qpart);
                qpart = fmaf(bm.y, hb[32], qpart);
                qpart = fmaf(bm.z, hb[64], qpart);
                qpart = fmaf(bm.w, hb[96], qpart);
            }
        }
        __syncthreads();
        {
            float4* d4 = (float4*)h_s;
#pragma unroll
            for (int i = 0; i < 8; i++) d4[tid + i * 512] = rg[i];
        }
        __syncthreads();
        {
            const float* Ub = U_s + (size_t)(512 + ks * 64) * 32 + 4 * ty;
            const float* Hb = h_s + (size_t)(ks * 64) * 32 + 4 * tx;
#pragma unroll 8
            for (int kk = 0; kk < 64; kk++) {
                float4 u  = *(const float4*)(Ub + kk * 32);
                float4 hv = *(const float4*)(Hb + kk * 32);
                FMA16(u, hv)
            }
        }
        if (tid < 128) {
            const int bcol = bh * 16 + qb;
#pragma unroll 4
            for (int k4 = 0; k4 < 64; k4 += 4) {
                float4 bm = *(const float4*)&Bm_s[512 + qk * 64 + k4];
                const float* hb = h_s + (size_t)(qk * 64 + k4) * 32 + bcol;
                qpart = fmaf(bm.x, hb[0],  qpart);
                qpart = fmaf(bm.y, hb[32], qpart);
                qpart = fmaf(bm.z, hb[64], qpart);
                qpart = fmaf(bm.w, hb[96], qpart);
            }
        }
        __syncthreads();
#pragma unroll
        for (int i = 0; i < 4; i++) {
            float* rr = red + (size_t)(ks * 32 + 4 * ty + i) * 33 + 4 * tx;
            rr[0] = acc[i][0]; rr[1] = acc[i][1];
            rr[2] = acc[i][2]; rr[3] = acc[i][3];
        }
        if (tid < 128) q_s[qk][qb] = qpart;
        __syncthreads();

        float a0 = 0.f, a1 = 0.f, a2 = 0.f, a3 = 0.f;
        if (tid < 256) {
#pragma unroll
            for (int k2 = 0; k2 < 8; k2++) {
                const float* rr = red + (size_t)k2 * 32 * 33 + sb;
                a0 += rr[(sj * 4 + 0) * 33];
                a1 += rr[(sj * 4 + 1) * 33];
                a2 += rr[(sj * 4 + 2) * 33];
                a3 += rr[(sj * 4 + 3) * 33];
            }
            a0 += xi + bi; a1 += xf + bf; a2 += xo + bo; a3 += xg + bg;
        }
        if (tid < 16) {
            float q = 0.f;
#pragma unroll
            for (int s2 = 0; s2 < 8; s2++) q += q_s[s2][tid];
            int bb = bh * 16 + tid;
            float xav = __ldg(&g_xa[((size_t)t * R_ + rq) * B_ + bb]);
            __stcg(&g_s[rq * B_ + bb], xav * q);
        }
        __threadfence();
        grid_sync();

        ((float4*)s_s)[tid] = __ldcg(((const float4*)g_s) + tid);
        __syncthreads();
        if (tid < 256) {
            float mix = 0.f;
#pragma unroll
            for (int r = 0; r < R_; r += 4) {
                float4 pv = __ldg((const float4*)(Pj + r));
                mix = fmaf(pv.x, s_s[(r + 0) * B_ + sb], mix);
                mix = fmaf(pv.y, s_s[(r + 1) * B_ + sb], mix);
                mix = fmaf(pv.z, s_s[(r + 2) * B_ + sb], mix);
                mix = fmaf(pv.w, s_s[(r + 3) * B_ + sb], mix);
            }
            float iv = sigmoidf_(a0), fv = sigmoidf_(a1);
            float ov = sigmoidf_(a2), gv = tanhf_(a3);
            c = fv * c + iv * gv + 0.1f * mix;
            float h = ov * tanhf_(c);
            __stcg(&g_hT[p ^ 1][jglob * B_ + sb], h);
            out[((size_t)sb * T_ + t) * H_ + jglob] = h;
        }
        __threadfence();
        grid_sync();
        p ^= 1;
    }
}

// ---------------- launch -----------------------------------------------------
extern "C" void kernel_launch(void* const* d_in, const int* in_sizes, int n_in,
                              void* d_out, int out_size)
{
    (void)in_sizes; (void)n_in; (void)out_size;
    const float* x     = (const float*)d_in[0];
    const float* Ws    = (const float*)d_in[1];
    const float* bWs   = (const float*)d_in[2];
    const float* Us    = (const float*)d_in[3];
    const float* bUs   = (const float*)d_in[4];
    const float* alpha = (const float*)d_in[5];
    const float* Wm    = (const float*)d_in[6];
    const float* bWm   = (const float*)d_in[7];
    const float* Um    = (const float*)d_in[8];
    const float* bUm   = (const float*)d_in[9];
    const float* A     = (const float*)d_in[10];
    const float* Bm    = (const float*)d_in[11];
    const float* P     = (const float*)d_in[12];

    cudaFuncSetAttribute(slstm_scan, cudaFuncAttributeMaxDynamicSharedMemorySize,
                         SMEM_SCAN_BYTES);
    cudaFuncSetAttribute(mlstm_scan, cudaFuncAttributeMaxDynamicSharedMemorySize,
                         SMEM_SCAN_BYTES);
    cudaFuncSetAttribute(ffn_gemm_mma, cudaFuncAttributeMaxDynamicSharedMemorySize,
                         SMEM_GEMM_BYTES);

    dim3 gG(FH / 128, (B_ * T_) / 128);  // 32 n-tiles x 128 m-tiles
    ffn_gemm_mma<<<gG, 256, SMEM_GEMM_BYTES>>>(x, 0, Ws, bWs);
    slstm_scan<<<NCTA, 512, SMEM_SCAN_BYTES>>>(Us, bUs, alpha);
    xa_gemm<<<dim3(1, T_), 128>>>(A);
    ffn_gemm_mma<<<gG, 256, SMEM_GEMM_BYTES>>>(nullptr, 1, Wm, bWm);
    mlstm_scan<<<NCTA, 512, SMEM_SCAN_BYTES>>>(Um, bUm, Bm, P, (float*)d_out);
}

// round 14
// speedup vs baseline: 3.6198x; 1.0175x over previous
#include <cuda_runtime.h>
#include <cuda_bf16.h>
#include <math.h>
#include <stdint.h>

#define B_   32
#define T_   512
#define D_   1024
#define H_   1024
#define R_   64
#define FH   4096
#define NCTA 128

// scan dynamic smem (floats): U_s[32768] | h_s[16384]
#define SMEM_SCAN_BYTES (49152 * 4)
// mma gemm dynamic smem: 2 buffers x 32 KB
#define SMEM_GEMM_BYTES 65536

// ---------------- scratch (device globals: allocation-free) ----------------
__device__ __align__(16) float g_xw[(size_t)T_ * FH * B_];   // [t][k][b]
__device__ __align__(16) float g_hs[(size_t)B_ * T_ * H_];   // [b][t][h]
__device__ __align__(16) float g_xa[(size_t)T_ * R_ * B_];   // [t][r][b]
__device__ __align__(16) float g_hT[2][H_ * B_];             // h dbl buf [j][b]
__device__ __align__(16) float g_s[R_ * B_];                 // [r][b]
__device__ unsigned g_bar_count = 0;
__device__ unsigned g_bar_gen   = 0;

// ---------------- software grid barrier (scan kernels, grid == NCTA) -------
__device__ __forceinline__ void grid_sync() {
    __syncthreads();
    if (threadIdx.x == 0) {
        volatile unsigned* vgen = &g_bar_gen;
        unsigned gen = *vgen;
        __threadfence();
        if (atomicAdd(&g_bar_count, 1u) == (unsigned)(NCTA - 1)) {
            atomicExch(&g_bar_count, 0u);
            __threadfence();
            atomicAdd(&g_bar_gen, 1u);
        } else {
            while (*vgen == gen) { }
        }
        __threadfence();
    }
    __syncthreads();
}

__device__ __forceinline__ float sigmoidf_(float x) {
    return 1.0f / (1.0f + __expf(-x));
}
__device__ __forceinline__ float tanhf_(float x) {
    float e = __expf(2.0f * x);
    return 1.0f - 2.0f / (e + 1.0f);
}

// ---- fp32 -> bf16 hi/lo split (packed bf16x2; x -> low half, y -> high) ----
__device__ __forceinline__ void split2(float x, float y, uint32_t& hp, uint32_t& lp) {
    uint32_t h;
    asm("cvt.rn.bf16x2.f32 %0, %1, %2;" : "=r"(h) : "f"(y), "f"(x));
    float xh = __uint_as_float(h << 16);
    float yh = __uint_as_float(h & 0xFFFF0000u);
    float xl = x - xh, yl = y - yh;
    uint32_t l;
    asm("cvt.rn.bf16x2.f32 %0, %1, %2;" : "=r"(l) : "f"(yl), "f"(xl));
    hp = h; lp = l;
}

// ---- warp mma m16n8k16 bf16, fp32 accumulate ----
__device__ __forceinline__ void mma_bf16(float* c, const uint32_t* a, const uint32_t* b) {
    asm volatile(
        "mma.sync.aligned.m16n8k16.row.col.f32.bf16.bf16.f32 "
        "{%0,%1,%2,%3}, {%4,%5,%6,%7}, {%8,%9}, {%0,%1,%2,%3};"
        : "+f"(c[0]), "+f"(c[1]), "+f"(c[2]), "+f"(c[3])
        : "r"(a[0]), "r"(a[1]), "r"(a[2]), "r"(a[3]), "r"(b[0]), "r"(b[1]));
}

// ============================================================================
// HMMA feedforward GEMM v2: 512 threads (16 warps, 4m x 4n), warp tile 32x32.
// g_xw[t][k][b] = bias[k] + X2d[m] . W[k],  m = t*32+b.
// CTA tile 128m x 128n, BK=32. bf16 hi/lo split, 3 products, fp32 accum.
// Smem holds mma fragments directly, per buffer (u32):
//   AH[2048] | AL[2048] | BH[2048] | BL[2048]   (32 KB)
//   A slot: ((ktile*8+mtile)*4 + reg)*32 + lane     (reg = (row>=8) + 2*(k>=8))
//   B slot: 4096 + ((ktile*16+ntile)*2 + reg)*32 + lane   (reg = (k>=8))
// Staging: thread = (row = tid>>1, half = tid&1); each thread converts 16
// floats (half a 32-wide k-chunk row) into hi/lo fragments.
// ============================================================================
__global__ void __launch_bounds__(512, 1) ffn_gemm_mma(
    const float* __restrict__ Aext, int a_is_hs,
    const float* __restrict__ W, const float* __restrict__ bias)
{
    extern __shared__ __align__(16) uint32_t smemu[];
    const float* A0 = a_is_hs ? g_hs : Aext;

    const int tid = threadIdx.x;
    const int wid = tid >> 5, lane = tid & 31;
    const int n0 = blockIdx.x * 128;
    const int m0 = blockIdx.y * 128;
    const int wm = wid >> 2, wn = wid & 3;     // 4 x 4 warp grid

    // ---- staging role
    const int row  = tid >> 1;      // 0..255
    const int half = tid & 1;       // which 16-float half of the row
    const int isB  = (row >= 128);
    const int r    = row & 127;
    const float* srow;
    if (isB) {
        srow = W + (size_t)(n0 + r) * 1024;
    } else {
        int m = m0 + r;
        srow = A0 + ((size_t)(m & 31) * T_ + (m >> 5)) * 1024;
    }
    // k2 = half*2 + j  (j=0,1): ktile = half, kb = j
    uint32_t sts_off[2];
#pragma unroll
    for (int j = 0; j < 2; j++) {
        int ktile = half, kb = j;
        if (isB) {
            int ntile = r >> 3, g = r & 7;
            sts_off[j] = 4096u + (uint32_t)(((ktile * 16 + ntile) * 2 + kb) * 32 + g * 4);
        } else {
            int mtile = r >> 4, gp = r & 15;
            int rb0 = gp >> 3, g = gp & 7;
            sts_off[j] = (uint32_t)(((ktile * 8 + mtile) * 4 + rb0 + 2 * kb) * 32 + g * 4);
        }
    }
    const float* sbase = srow + half * 16;

    // ---- prologue: stage chunk 0 into buffer 0
    {
#pragma unroll
        for (int j = 0; j < 2; j++) {
            float4 v0 = __ldg((const float4*)(sbase + j * 8));
            float4 v1 = __ldg((const float4*)(sbase + j * 8 + 4));
            uint32_t h0, h1, h2, h3, l0, l1, l2, l3;
            split2(v0.x, v0.y, h0, l0); split2(v0.z, v0.w, h1, l1);
            split2(v1.x, v1.y, h2, l2); split2(v1.z, v1.w, h3, l3);
            uint32_t* q = smemu + sts_off[j];
            *(uint4*)q          = make_uint4(h0, h1, h2, h3);
            *(uint4*)(q + 2048) = make_uint4(l0, l1, l2, l3);
        }
    }
    __syncthreads();

    float acc[2][4][4];
#pragma unroll
    for (int mt = 0; mt < 2; mt++)
#pragma unroll
        for (int nt = 0; nt < 4; nt++)
#pragma unroll
            for (int e = 0; e < 4; e++) acc[mt][nt][e] = 0.f;

    for (int c = 0; c < 32; c++) {
        const uint32_t* buf = smemu + (c & 1) * 8192;
        float4 pend[4];
        if (c < 31) {
            const float* sp = sbase + (c + 1) * 32;
#pragma unroll
            for (int j = 0; j < 2; j++) {
                pend[2 * j]     = __ldg((const float4*)(sp + j * 8));
                pend[2 * j + 1] = __ldg((const float4*)(sp + j * 8 + 4));
            }
        }
        // ---- compute: 2 k-tiles of 16
#pragma unroll
        for (int kt = 0; kt < 2; kt++) {
            uint32_t aH[2][4], aL[2][4], bH[4][2], bL[4][2];
#pragma unroll
            for (int mt = 0; mt < 2; mt++) {
                const uint32_t* p = buf + ((kt * 8 + wm * 2 + mt) * 4) * 32 + lane;
#pragma unroll
                for (int rr = 0; rr < 4; rr++) {
                    aH[mt][rr] = p[rr * 32];
                    aL[mt][rr] = p[rr * 32 + 2048];
                }
            }
#pragma unroll
            for (int nt = 0; nt < 4; nt++) {
                const uint32_t* p = buf + 4096 + ((kt * 16 + wn * 4 + nt) * 2) * 32 + lane;
                bH[nt][0] = p[0];    bH[nt][1] = p[32];
                bL[nt][0] = p[2048]; bL[nt][1] = p[2080];
            }
#pragma unroll
            for (int mt = 0; mt < 2; mt++)
#pragma unroll
                for (int nt = 0; nt < 4; nt++) {
                    mma_bf16(acc[mt][nt], aH[mt], bH[nt]);
                    mma_bf16(acc[mt][nt], aH[mt], bL[nt]);
                    mma_bf16(acc[mt][nt], aL[mt], bH[nt]);
                }
        }
        // ---- convert + store chunk c+1 into the other buffer
        if (c < 31) {
            uint32_t* nb = smemu + ((c + 1) & 1) * 8192;
#pragma unroll
            for (int j = 0; j < 2; j++) {
                uint32_t h0, h1, h2, h3, l0, l1, l2, l3;
                split2(pend[2*j].x,   pend[2*j].y,   h0, l0);
                split2(pend[2*j].z,   pend[2*j].w,   h1, l1);
                split2(pend[2*j+1].x, pend[2*j+1].y, h2, l2);
                split2(pend[2*j+1].z, pend[2*j+1].w, h3, l3);
                uint32_t* q = nb + sts_off[j];
                *(uint4*)q          = make_uint4(h0, h1, h2, h3);
                *(uint4*)(q + 2048) = make_uint4(l0, l1, l2, l3);
            }
        }
        __syncthreads();
    }

    // ---- epilogue: acc[mt][nt] c-fragment -> g_xw[t][k][b] + bias
    const int g = lane >> 2, cc = lane & 3;
#pragma unroll
    for (int mt = 0; mt < 2; mt++) {
#pragma unroll
        for (int nt = 0; nt < 4; nt++) {
            int mA = m0 + wm * 32 + mt * 16 + g;
            int mB = mA + 8;
            int k0 = n0 + wn * 32 + nt * 8 + 2 * cc;
            float b0 = __ldg(&bias[k0]);
            float b1 = __ldg(&bias[k0 + 1]);
            size_t oA = ((size_t)(mA >> 5) * FH) * B_ + (mA & 31);
            size_t oB = ((size_t)(mB >> 5) * FH) * B_ + (mB & 31);
            g_xw[oA + (size_t)k0 * B_]       = acc[mt][nt][0] + b0;
            g_xw[oA + (size_t)(k0 + 1) * B_] = acc[mt][nt][1] + b1;
            g_xw[oB + (size_t)k0 * B_]       = acc[mt][nt][2] + b0;
            g_xw[oB + (size_t)(k0 + 1) * B_] = acc[mt][nt][3] + b1;
        }
    }
}

// ---------------- small GEMM for xa: out[t][r][b] (fp32) --------------------
__global__ void __launch_bounds__(128) xa_gemm(const float* __restrict__ A)
{
    const float* X = g_hs;
    float* out = g_xa;
    const int t = blockIdx.y;

    __shared__ __align__(16) float sX[32][36];
    __shared__ __align__(16) float sW[32][68];

    const int tid = threadIdx.x;
    const int b4  = (tid & 7) * 4;
    const int k4  = (tid >> 3) * 4;

    float acc[4][4];
#pragma unroll
    for (int i = 0; i < 4; i++)
#pragma unroll
        for (int jx = 0; jx < 4; jx++) acc[i][jx] = 0.f;

    for (int d0 = 0; d0 < 1024; d0 += 32) {
#pragma unroll
        for (int i = 0; i < 2; i++) {
            int qq = tid + i * 128;
            int br = qq >> 3, ds = (qq & 7) * 4;
            float4 v = *(const float4*)(X + ((size_t)br * T_ + t) * 1024 + d0 + ds);
            sX[ds + 0][br] = v.x; sX[ds + 1][br] = v.y;
            sX[ds + 2][br] = v.z; sX[ds + 3][br] = v.w;
        }
#pragma unroll
        for (int i = 0; i < 4; i++) {
            int qq = tid + i * 128;
            int kr = qq >> 3, ds = (qq & 7) * 4;
            float4 v = *(const float4*)(A + (size_t)kr * 1024 + d0 + ds);
            sW[ds + 0][kr] = v.x; sW[ds + 1][kr] = v.y;
            sW[ds + 2][kr] = v.z; sW[ds + 3][kr] = v.w;
        }
        __syncthreads();
#pragma unroll
        for (int d = 0; d < 32; d++) {
            float4 xv = *(const float4*)&sX[d][b4];
            float4 wv = *(const float4*)&sW[d][k4];
            float xs[4] = {xv.x, xv.y, xv.z, xv.w};
            float ws[4] = {wv.x, wv.y, wv.z, wv.w};
#pragma unroll
            for (int i = 0; i < 4; i++)
#pragma unroll
                for (int jx = 0; jx < 4; jx++)
                    acc[i][jx] = fmaf(ws[i], xs[jx], acc[i][jx]);
        }
        __syncthreads();
    }
#pragma unroll
    for (int i = 0; i < 4; i++) {
        float4 r = make_float4(acc[i][0], acc[i][1], acc[i][2], acc[i][3]);
        *(float4*)(out + ((size_t)t * R_ + (k4 + i)) * B_ + b4) = r;
    }
}

// ============================================================================
// Scan v3 (passing): U resident in smem, reg-tiled 4x4, K-split 8
// ============================================================================
#define FMA16(u, hv)                                                     \
    acc[0][0] = fmaf(u.x, hv.x, acc[0][0]);                              \
    acc[0][1] = fmaf(u.x, hv.y, acc[0][1]);                              \
    acc[0][2] = fmaf(u.x, hv.z, acc[0][2]);                              \
    acc[0][3] = fmaf(u.x, hv.w, acc[0][3]);                              \
    acc[1][0] = fmaf(u.y, hv.x, acc[1][0]);                              \
    acc[1][1] = fmaf(u.y, hv.y, acc[1][1]);                              \
    acc[1][2] = fmaf(u.y, hv.z, acc[1][2]);                              \
    acc[1][3] = fmaf(u.y, hv.w, acc[1][3]);                              \
    acc[2][0] = fmaf(u.z, hv.x, acc[2][0]);                              \
    acc[2][1] = fmaf(u.z, hv.y, acc[2][1]);                              \
    acc[2][2] = fmaf(u.z, hv.z, acc[2][2]);                              \
    acc[2][3] = fmaf(u.z, hv.w, acc[2][3]);                              \
    acc[3][0] = fmaf(u.w, hv.x, acc[3][0]);                              \
    acc[3][1] = fmaf(u.w, hv.y, acc[3][1]);                              \
    acc[3][2] = fmaf(u.w, hv.z, acc[3][2]);                              \
    acc[3][3] = fmaf(u.w, hv.w, acc[3][3]);

__device__ __forceinline__ void load_U_smem(float* U_s, const float* U, int jb, int tid) {
    const int row = tid & 31;
    const int g = row & 3, jl = row >> 2;
    const float* Urow = U + (size_t)(g * H_ + jb + jl) * H_;
    for (int k0 = (tid >> 5) * 4; k0 < H_; k0 += 64) {
        float4 v = *(const float4*)(Urow + k0);
        U_s[(k0 + 0) * 32 + row] = v.x;
        U_s[(k0 + 1) * 32 + row] = v.y;
        U_s[(k0 + 2) * 32 + row] = v.z;
        U_s[(k0 + 3) * 32 + row] = v.w;
    }
}

__global__ void __launch_bounds__(512, 1) slstm_scan(
    const float* __restrict__ U, const float* __restrict__ bU,
    const float* __restrict__ alpha)
{
    extern __shared__ __align__(16) float smem_dyn[];
    float* U_s = smem_dyn;
    float* h_s = smem_dyn + 32768;
    float* red = h_s;

    const int tid = threadIdx.x;
    const int ks = tid >> 6, ty = (tid >> 3) & 7, tx = tid & 7;
    const int jb = blockIdx.x * 8;

    load_U_smem(U_s, U, jb, tid);

    int gid = blockIdx.x * 512 + tid;
    if (gid < H_ * B_) __stcg(&g_hT[0][gid], 0.f);
    __threadfence();
    grid_sync();

    const int sj = tid >> 5, sb = tid & 31;
    const int jglob = jb + sj;
    float c = 0.f;
    float balph = 0.f, bi = 0.f, bf = 0.f, bo = 0.f, bg = 0.f;
    if (tid < 256) {
        balph = __ldg(&alpha[jglob]);
        bi = __ldg(&bU[jglob]);
        bf = __ldg(&bU[H_ + jglob]);
        bo = __ldg(&bU[2 * H_ + jglob]);
        bg = __ldg(&bU[3 * H_ + jglob]);
    }

    int p = 0;
    for (int t = 0; t < T_; t++) {
        float xi = 0.f, xf = 0.f, xo = 0.f, xg = 0.f;
        if (tid < 256) {
            const float* xwt = g_xw + (size_t)t * FH * B_;
            xi = __ldg(xwt + (size_t)jglob * B_ + sb);
            xf = __ldg(xwt + (size_t)(H_ + jglob) * B_ + sb);
            xo = __ldg(xwt + (size_t)(2 * H_ + jglob) * B_ + sb);
            xg = __ldg(xwt + (size_t)(3 * H_ + jglob) * B_ + sb);
        }

        const float4* hsrc = (const float4*)(&g_hT[p][0]);
        float4 rg[8];
#pragma unroll
        for (int i = 0; i < 8; i++) rg[i] = __ldcg(hsrc + tid + i * 512);
        {
            float4* d4 = (float4*)h_s;
#pragma unroll
            for (int i = 0; i < 8; i++) d4[tid + i * 512] = rg[i];
        }
        __syncthreads();
#pragma unroll
        for (int i = 0; i < 8; i++) rg[i] = __ldcg(hsrc + 4096 + tid + i * 512);

        float acc[4][4];
#pragma unroll
        for (int i = 0; i < 4; i++)
#pragma unroll
            for (int jx = 0; jx < 4; jx++) acc[i][jx] = 0.f;

        {
            const float* Ub = U_s + (size_t)(ks * 64) * 32 + 4 * ty;
            const float* Hb = h_s + (size_t)(ks * 64) * 32 + 4 * tx;
#pragma unroll 8
            for (int kk = 0; kk < 64; kk++) {
                float4 u  = *(const float4*)(Ub + kk * 32);
                float4 hv = *(const float4*)(Hb + kk * 32);
                FMA16(u, hv)
            }
        }
        __syncthreads();
        {
            float4* d4 = (float4*)h_s;
#pragma unroll
            for (int i = 0; i < 8; i++) d4[tid + i * 512] = rg[i];
        }
        __syncthreads();
        {
            const float* Ub = U_s + (size_t)(512 + ks * 64) * 32 + 4 * ty;
            const float* Hb = h_s + (size_t)(ks * 64) * 32 + 4 * tx;
#pragma unroll 8
            for (int kk = 0; kk < 64; kk++) {
                float4 u  = *(const float4*)(Ub + kk * 32);
                float4 hv = *(const float4*)(Hb + kk * 32);
                FMA16(u, hv)
            }
        }
        __syncthreads();
#pragma unroll
        for (int i = 0; i < 4; i++) {
            float* rr = red + (size_t)(ks * 32 + 4 * ty + i) * 33 + 4 * tx;
            rr[0] = acc[i][0]; rr[1] = acc[i][1];
            rr[2] = acc[i][2]; rr[3] = acc[i][3];
        }
        __syncthreads();
        if (tid < 256) {
            float s0 = 0.f, s1 = 0.f, s2 = 0.f, s3 = 0.f;
#pragma unroll
            for (int k2 = 0; k2 < 8; k2++) {
                const float* rr = red + (size_t)k2 * 32 * 33 + sb;
                s0 += rr[(sj * 4 + 0) * 33];
                s1 += rr[(sj * 4 + 1) * 33];
                s2 += rr[(sj * 4 + 2) * 33];
                s3 += rr[(sj * 4 + 3) * 33];
            }
            float iv = sigmoidf_(xi + bi + s0);
            float fv = sigmoidf_(xf + bf + s1);
            float ov = sigmoidf_(xo + bo + s2);
            float gv = tanhf_(xg + bg + s3);
            c = balph * (fv * c + iv * gv);
            float h = ov * tanhf_(c);
            __stcg(&g_hT[p ^ 1][jglob * B_ + sb], h);
            g_hs[((size_t)sb * T_ + t) * H_ + jglob] = h;
        }
        __threadfence();
        grid_sync();
        p ^= 1;
    }
}

__global__ void __launch_bounds__(512, 1) mlstm_scan(
    const float* __restrict__ U, const float* __restrict__ bU,
    const float* __restrict__ Bm, const float* __restrict__ P,
    float* __restrict__ out)
{
    extern __shared__ __align__(16) float smem_dyn[];
    float* U_s = smem_dyn;
    float* h_s = smem_dyn + 32768;
    float* red = h_s;
    float* s_s = h_s;

    __shared__ float Bm_s[1024];
    __shared__ float q_s[8][16];

    const int tid = threadIdx.x;
    const int ks = tid >> 6, ty = (tid >> 3) & 7, tx = tid & 7;
    const int jb = blockIdx.x * 8;
    const int rq = blockIdx.x & 63;
    const int bh = blockIdx.x >> 6;

    load_U_smem(U_s, U, jb, tid);
    {
        const float* Bmr = Bm + (size_t)rq * H_;
        for (int i = tid; i < 256; i += 512)
            *(float4*)&Bm_s[i * 4] = __ldg((const float4*)(Bmr + i * 4));
    }

    int gid = blockIdx.x * 512 + tid;
    if (gid < H_ * B_) __stcg(&g_hT[0][gid], 0.f);
    __threadfence();
    grid_sync();

    const int sj = tid >> 5, sb = tid & 31;
    const int jglob = jb + sj;
    float c = 0.f;
    float bi = 0.f, bf = 0.f, bo = 0.f, bg = 0.f;
    if (tid < 256) {
        bi = __ldg(&bU[jglob]);
        bf = __ldg(&bU[H_ + jglob]);
        bo = __ldg(&bU[2 * H_ + jglob]);
        bg = __ldg(&bU[3 * H_ + jglob]);
    }
    const float* Pj = P + (size_t)jglob * R_;
    const int qb = tid & 15, qk = tid >> 4;

    int p = 0;
    for (int t = 0; t < T_; t++) {
        float xi = 0.f, xf = 0.f, xo = 0.f, xg = 0.f;
        if (tid < 256) {
            const float* xwt = g_xw + (size_t)t * FH * B_;
            xi = __ldg(xwt + (size_t)jglob * B_ + sb);
            xf = __ldg(xwt + (size_t)(H_ + jglob) * B_ + sb);
            xo = __ldg(xwt + (size_t)(2 * H_ + jglob) * B_ + sb);
            xg = __ldg(xwt + (size_t)(3 * H_ + jglob) * B_ + sb);
        }

        const float4* hsrc = (const float4*)(&g_hT[p][0]);
        float4 rg[8];
#pragma unroll
        for (int i = 0; i < 8; i++) rg[i] = __ldcg(hsrc + tid + i * 512);
        {
            float4* d4 = (float4*)h_s;
#pragma unroll
            for (int i = 0; i < 8; i++) d4[tid + i * 512] = rg[i];
        }
        __syncthreads();
#pragma unroll
        for (int i = 0; i < 8; i++) rg[i] = __ldcg(hsrc + 4096 + tid + i * 512);

        float acc[4][4];
#pragma unroll
        for (int i = 0; i < 4; i++)
#pragma unroll
            for (int jx = 0; jx < 4; jx++) acc[i][jx] = 0.f;
        float qpart = 0.f;

        {
            const float* Ub = U_s + (size_t)(ks * 64) * 32 + 4 * ty;
            const float* Hb = h_s + (size_t)(ks * 64) * 32 + 4 * tx;
#pragma unroll 8
            for (int kk = 0; kk < 64; kk++) {
                float4 u  = *(const float4*)(Ub + kk * 32);
                float4 hv = *(const float4*)(Hb + kk * 32);
                FMA16(u, hv)
            }
        }
        if (tid < 128) {
            const int bcol = bh * 16 + qb;
#pragma unroll 4
            for (int k4 = 0; k4 < 64; k4 += 4) {
                float4 bm = *(const float4*)&Bm_s[qk * 64 + k4];
                const float* hb = h_s + (size_t)(qk * 64 + k4) * 32 + bcol;
                qpart = fmaf(bm.x, hb[0],  qpart);
                qpart = fmaf(bm.y, hb[32], qpart);
                qpart = fmaf(bm.z, hb[64], qpart);
                qpart = fmaf(bm.w, hb[96], qpart);
            }
        }
        __syncthreads();
        {
            float4* d4 = (float4*)h_s;
#pragma unroll
            for (int i = 0; i < 8; i++) d4[tid + i * 512] = rg[i];
        }
        __syncthreads();
        {
            const float* Ub = U_s + (size_t)(512 + ks * 64) * 32 + 4 * ty;
            const float* Hb = h_s + (size_t)(ks * 64) * 32 + 4 * tx;
#pragma unroll 8
            for (int kk = 0; kk < 64; kk++) {
                float4 u  = *(const float4*)(Ub + kk * 32);
                float4 hv = *(const float4*)(Hb + kk * 32);
                FMA16(u, hv)
            }
        }
        if (tid < 128) {
            const int bcol = bh * 16 + qb;
#pragma unroll 4
            for (int k4 = 0; k4 < 64; k4 += 4) {
                float4 bm = *(const float4*)&Bm_s[512 + qk * 64 + k4];
                const float* hb = h_s + (size_t)(qk * 64 + k4) * 32 + bcol;
                qpart = fmaf(bm.x, hb[0],  qpart);
                qpart = fmaf(bm.y, hb[32], qpart);
                qpart = fmaf(bm.z, hb[64], qpart);
                qpart = fmaf(bm.w, hb[96], qpart);
            }
        }
        __syncthreads();
#pragma unroll
        for (int i = 0; i < 4; i++) {
            float* rr = red + (size_t)(ks * 32 + 4 * ty + i) * 33 + 4 * tx;
            rr[0] = acc[i][0]; rr[1] = acc[i][1];
            rr[2] = acc[i][2]; rr[3] = acc[i][3];
        }
        if (tid < 128) q_s[qk][qb] = qpart;
        __syncthreads();

        float a0 = 0.f, a1 = 0.f, a2 = 0.f, a3 = 0.f;
        if (tid < 256) {
#pragma unroll
            for (int k2 = 0; k2 < 8; k2++) {
                const float* rr = red + (size_t)k2 * 32 * 33 + sb;
                a0 += rr[(sj * 4 + 0) * 33];
                a1 += rr[(sj * 4 + 1) * 33];
                a2 += rr[(sj * 4 + 2) * 33];
                a3 += rr[(sj * 4 + 3) * 33];
            }
            a0 += xi + bi; a1 += xf + bf; a2 += xo + bo; a3 += xg + bg;
        }
        if (tid < 16) {
            float q = 0.f;
#pragma unroll
            for (int s2 = 0; s2 < 8; s2++) q += q_s[s2][tid];
            int bb = bh * 16 + tid;
            float xav = __ldg(&g_xa[((size_t)t * R_ + rq) * B_ + bb]);
            __stcg(&g_s[rq * B_ + bb], xav * q);
        }
        __threadfence();
        grid_sync();

        ((float4*)s_s)[tid] = __ldcg(((const float4*)g_s) + tid);
        __syncthreads();
        if (tid < 256) {
            float mix = 0.f;
#pragma unroll
            for (int r = 0; r < R_; r += 4) {
                float4 pv = __ldg((const float4*)(Pj + r));
                mix = fmaf(pv.x, s_s[(r + 0) * B_ + sb], mix);
                mix = fmaf(pv.y, s_s[(r + 1) * B_ + sb], mix);
                mix = fmaf(pv.z, s_s[(r + 2) * B_ + sb], mix);
                mix = fmaf(pv.w, s_s[(r + 3) * B_ + sb], mix);
            }
            float iv = sigmoidf_(a0), fv = sigmoidf_(a1);
            float ov = sigmoidf_(a2), gv = tanhf_(a3);
            c = fv * c + iv * gv + 0.1f * mix;
            float h = ov * tanhf_(c);
            __stcg(&g_hT[p ^ 1][jglob * B_ + sb], h);
            out[((size_t)sb * T_ + t) * H_ + jglob] = h;
        }
        __threadfence();
        grid_sync();
        p ^= 1;
    }
}

// ---------------- launch -----------------------------------------------------
extern "C" void kernel_launch(void* const* d_in, const int* in_sizes, int n_in,
                              void* d_out, int out_size)
{
    (void)in_sizes; (void)n_in; (void)out_size;
    const float* x     = (const float*)d_in[0];
    const float* Ws    = (const float*)d_in[1];
    const float* bWs   = (const float*)d_in[2];
    const float* Us    = (const float*)d_in[3];
    const float* bUs   = (const float*)d_in[4];
    const float* alpha = (const float*)d_in[5];
    const float* Wm    = (const float*)d_in[6];
    const float* bWm   = (const float*)d_in[7];
    const float* Um    = (const float*)d_in[8];
    const float* bUm   = (const float*)d_in[9];
    const float* A     = (const float*)d_in[10];
    const float* Bm    = (const float*)d_in[11];
    const float* P     = (const float*)d_in[12];

    cudaFuncSetAttribute(slstm_scan, cudaFuncAttributeMaxDynamicSharedMemorySize,
                         SMEM_SCAN_BYTES);
    cudaFuncSetAttribute(mlstm_scan, cudaFuncAttributeMaxDynamicSharedMemorySize,
                         SMEM_SCAN_BYTES);
    cudaFuncSetAttribute(ffn_gemm_mma, cudaFuncAttributeMaxDynamicSharedMemorySize,
                         SMEM_GEMM_BYTES);

    dim3 gG(FH / 128, (B_ * T_) / 128);  // 32 n-tiles x 128 m-tiles
    ffn_gemm_mma<<<gG, 512, SMEM_GEMM_BYTES>>>(x, 0, Ws, bWs);
    slstm_scan<<<NCTA, 512, SMEM_SCAN_BYTES>>>(Us, bUs, alpha);
    xa_gemm<<<dim3(1, T_), 128>>>(A);
    ffn_gemm_mma<<<gG, 512, SMEM_GEMM_BYTES>>>(nullptr, 1, Wm, bWm);
    mlstm_scan<<<NCTA, 512, SMEM_SCAN_BYTES>>>(Um, bUm, Bm, P, (float*)d_out);
}

// round 15
// speedup vs baseline: 3.6442x; 1.0068x over previous
#include <cuda_runtime.h>
#include <cuda_bf16.h>
#include <math.h>
#include <stdint.h>

#define B_   32
#define T_   512
#define D_   1024
#define H_   1024
#define R_   64
#define FH   4096
#define NCTA 128

// scan dynamic smem (floats): U_s[32768] | h_s[16384]
#define SMEM_SCAN_BYTES (49152 * 4)
// mma gemm dynamic smem: 2 buffers x 32 KB
#define SMEM_GEMM_BYTES 65536

// ---------------- scratch (device globals: allocation-free) ----------------
__device__ __align__(16) float g_xw[(size_t)T_ * FH * B_];   // [t][k][b]
__device__ __align__(16) float g_hs[(size_t)B_ * T_ * H_];   // [b][t][h]
__device__ __align__(16) float g_xa[(size_t)T_ * R_ * B_];   // [t][r][b]
__device__ __align__(16) float g_hT[2][H_ * B_];             // h dbl buf [j][b]
__device__ __align__(16) float g_s[R_ * B_];                 // [r][b]
__device__ unsigned g_bar_count = 0;
__device__ unsigned g_bar_gen   = 0;

// ---------------- software grid barrier (scan kernels, grid == NCTA) -------
__device__ __forceinline__ void grid_sync() {
    __syncthreads();
    if (threadIdx.x == 0) {
        volatile unsigned* vgen = &g_bar_gen;
        unsigned gen = *vgen;
        __threadfence();
        if (atomicAdd(&g_bar_count, 1u) == (unsigned)(NCTA - 1)) {
            atomicExch(&g_bar_count, 0u);
            __threadfence();
            atomicAdd(&g_bar_gen, 1u);
        } else {
            while (*vgen == gen) { }
        }
        __threadfence();
    }
    __syncthreads();
}

__device__ __forceinline__ float sigmoidf_(float x) {
    return 1.0f / (1.0f + __expf(-x));
}
__device__ __forceinline__ float tanhf_(float x) {
    float e = __expf(2.0f * x);
    return 1.0f - 2.0f / (e + 1.0f);
}

// ---------------- packed f32x2 helpers (sm_100-family base ISA) -------------
__device__ __forceinline__ void fma2(uint64_t& d, uint64_t a, uint64_t b) {
    asm("fma.rn.f32x2 %0, %1, %2, %0;" : "+l"(d) : "l"(a), "l"(b));
}
__device__ __forceinline__ uint64_t pk2(float x) {
    uint64_t r;
    asm("mov.b64 %0, {%1, %1};" : "=l"(r) : "r"(__float_as_uint(x)));
    return r;
}
__device__ __forceinline__ void upk2(uint64_t v, float& lo, float& hi) {
    uint32_t a, b;
    asm("mov.b64 {%0, %1}, %2;" : "=r"(a), "=r"(b) : "l"(v));
    lo = __uint_as_float(a); hi = __uint_as_float(b);
}

// 4 rows x 4 b (2 packed pairs) outer product for one k, packed FMA
#define FMA16P(u, hv)                         \
    {                                         \
        uint64_t u0 = pk2(u.x), u1 = pk2(u.y);\
        uint64_t u2 = pk2(u.z), u3 = pk2(u.w);\
        fma2(a2[0][0], u0, hv.x);             \
        fma2(a2[0][1], u0, hv.y);             \
        fma2(a2[1][0], u1, hv.x);             \
        fma2(a2[1][1], u1, hv.y);             \
        fma2(a2[2][0], u2, hv.x);             \
        fma2(a2[2][1], u2, hv.y);             \
        fma2(a2[3][0], u3, hv.x);             \
        fma2(a2[3][1], u3, hv.y);             \
    }

// ---- fp32 -> bf16 hi/lo split (packed bf16x2; x -> low half, y -> high) ----
__device__ __forceinline__ void split2(float x, float y, uint32_t& hp, uint32_t& lp) {
    uint32_t h;
    asm("cvt.rn.bf16x2.f32 %0, %1, %2;" : "=r"(h) : "f"(y), "f"(x));
    float xh = __uint_as_float(h << 16);
    float yh = __uint_as_float(h & 0xFFFF0000u);
    float xl = x - xh, yl = y - yh;
    uint32_t l;
    asm("cvt.rn.bf16x2.f32 %0, %1, %2;" : "=r"(l) : "f"(yl), "f"(xl));
    hp = h; lp = l;
}

// ---- warp mma m16n8k16 bf16, fp32 accumulate ----
__device__ __forceinline__ void mma_bf16(float* c, const uint32_t* a, const uint32_t* b) {
    asm volatile(
        "mma.sync.aligned.m16n8k16.row.col.f32.bf16.bf16.f32 "
        "{%0,%1,%2,%3}, {%4,%5,%6,%7}, {%8,%9}, {%0,%1,%2,%3};"
        : "+f"(c[0]), "+f"(c[1]), "+f"(c[2]), "+f"(c[3])
        : "r"(a[0]), "r"(a[1]), "r"(a[2]), "r"(a[3]), "r"(b[0]), "r"(b[1]));
}

// ============================================================================
// HMMA feedforward GEMM (R14, passing): 512 threads, warp tile 32x32
// ============================================================================
__global__ void __launch_bounds__(512, 1) ffn_gemm_mma(
    const float* __restrict__ Aext, int a_is_hs,
    const float* __restrict__ W, const float* __restrict__ bias)
{
    extern __shared__ __align__(16) uint32_t smemu[];
    const float* A0 = a_is_hs ? g_hs : Aext;

    const int tid = threadIdx.x;
    const int wid = tid >> 5, lane = tid & 31;
    const int n0 = blockIdx.x * 128;
    const int m0 = blockIdx.y * 128;
    const int wm = wid >> 2, wn = wid & 3;

    const int row  = tid >> 1;
    const int half = tid & 1;
    const int isB  = (row >= 128);
    const int r    = row & 127;
    const float* srow;
    if (isB) {
        srow = W + (size_t)(n0 + r) * 1024;
    } else {
        int m = m0 + r;
        srow = A0 + ((size_t)(m & 31) * T_ + (m >> 5)) * 1024;
    }
    uint32_t sts_off[2];
#pragma unroll
    for (int j = 0; j < 2; j++) {
        int ktile = half, kb = j;
        if (isB) {
            int ntile = r >> 3, g = r & 7;
            sts_off[j] = 4096u + (uint32_t)(((ktile * 16 + ntile) * 2 + kb) * 32 + g * 4);
        } else {
            int mtile = r >> 4, gp = r & 15;
            int rb0 = gp >> 3, g = gp & 7;
            sts_off[j] = (uint32_t)(((ktile * 8 + mtile) * 4 + rb0 + 2 * kb) * 32 + g * 4);
        }
    }
    const float* sbase = srow + half * 16;

    {
#pragma unroll
        for (int j = 0; j < 2; j++) {
            float4 v0 = __ldg((const float4*)(sbase + j * 8));
            float4 v1 = __ldg((const float4*)(sbase + j * 8 + 4));
            uint32_t h0, h1, h2, h3, l0, l1, l2, l3;
            split2(v0.x, v0.y, h0, l0); split2(v0.z, v0.w, h1, l1);
            split2(v1.x, v1.y, h2, l2); split2(v1.z, v1.w, h3, l3);
            uint32_t* q = smemu + sts_off[j];
            *(uint4*)q          = make_uint4(h0, h1, h2, h3);
            *(uint4*)(q + 2048) = make_uint4(l0, l1, l2, l3);
        }
    }
    __syncthreads();

    float acc[2][4][4];
#pragma unroll
    for (int mt = 0; mt < 2; mt++)
#pragma unroll
        for (int nt = 0; nt < 4; nt++)
#pragma unroll
            for (int e = 0; e < 4; e++) acc[mt][nt][e] = 0.f;

    for (int c = 0; c < 32; c++) {
        const uint32_t* buf = smemu + (c & 1) * 8192;
        float4 pend[4];
        if (c < 31) {
            const float* sp = sbase + (c + 1) * 32;
#pragma unroll
            for (int j = 0; j < 2; j++) {
                pend[2 * j]     = __ldg((const float4*)(sp + j * 8));
                pend[2 * j + 1] = __ldg((const float4*)(sp + j * 8 + 4));
            }
        }
#pragma unroll
        for (int kt = 0; kt < 2; kt++) {
            uint32_t aH[2][4], aL[2][4], bH[4][2], bL[4][2];
#pragma unroll
            for (int mt = 0; mt < 2; mt++) {
                const uint32_t* p = buf + ((kt * 8 + wm * 2 + mt) * 4) * 32 + lane;
#pragma unroll
                for (int rr = 0; rr < 4; rr++) {
                    aH[mt][rr] = p[rr * 32];
                    aL[mt][rr] = p[rr * 32 + 2048];
                }
            }
#pragma unroll
            for (int nt = 0; nt < 4; nt++) {
                const uint32_t* p = buf + 4096 + ((kt * 16 + wn * 4 + nt) * 2) * 32 + lane;
                bH[nt][0] = p[0];    bH[nt][1] = p[32];
                bL[nt][0] = p[2048]; bL[nt][1] = p[2080];
            }
#pragma unroll
            for (int mt = 0; mt < 2; mt++)
#pragma unroll
                for (int nt = 0; nt < 4; nt++) {
                    mma_bf16(acc[mt][nt], aH[mt], bH[nt]);
                    mma_bf16(acc[mt][nt], aH[mt], bL[nt]);
                    mma_bf16(acc[mt][nt], aL[mt], bH[nt]);
                }
        }
        if (c < 31) {
            uint32_t* nb = smemu + ((c + 1) & 1) * 8192;
#pragma unroll
            for (int j = 0; j < 2; j++) {
                uint32_t h0, h1, h2, h3, l0, l1, l2, l3;
                split2(pend[2*j].x,   pend[2*j].y,   h0, l0);
                split2(pend[2*j].z,   pend[2*j].w,   h1, l1);
                split2(pend[2*j+1].x, pend[2*j+1].y, h2, l2);
                split2(pend[2*j+1].z, pend[2*j+1].w, h3, l3);
                uint32_t* q = nb + sts_off[j];
                *(uint4*)q          = make_uint4(h0, h1, h2, h3);
                *(uint4*)(q + 2048) = make_uint4(l0, l1, l2, l3);
            }
        }
        __syncthreads();
    }

    const int g = lane >> 2, cc = lane & 3;
#pragma unroll
    for (int mt = 0; mt < 2; mt++) {
#pragma unroll
        for (int nt = 0; nt < 4; nt++) {
            int mA = m0 + wm * 32 + mt * 16 + g;
            int mB = mA + 8;
            int k0 = n0 + wn * 32 + nt * 8 + 2 * cc;
            float b0 = __ldg(&bias[k0]);
            float b1 = __ldg(&bias[k0 + 1]);
            size_t oA = ((size_t)(mA >> 5) * FH) * B_ + (mA & 31);
            size_t oB = ((size_t)(mB >> 5) * FH) * B_ + (mB & 31);
            g_xw[oA + (size_t)k0 * B_]       = acc[mt][nt][0] + b0;
            g_xw[oA + (size_t)(k0 + 1) * B_] = acc[mt][nt][1] + b1;
            g_xw[oB + (size_t)k0 * B_]       = acc[mt][nt][2] + b0;
            g_xw[oB + (size_t)(k0 + 1) * B_] = acc[mt][nt][3] + b1;
        }
    }
}

// ---------------- small GEMM for xa: out[t][r][b] (fp32) --------------------
__global__ void __launch_bounds__(128) xa_gemm(const float* __restrict__ A)
{
    const float* X = g_hs;
    float* out = g_xa;
    const int t = blockIdx.y;

    __shared__ __align__(16) float sX[32][36];
    __shared__ __align__(16) float sW[32][68];

    const int tid = threadIdx.x;
    const int b4  = (tid & 7) * 4;
    const int k4  = (tid >> 3) * 4;

    float acc[4][4];
#pragma unroll
    for (int i = 0; i < 4; i++)
#pragma unroll
        for (int jx = 0; jx < 4; jx++) acc[i][jx] = 0.f;

    for (int d0 = 0; d0 < 1024; d0 += 32) {
#pragma unroll
        for (int i = 0; i < 2; i++) {
            int qq = tid + i * 128;
            int br = qq >> 3, ds = (qq & 7) * 4;
            float4 v = *(const float4*)(X + ((size_t)br * T_ + t) * 1024 + d0 + ds);
            sX[ds + 0][br] = v.x; sX[ds + 1][br] = v.y;
            sX[ds + 2][br] = v.z; sX[ds + 3][br] = v.w;
        }
#pragma unroll
        for (int i = 0; i < 4; i++) {
            int qq = tid + i * 128;
            int kr = qq >> 3, ds = (qq & 7) * 4;
            float4 v = *(const float4*)(A + (size_t)kr * 1024 + d0 + ds);
            sW[ds + 0][kr] = v.x; sW[ds + 1][kr] = v.y;
            sW[ds + 2][kr] = v.z; sW[ds + 3][kr] = v.w;
        }
        __syncthreads();
#pragma unroll
        for (int d = 0; d < 32; d++) {
            float4 xv = *(const float4*)&sX[d][b4];
            float4 wv = *(const float4*)&sW[d][k4];
            float xs[4] = {xv.x, xv.y, xv.z, xv.w};
            float ws[4] = {wv.x, wv.y, wv.z, wv.w};
#pragma unroll
            for (int i = 0; i < 4; i++)
#pragma unroll
                for (int jx = 0; jx < 4; jx++)
                    acc[i][jx] = fmaf(ws[i], xs[jx], acc[i][jx]);
        }
        __syncthreads();
    }
#pragma unroll
    for (int i = 0; i < 4; i++) {
        float4 r = make_float4(acc[i][0], acc[i][1], acc[i][2], acc[i][3]);
        *(float4*)(out + ((size_t)t * R_ + (k4 + i)) * B_ + b4) = r;
    }
}

// ============================================================================
// Scan v4: U resident in smem, reg-tiled 4x4 with packed f32x2 FMA, K-split 8
// ============================================================================
__device__ __forceinline__ void load_U_smem(float* U_s, const float* U, int jb, int tid) {
    const int row = tid & 31;
    const int g = row & 3, jl = row >> 2;
    const float* Urow = U + (size_t)(g * H_ + jb + jl) * H_;
    for (int k0 = (tid >> 5) * 4; k0 < H_; k0 += 64) {
        float4 v = *(const float4*)(Urow + k0);
        U_s[(k0 + 0) * 32 + row] = v.x;
        U_s[(k0 + 1) * 32 + row] = v.y;
        U_s[(k0 + 2) * 32 + row] = v.z;
        U_s[(k0 + 3) * 32 + row] = v.w;
    }
}

__global__ void __launch_bounds__(512, 1) slstm_scan(
    const float* __restrict__ U, const float* __restrict__ bU,
    const float* __restrict__ alpha)
{
    extern __shared__ __align__(16) float smem_dyn[];
    float* U_s = smem_dyn;
    float* h_s = smem_dyn + 32768;
    float* red = h_s;

    const int tid = threadIdx.x;
    const int ks = tid >> 6, ty = (tid >> 3) & 7, tx = tid & 7;
    const int jb = blockIdx.x * 8;

    load_U_smem(U_s, U, jb, tid);

    int gid = blockIdx.x * 512 + tid;
    if (gid < H_ * B_) __stcg(&g_hT[0][gid], 0.f);
    __threadfence();
    grid_sync();

    const int sj = tid >> 5, sb = tid & 31;
    const int jglob = jb + sj;
    float c = 0.f;
    float balph = 0.f, bi = 0.f, bf = 0.f, bo = 0.f, bg = 0.f;
    if (tid < 256) {
        balph = __ldg(&alpha[jglob]);
        bi = __ldg(&bU[jglob]);
        bf = __ldg(&bU[H_ + jglob]);
        bo = __ldg(&bU[2 * H_ + jglob]);
        bg = __ldg(&bU[3 * H_ + jglob]);
    }

    int p = 0;
    for (int t = 0; t < T_; t++) {
        float xi = 0.f, xf = 0.f, xo = 0.f, xg = 0.f;
        if (tid < 256) {
            const float* xwt = g_xw + (size_t)t * FH * B_;
            xi = __ldg(xwt + (size_t)jglob * B_ + sb);
            xf = __ldg(xwt + (size_t)(H_ + jglob) * B_ + sb);
            xo = __ldg(xwt + (size_t)(2 * H_ + jglob) * B_ + sb);
            xg = __ldg(xwt + (size_t)(3 * H_ + jglob) * B_ + sb);
        }

        const float4* hsrc = (const float4*)(&g_hT[p][0]);
        float4 rg[8];
#pragma unroll
        for (int i = 0; i < 8; i++) rg[i] = __ldcg(hsrc + tid + i * 512);
        {
            float4* d4 = (float4*)h_s;
#pragma unroll
            for (int i = 0; i < 8; i++) d4[tid + i * 512] = rg[i];
        }
        __syncthreads();
#pragma unroll
        for (int i = 0; i < 8; i++) rg[i] = __ldcg(hsrc + 4096 + tid + i * 512);

        uint64_t a2[4][2];
#pragma unroll
        for (int i = 0; i < 4; i++) { a2[i][0] = 0ull; a2[i][1] = 0ull; }

        {
            const float* Ub = U_s + (size_t)(ks * 64) * 32 + 4 * ty;
            const char*  Hb = (const char*)(h_s + (size_t)(ks * 64) * 32 + 4 * tx);
#pragma unroll 8
            for (int kk = 0; kk < 64; kk++) {
                float4 u = *(const float4*)(Ub + kk * 32);
                ulonglong2 hv = *(const ulonglong2*)(Hb + kk * 128);
                FMA16P(u, hv)
            }
        }
        __syncthreads();
        {
            float4* d4 = (float4*)h_s;
#pragma unroll
            for (int i = 0; i < 8; i++) d4[tid + i * 512] = rg[i];
        }
        __syncthreads();
        {
            const float* Ub = U_s + (size_t)(512 + ks * 64) * 32 + 4 * ty;
            const char*  Hb = (const char*)(h_s + (size_t)(ks * 64) * 32 + 4 * tx);
#pragma unroll 8
            for (int kk = 0; kk < 64; kk++) {
                float4 u = *(const float4*)(Ub + kk * 32);
                ulonglong2 hv = *(const ulonglong2*)(Hb + kk * 128);
                FMA16P(u, hv)
            }
        }
        __syncthreads();
#pragma unroll
        for (int i = 0; i < 4; i++) {
            float* rr = red + (size_t)(ks * 32 + 4 * ty + i) * 33 + 4 * tx;
            upk2(a2[i][0], rr[0], rr[1]);
            upk2(a2[i][1], rr[2], rr[3]);
        }
        __syncthreads();
        if (tid < 256) {
            float s0 = 0.f, s1 = 0.f, s2 = 0.f, s3 = 0.f;
#pragma unroll
            for (int k2 = 0; k2 < 8; k2++) {
                const float* rr = red + (size_t)k2 * 32 * 33 + sb;
                s0 += rr[(sj * 4 + 0) * 33];
                s1 += rr[(sj * 4 + 1) * 33];
                s2 += rr[(sj * 4 + 2) * 33];
                s3 += rr[(sj * 4 + 3) * 33];
            }
            float iv = sigmoidf_(xi + bi + s0);
            float fv = sigmoidf_(xf + bf + s1);
            float ov = sigmoidf_(xo + bo + s2);
            float gv = tanhf_(xg + bg + s3);
            c = balph * (fv * c + iv * gv);
            float h = ov * tanhf_(c);
            __stcg(&g_hT[p ^ 1][jglob * B_ + sb], h);
            g_hs[((size_t)sb * T_ + t) * H_ + jglob] = h;
        }
        __threadfence();
        grid_sync();
        p ^= 1;
    }
}

__global__ void __launch_bounds__(512, 1) mlstm_scan(
    const float* __restrict__ U, const float* __restrict__ bU,
    const float* __restrict__ Bm, const float* __restrict__ P,
    float* __restrict__ out)
{
    extern __shared__ __align__(16) float smem_dyn[];
    float* U_s = smem_dyn;
    float* h_s = smem_dyn + 32768;
    float* red = h_s;
    float* s_s = h_s;

    __shared__ float Bm_s[1024];
    __shared__ float q_s[8][16];

    const int tid = threadIdx.x;
    const int ks = tid >> 6, ty = (tid >> 3) & 7, tx = tid & 7;
    const int jb = blockIdx.x * 8;
    const int rq = blockIdx.x & 63;
    const int bh = blockIdx.x >> 6;

    load_U_smem(U_s, U, jb, tid);
    {
        const float* Bmr = Bm + (size_t)rq * H_;
        for (int i = tid; i < 256; i += 512)
            *(float4*)&Bm_s[i * 4] = __ldg((const float4*)(Bmr + i * 4));
    }

    int gid = blockIdx.x * 512 + tid;
    if (gid < H_ * B_) __stcg(&g_hT[0][gid], 0.f);
    __threadfence();
    grid_sync();

    const int sj = tid >> 5, sb = tid & 31;
    const int jglob = jb + sj;
    float c = 0.f;
    float bi = 0.f, bf = 0.f, bo = 0.f, bg = 0.f;
    if (tid < 256) {
        bi = __ldg(&bU[jglob]);
        bf = __ldg(&bU[H_ + jglob]);
        bo = __ldg(&bU[2 * H_ + jglob]);
        bg = __ldg(&bU[3 * H_ + jglob]);
    }
    const float* Pj = P + (size_t)jglob * R_;
    const int qb = tid & 15, qk = tid >> 4;

    int p = 0;
    for (int t = 0; t < T_; t++) {
        float xi = 0.f, xf = 0.f, xo = 0.f, xg = 0.f;
        if (tid < 256) {
            const float* xwt = g_xw + (size_t)t * FH * B_;
            xi = __ldg(xwt + (size_t)jglob * B_ + sb);
            xf = __ldg(xwt + (size_t)(H_ + jglob) * B_ + sb);
            xo = __ldg(xwt + (size_t)(2 * H_ + jglob) * B_ + sb);
            xg = __ldg(xwt + (size_t)(3 * H_ + jglob) * B_ + sb);
        }

        const float4* hsrc = (const float4*)(&g_hT[p][0]);
        float4 rg[8];
#pragma unroll
        for (int i = 0; i < 8; i++) rg[i] = __ldcg(hsrc + tid + i * 512);
        {
            float4* d4 = (float4*)h_s;
#pragma unroll
            for (int i = 0; i < 8; i++) d4[tid + i * 512] = rg[i];
        }
        __syncthreads();
#pragma unroll
        for (int i = 0; i < 8; i++) rg[i] = __ldcg(hsrc + 4096 + tid + i * 512);

        uint64_t a2[4][2];
#pragma unroll
        for (int i = 0; i < 4; i++) { a2[i][0] = 0ull; a2[i][1] = 0ull; }
        float qpart = 0.f;

        {
            const float* Ub = U_s + (size_t)(ks * 64) * 32 + 4 * ty;
            const char*  Hb = (const char*)(h_s + (size_t)(ks * 64) * 32 + 4 * tx);
#pragma unroll 8
            for (int kk = 0; kk < 64; kk++) {
                float4 u = *(const float4*)(Ub + kk * 32);
                ulonglong2 hv = *(const ulonglong2*)(Hb + kk * 128);
                FMA16P(u, hv)
            }
        }
        if (tid < 128) {
            const int bcol = bh * 16 + qb;
#pragma unroll 4
            for (int k4 = 0; k4 < 64; k4 += 4) {
                float4 bm = *(const float4*)&Bm_s[qk * 64 + k4];
                const float* hb = h_s + (size_t)(qk * 64 + k4) * 32 + bcol;
                qpart = fmaf(bm.x, hb[0],  qpart);
                qpart = fmaf(bm.y, hb[32], qpart);
                qpart = fmaf(bm.z, hb[64], qpart);
                qpart = fmaf(bm.w, hb[96], qpart);
            }
        }
        __syncthreads();
        {
            float4* d4 = (float4*)h_s;
#pragma unroll
            for (int i = 0; i < 8; i++) d4[tid + i * 512] = rg[i];
        }
        __syncthreads();
        {
            const float* Ub = U_s + (size_t)(512 + ks * 64) * 32 + 4 * ty;
            const char*  Hb = (const char*)(h_s + (size_t)(ks * 64) * 32 + 4 * tx);
#pragma unroll 8
            for (int kk = 0; kk < 64; kk++) {
                float4 u = *(const float4*)(Ub + kk * 32);
                ulonglong2 hv = *(const ulonglong2*)(Hb + kk * 128);
                FMA16P(u, hv)
            }
        }
        if (tid < 128) {
            const int bcol = bh * 16 + qb;
#pragma unroll 4
            for (int k4 = 0; k4 < 64; k4 += 4) {
                float4 bm = *(const float4*)&Bm_s[512 + qk * 64 + k4];
                const float* hb = h_s + (size_t)(qk * 64 + k4) * 32 + bcol;
                qpart = fmaf(bm.x, hb[0],  qpart);
                qpart = fmaf(bm.y, hb[32], qpart);
                qpart = fmaf(bm.z, hb[64], qpart);
                qpart = fmaf(bm.w, hb[96], qpart);
            }
        }
        __syncthreads();
#pragma unroll
        for (int i = 0; i < 4; i++) {
            float* rr = red + (size_t)(ks * 32 + 4 * ty + i) * 33 + 4 * tx;
            upk2(a2[i][0], rr[0], rr[1]);
            upk2(a2[i][1], rr[2], rr[3]);
        }
        if (tid < 128) q_s[qk][qb] = qpart;
        __syncthreads();

        float a0 = 0.f, a1 = 0.f, a2s = 0.f, a3 = 0.f;
        if (tid < 256) {
#pragma unroll
            for (int k2 = 0; k2 < 8; k2++) {
                const float* rr = red + (size_t)k2 * 32 * 33 + sb;
                a0  += rr[(sj * 4 + 0) * 33];
                a1  += rr[(sj * 4 + 1) * 33];
                a2s += rr[(sj * 4 + 2) * 33];
                a3  += rr[(sj * 4 + 3) * 33];
            }
            a0 += xi + bi; a1 += xf + bf; a2s += xo + bo; a3 += xg + bg;
        }
        if (tid < 16) {
            float q = 0.f;
#pragma unroll
            for (int s2 = 0; s2 < 8; s2++) q += q_s[s2][tid];
            int bb = bh * 16 + tid;
            float xav = __ldg(&g_xa[((size_t)t * R_ + rq) * B_ + bb]);
            __stcg(&g_s[rq * B_ + bb], xav * q);
        }
        __threadfence();
        grid_sync();

        ((float4*)s_s)[tid] = __ldcg(((const float4*)g_s) + tid);
        __syncthreads();
        if (tid < 256) {
            float mix = 0.f;
#pragma unroll
            for (int r = 0; r < R_; r += 4) {
                float4 pv = __ldg((const float4*)(Pj + r));
                mix = fmaf(pv.x, s_s[(r + 0) * B_ + sb], mix);
                mix = fmaf(pv.y, s_s[(r + 1) * B_ + sb], mix);
                mix = fmaf(pv.z, s_s[(r + 2) * B_ + sb], mix);
                mix = fmaf(pv.w, s_s[(r + 3) * B_ + sb], mix);
            }
            float iv = sigmoidf_(a0), fv = sigmoidf_(a1);
            float ov = sigmoidf_(a2s), gv = tanhf_(a3);
            c = fv * c + iv * gv + 0.1f * mix;
            float h = ov * tanhf_(c);
            __stcg(&g_hT[p ^ 1][jglob * B_ + sb], h);
            out[((size_t)sb * T_ + t) * H_ + jglob] = h;
        }
        __threadfence();
        grid_sync();
        p ^= 1;
    }
}

// ---------------- launch -----------------------------------------------------
extern "C" void kernel_launch(void* const* d_in, const int* in_sizes, int n_in,
                              void* d_out, int out_size)
{
    (void)in_sizes; (void)n_in; (void)out_size;
    const float* x     = (const float*)d_in[0];
    const float* Ws    = (const float*)d_in[1];
    const float* bWs   = (const float*)d_in[2];
    const float* Us    = (const float*)d_in[3];
    const float* bUs   = (const float*)d_in[4];
    const float* alpha = (const float*)d_in[5];
    const float* Wm    = (const float*)d_in[6];
    const float* bWm   = (const float*)d_in[7];
    const float* Um    = (const float*)d_in[8];
    const float* bUm   = (const float*)d_in[9];
    const float* A     = (const float*)d_in[10];
    const float* Bm    = (const float*)d_in[11];
    const float* P     = (const float*)d_in[12];

    cudaFuncSetAttribute(slstm_scan, cudaFuncAttributeMaxDynamicSharedMemorySize,
                         SMEM_SCAN_BYTES);
    cudaFuncSetAttribute(mlstm_scan, cudaFuncAttributeMaxDynamicSharedMemorySize,
                         SMEM_SCAN_BYTES);
    cudaFuncSetAttribute(ffn_gemm_mma, cudaFuncAttributeMaxDynamicSharedMemorySize,
                         SMEM_GEMM_BYTES);

    dim3 gG(FH / 128, (B_ * T_) / 128);  // 32 n-tiles x 128 m-tiles
    ffn_gemm_mma<<<gG, 512, SMEM_GEMM_BYTES>>>(x, 0, Ws, bWs);
    slstm_scan<<<NCTA, 512, SMEM_SCAN_BYTES>>>(Us, bUs, alpha);
    xa_gemm<<<dim3(1, T_), 128>>>(A);
    ffn_gemm_mma<<<gG, 512, SMEM_GEMM_BYTES>>>(nullptr, 1, Wm, bWm);
    mlstm_scan<<<NCTA, 512, SMEM_SCAN_BYTES>>>(Um, bUm, Bm, P, (float*)d_out);
}

// round 16
// speedup vs baseline: 4.5786x; 1.2564x over previous
#include <cuda_runtime.h>
#include <cuda_bf16.h>
#include <math.h>
#include <stdint.h>

#define B_   32
#define T_   512
#define D_   1024
#define H_   1024
#define R_   64
#define FH   4096
#define NCTA 128

// mma gemm dynamic smem: 2 buffers x 32 KB
#define SMEM_GEMM_BYTES 65536
// scan v5 dynamic smem: sLSTM 128KB (Ulo 64K | D_s 64K), mLSTM +64KB h_q
#define SMEM_SL_BYTES 131072
#define SMEM_ML_BYTES 196608

// ---------------- scratch (device globals: allocation-free) ----------------
__device__ __align__(16) float g_xw[(size_t)T_ * FH * B_];   // [t][k][b]
__device__ __align__(16) float g_hs[(size_t)B_ * T_ * H_];   // [b][t][h]
__device__ __align__(16) float g_xa[(size_t)T_ * R_ * B_];   // [t][r][b]
__device__ __align__(16) float g_hT[2][H_ * B_];             // h fp32 dbl buf [j][b]
__device__ __align__(16) float g_s[R_ * B_];                 // [r][b]
// h as bf16 A-fragments (hi/lo), double buffered: [kt(64)][mt(2)][lane(32)][reg(4)] u32
__device__ __align__(16) uint32_t g_hfH[2][16384];
__device__ __align__(16) uint32_t g_hfL[2][16384];
__device__ unsigned g_bar_count = 0;
__device__ unsigned g_bar_gen   = 0;

// ---------------- software grid barrier -------------------------------------
__device__ __forceinline__ void grid_sync() {
    __syncthreads();
    if (threadIdx.x == 0) {
        volatile unsigned* vgen = &g_bar_gen;
        unsigned gen = *vgen;
        __threadfence();
        if (atomicAdd(&g_bar_count, 1u) == (unsigned)(NCTA - 1)) {
            atomicExch(&g_bar_count, 0u);
            __threadfence();
            atomicAdd(&g_bar_gen, 1u);
        } else {
            while (*vgen == gen) { }
        }
        __threadfence();
    }
    __syncthreads();
}

__device__ __forceinline__ float sigmoidf_(float x) {
    return 1.0f / (1.0f + __expf(-x));
}
__device__ __forceinline__ float tanhf_(float x) {
    float e = __expf(2.0f * x);
    return 1.0f - 2.0f / (e + 1.0f);
}

// ---- fp32 -> bf16 hi/lo split (packed bf16x2; x -> low half, y -> high) ----
__device__ __forceinline__ void split2(float x, float y, uint32_t& hp, uint32_t& lp) {
    uint32_t h;
    asm("cvt.rn.bf16x2.f32 %0, %1, %2;" : "=r"(h) : "f"(y), "f"(x));
    float xh = __uint_as_float(h << 16);
    float yh = __uint_as_float(h & 0xFFFF0000u);
    float xl = x - xh, yl = y - yh;
    uint32_t l;
    asm("cvt.rn.bf16x2.f32 %0, %1, %2;" : "=r"(l) : "f"(yl), "f"(xl));
    hp = h; lp = l;
}

// ---- warp mma m16n8k16 bf16, fp32 accumulate ----
__device__ __forceinline__ void mma_bf16(float* c, const uint32_t* a, const uint32_t* b) {
    asm volatile(
        "mma.sync.aligned.m16n8k16.row.col.f32.bf16.bf16.f32 "
        "{%0,%1,%2,%3}, {%4,%5,%6,%7}, {%8,%9}, {%0,%1,%2,%3};"
        : "+f"(c[0]), "+f"(c[1]), "+f"(c[2]), "+f"(c[3])
        : "r"(a[0]), "r"(a[1]), "r"(a[2]), "r"(a[3]), "r"(b[0]), "r"(b[1]));
}

// ============================================================================
// HMMA feedforward GEMM (R14, passing, unchanged)
// ============================================================================
__global__ void __launch_bounds__(512, 1) ffn_gemm_mma(
    const float* __restrict__ Aext, int a_is_hs,
    const float* __restrict__ W, const float* __restrict__ bias)
{
    extern __shared__ __align__(16) uint32_t smemu[];
    const float* A0 = a_is_hs ? g_hs : Aext;

    const int tid = threadIdx.x;
    const int wid = tid >> 5, lane = tid & 31;
    const int n0 = blockIdx.x * 128;
    const int m0 = blockIdx.y * 128;
    const int wm = wid >> 2, wn = wid & 3;

    const int row  = tid >> 1;
    const int half = tid & 1;
    const int isB  = (row >= 128);
    const int r    = row & 127;
    const float* srow;
    if (isB) {
        srow = W + (size_t)(n0 + r) * 1024;
    } else {
        int m = m0 + r;
        srow = A0 + ((size_t)(m & 31) * T_ + (m >> 5)) * 1024;
    }
    uint32_t sts_off[2];
#pragma unroll
    for (int j = 0; j < 2; j++) {
        int ktile = half, kb = j;
        if (isB) {
            int ntile = r >> 3, g = r & 7;
            sts_off[j] = 4096u + (uint32_t)(((ktile * 16 + ntile) * 2 + kb) * 32 + g * 4);
        } else {
            int mtile = r >> 4, gp = r & 15;
            int rb0 = gp >> 3, g = gp & 7;
            sts_off[j] = (uint32_t)(((ktile * 8 + mtile) * 4 + rb0 + 2 * kb) * 32 + g * 4);
        }
    }
    const float* sbase = srow + half * 16;

    {
#pragma unroll
        for (int j = 0; j < 2; j++) {
            float4 v0 = __ldg((const float4*)(sbase + j * 8));
            float4 v1 = __ldg((const float4*)(sbase + j * 8 + 4));
            uint32_t h0, h1, h2, h3, l0, l1, l2, l3;
            split2(v0.x, v0.y, h0, l0); split2(v0.z, v0.w, h1, l1);
            split2(v1.x, v1.y, h2, l2); split2(v1.z, v1.w, h3, l3);
            uint32_t* q = smemu + sts_off[j];
            *(uint4*)q          = make_uint4(h0, h1, h2, h3);
            *(uint4*)(q + 2048) = make_uint4(l0, l1, l2, l3);
        }
    }
    __syncthreads();

    float acc[2][4][4];
#pragma unroll
    for (int mt = 0; mt < 2; mt++)
#pragma unroll
        for (int nt = 0; nt < 4; nt++)
#pragma unroll
            for (int e = 0; e < 4; e++) acc[mt][nt][e] = 0.f;

    for (int c = 0; c < 32; c++) {
        const uint32_t* buf = smemu + (c & 1) * 8192;
        float4 pend[4];
        if (c < 31) {
            const float* sp = sbase + (c + 1) * 32;
#pragma unroll
            for (int j = 0; j < 2; j++) {
                pend[2 * j]     = __ldg((const float4*)(sp + j * 8));
                pend[2 * j + 1] = __ldg((const float4*)(sp + j * 8 + 4));
            }
        }
#pragma unroll
        for (int kt = 0; kt < 2; kt++) {
            uint32_t aH[2][4], aL[2][4], bH[4][2], bL[4][2];
#pragma unroll
            for (int mt = 0; mt < 2; mt++) {
                const uint32_t* p = buf + ((kt * 8 + wm * 2 + mt) * 4) * 32 + lane;
#pragma unroll
                for (int rr = 0; rr < 4; rr++) {
                    aH[mt][rr] = p[rr * 32];
                    aL[mt][rr] = p[rr * 32 + 2048];
                }
            }
#pragma unroll
            for (int nt = 0; nt < 4; nt++) {
                const uint32_t* p = buf + 4096 + ((kt * 16 + wn * 4 + nt) * 2) * 32 + lane;
                bH[nt][0] = p[0];    bH[nt][1] = p[32];
                bL[nt][0] = p[2048]; bL[nt][1] = p[2080];
            }
#pragma unroll
            for (int mt = 0; mt < 2; mt++)
#pragma unroll
                for (int nt = 0; nt < 4; nt++) {
                    mma_bf16(acc[mt][nt], aH[mt], bH[nt]);
                    mma_bf16(acc[mt][nt], aH[mt], bL[nt]);
                    mma_bf16(acc[mt][nt], aL[mt], bH[nt]);
                }
        }
        if (c < 31) {
            uint32_t* nb = smemu + ((c + 1) & 1) * 8192;
#pragma unroll
            for (int j = 0; j < 2; j++) {
                uint32_t h0, h1, h2, h3, l0, l1, l2, l3;
                split2(pend[2*j].x,   pend[2*j].y,   h0, l0);
                split2(pend[2*j].z,   pend[2*j].w,   h1, l1);
                split2(pend[2*j+1].x, pend[2*j+1].y, h2, l2);
                split2(pend[2*j+1].z, pend[2*j+1].w, h3, l3);
                uint32_t* q = nb + sts_off[j];
                *(uint4*)q          = make_uint4(h0, h1, h2, h3);
                *(uint4*)(q + 2048) = make_uint4(l0, l1, l2, l3);
            }
        }
        __syncthreads();
    }

    const int g = lane >> 2, cc = lane & 3;
#pragma unroll
    for (int mt = 0; mt < 2; mt++) {
#pragma unroll
        for (int nt = 0; nt < 4; nt++) {
            int mA = m0 + wm * 32 + mt * 16 + g;
            int mB = mA + 8;
            int k0 = n0 + wn * 32 + nt * 8 + 2 * cc;
            float b0 = __ldg(&bias[k0]);
            float b1 = __ldg(&bias[k0 + 1]);
            size_t oA = ((size_t)(mA >> 5) * FH) * B_ + (mA & 31);
            size_t oB = ((size_t)(mB >> 5) * FH) * B_ + (mB & 31);
            g_xw[oA + (size_t)k0 * B_]       = acc[mt][nt][0] + b0;
            g_xw[oA + (size_t)(k0 + 1) * B_] = acc[mt][nt][1] + b1;
            g_xw[oB + (size_t)k0 * B_]       = acc[mt][nt][2] + b0;
            g_xw[oB + (size_t)(k0 + 1) * B_] = acc[mt][nt][3] + b1;
        }
    }
}

// ---------------- small GEMM for xa: out[t][r][b] (fp32, unchanged) ---------
__global__ void __launch_bounds__(128) xa_gemm(const float* __restrict__ A)
{
    const float* X = g_hs;
    float* out = g_xa;
    const int t = blockIdx.y;

    __shared__ __align__(16) float sX[32][36];
    __shared__ __align__(16) float sW[32][68];

    const int tid = threadIdx.x;
    const int b4  = (tid & 7) * 4;
    const int k4  = (tid >> 3) * 4;

    float acc[4][4];
#pragma unroll
    for (int i = 0; i < 4; i++)
#pragma unroll
        for (int jx = 0; jx < 4; jx++) acc[i][jx] = 0.f;

    for (int d0 = 0; d0 < 1024; d0 += 32) {
#pragma unroll
        for (int i = 0; i < 2; i++) {
            int qq = tid + i * 128;
            int br = qq >> 3, ds = (qq & 7) * 4;
            float4 v = *(const float4*)(X + ((size_t)br * T_ + t) * 1024 + d0 + ds);
            sX[ds + 0][br] = v.x; sX[ds + 1][br] = v.y;
            sX[ds + 2][br] = v.z; sX[ds + 3][br] = v.w;
        }
#pragma unroll
        for (int i = 0; i < 4; i++) {
            int qq = tid + i * 128;
            int kr = qq >> 3, ds = (qq & 7) * 4;
            float4 v = *(const float4*)(A + (size_t)kr * 1024 + d0 + ds);
            sW[ds + 0][kr] = v.x; sW[ds + 1][kr] = v.y;
            sW[ds + 2][kr] = v.z; sW[ds + 3][kr] = v.w;
        }
        __syncthreads();
#pragma unroll
        for (int d = 0; d < 32; d++) {
            float4 xv = *(const float4*)&sX[d][b4];
            float4 wv = *(const float4*)&sW[d][k4];
            float xs[4] = {xv.x, xv.y, xv.z, xv.w};
            float ws[4] = {wv.x, wv.y, wv.z, wv.w};
#pragma unroll
            for (int i = 0; i < 4; i++)
#pragma unroll
                for (int jx = 0; jx < 4; jx++)
                    acc[i][jx] = fmaf(ws[i], xs[jx], acc[i][jx]);
        }
        __syncthreads();
    }
#pragma unroll
    for (int i = 0; i < 4; i++) {
        float4 r = make_float4(acc[i][0], acc[i][1], acc[i][2], acc[i][3]);
        *(float4*)(out + ((size_t)t * R_ + (k4 + i)) * B_ + b4) = r;
    }
}

// ============================================================================
// Scan v5 common: stage U bf16 hi/lo into mma B-frag layout.
// B frag word (per CTA): ((kt*4 + nt)*2 + kb)*32 + lane, kt 0..63, nt = gate.
// n = gate*8 + jl; source row U[gate*H + jb + jl].
// ============================================================================
__device__ __forceinline__ void stage_U_frags(
    uint32_t* Uhi, uint32_t* Ulo, const float* __restrict__ U, int jb, int tid)
{
#pragma unroll
    for (int i = 0; i < 8; i++) {
        int tk = tid + i * 512;              // 0..4095
        int n  = tk & 31;
        int kt = (tk >> 5) & 63;
        int kb = tk >> 11;
        const float* src = U + ((size_t)((n >> 3) * H_ + jb + (n & 7))) * H_
                             + kt * 16 + kb * 8;
        float4 v0 = __ldg((const float4*)src);
        float4 v1 = __ldg((const float4*)(src + 4));
        uint32_t h0, h1, h2, h3, l0, l1, l2, l3;
        split2(v0.x, v0.y, h0, l0); split2(v0.z, v0.w, h1, l1);
        split2(v1.x, v1.y, h2, l2); split2(v1.z, v1.w, h3, l3);
        uint32_t word = (uint32_t)(((kt * 4 + (n >> 3)) * 2 + kb) * 32 + (n & 7) * 4);
        *(uint4*)(Uhi + word) = make_uint4(h0, h1, h2, h3);
        *(uint4*)(Ulo + word) = make_uint4(l0, l1, l2, l3);
    }
}

// per-warp recurrent mma: 4 ktiles, 4 ntiles, 2 mtiles, 3 products
#define SCAN_MMA_BODY(acc, hfH, hfL, Ulo, bH, w, lane)                         \
    _Pragma("unroll")                                                          \
    for (int il = 0; il < 4; il++) {                                           \
        int kt = (w << 2) + il;                                                \
        uint4 ah0 = __ldcg(((const uint4*)hfH) + (kt * 2 + 0) * 32 + lane);    \
        uint4 ah1 = __ldcg(((const uint4*)hfH) + (kt * 2 + 1) * 32 + lane);    \
        uint4 al0 = __ldcg(((const uint4*)hfL) + (kt * 2 + 0) * 32 + lane);    \
        uint4 al1 = __ldcg(((const uint4*)hfL) + (kt * 2 + 1) * 32 + lane);    \
        _Pragma("unroll")                                                      \
        for (int nt = 0; nt < 4; nt++) {                                       \
            uint32_t bl[2];                                                    \
            bl[0] = Ulo[((kt * 4 + nt) * 2 + 0) * 32 + lane];                  \
            bl[1] = Ulo[((kt * 4 + nt) * 2 + 1) * 32 + lane];                  \
            mma_bf16(acc[0][nt], &ah0.x, bH[il][nt]);                          \
            mma_bf16(acc[0][nt], &ah0.x, bl);                                  \
            mma_bf16(acc[0][nt], &al0.x, bH[il][nt]);                          \
            mma_bf16(acc[1][nt], &ah1.x, bH[il][nt]);                          \
            mma_bf16(acc[1][nt], &ah1.x, bl);                                  \
            mma_bf16(acc[1][nt], &al1.x, bH[il][nt]);                          \
        }                                                                      \
    }

// gate-thread: write h into A-frag layout for (m=sb, k=jglob)
__device__ __forceinline__ void store_h_frag(int p_next, int jglob, int sb, float h) {
    int kt = jglob >> 4, kk = jglob & 15;
    int mt = sb >> 4,    mi = sb & 15;
    int reg = ((mi >= 8) ? 1 : 0) + ((kk >= 8) ? 2 : 0);
    int lw  = (mi & 7) * 4 + ((kk & 7) >> 1);
    int word = ((kt * 2 + mt) * 32 + lw) * 4 + reg;
    uint32_t hp, lp;
    split2(h, 0.f, hp, lp);
    ((uint16_t*)g_hfH[p_next])[word * 2 + (kk & 1)] = (uint16_t)(hp & 0xFFFFu);
    ((uint16_t*)g_hfL[p_next])[word * 2 + (kk & 1)] = (uint16_t)(lp & 0xFFFFu);
}

// ============================================================================
// sLSTM scan v5 (HMMA recurrent step)
// ============================================================================
__global__ void __launch_bounds__(512, 1) slstm_scan(
    const float* __restrict__ U, const float* __restrict__ bU,
    const float* __restrict__ alpha)
{
    extern __shared__ __align__(16) uint32_t dyn[];
    uint32_t* Ulo = dyn;                 // 16384 u32
    float*    D_s = (float*)(dyn + 16384);  // 16384 f32 (also U-hi staging)
    uint32_t* Uhi = dyn + 16384;

    const int tid = threadIdx.x, w = tid >> 5, lane = tid & 31;
    const int jb = blockIdx.x * 8;

    stage_U_frags(Uhi, Ulo, U, jb, tid);
    __syncthreads();
    uint32_t bH[4][4][2];
#pragma unroll
    for (int il = 0; il < 4; il++)
#pragma unroll
        for (int nt = 0; nt < 4; nt++) {
            int kt = (w << 2) + il;
            bH[il][nt][0] = Uhi[((kt * 4 + nt) * 2 + 0) * 32 + lane];
            bH[il][nt][1] = Uhi[((kt * 4 + nt) * 2 + 1) * 32 + lane];
        }

    int gid = blockIdx.x * 512 + tid;
    if (gid < 16384) { g_hfH[0][gid] = 0u; g_hfL[0][gid] = 0u; }
    __threadfence();
    grid_sync();

    const int sj = tid >> 5, sb = tid & 31;     // gate threads: tid < 256
    const int jglob = jb + sj;
    float c = 0.f;
    float balph = 0.f, bi = 0.f, bf = 0.f, bo = 0.f, bg = 0.f;
    if (tid < 256) {
        balph = __ldg(&alpha[jglob]);
        bi = __ldg(&bU[jglob]);
        bf = __ldg(&bU[H_ + jglob]);
        bo = __ldg(&bU[2 * H_ + jglob]);
        bg = __ldg(&bU[3 * H_ + jglob]);
    }
    const int mtR   = sb >> 4;
    const int laneR = (sb & 7) * 4 + (sj >> 1);
    const int eR    = (((sb & 15) >= 8) ? 2 : 0) + (sj & 1);

    int p = 0;
    for (int t = 0; t < T_; t++) {
        float xi = 0.f, xf = 0.f, xo = 0.f, xg = 0.f;
        if (tid < 256) {
            const float* xwt = g_xw + (size_t)t * FH * B_;
            xi = __ldg(xwt + (size_t)jglob * B_ + sb);
            xf = __ldg(xwt + (size_t)(H_ + jglob) * B_ + sb);
            xo = __ldg(xwt + (size_t)(2 * H_ + jglob) * B_ + sb);
            xg = __ldg(xwt + (size_t)(3 * H_ + jglob) * B_ + sb);
        }

        float acc[2][4][4];
#pragma unroll
        for (int mt = 0; mt < 2; mt++)
#pragma unroll
            for (int nt = 0; nt < 4; nt++)
#pragma unroll
                for (int e = 0; e < 4; e++) acc[mt][nt][e] = 0.f;

        SCAN_MMA_BODY(acc, g_hfH[p], g_hfL[p], Ulo, bH, w, lane)

#pragma unroll
        for (int mt = 0; mt < 2; mt++)
#pragma unroll
            for (int nt = 0; nt < 4; nt++)
                *(float4*)(D_s + (size_t)(((w * 2 + mt) * 4 + nt) * 32 + lane) * 4)
                    = *(float4*)acc[mt][nt];
        __syncthreads();

        if (tid < 256) {
            float a[4];
#pragma unroll
            for (int gt = 0; gt < 4; gt++) {
                float s = 0.f;
#pragma unroll
                for (int ksv = 0; ksv < 16; ksv++)
                    s += D_s[(size_t)(((ksv * 2 + mtR) * 4 + gt) * 32 + laneR) * 4 + eR];
                a[gt] = s;
            }
            float iv = sigmoidf_(xi + bi + a[0]);
            float fv = sigmoidf_(xf + bf + a[1]);
            float ov = sigmoidf_(xo + bo + a[2]);
            float gv = tanhf_(xg + bg + a[3]);
            c = balph * (fv * c + iv * gv);
            float h = ov * tanhf_(c);
            store_h_frag(p ^ 1, jglob, sb, h);
            g_hs[((size_t)sb * T_ + t) * H_ + jglob] = h;
        }
        __threadfence();
        grid_sync();
        p ^= 1;
    }
}

// ============================================================================
// mLSTM scan v5 (HMMA recurrent step + low-rank mix; 2 barriers/step)
// ============================================================================
__global__ void __launch_bounds__(512, 1) mlstm_scan(
    const float* __restrict__ U, const float* __restrict__ bU,
    const float* __restrict__ Bm, const float* __restrict__ P,
    float* __restrict__ out)
{
    extern __shared__ __align__(16) uint32_t dyn[];
    uint32_t* Ulo = dyn;                       // 16384 u32
    float*    D_s = (float*)(dyn + 16384);     // 16384 f32 (also U-hi staging)
    uint32_t* Uhi = dyn + 16384;
    float*    h_q = (float*)(dyn + 32768);     // 16384 f32: [k][16 b of half]
    float*    s_s = h_q;                       // phase-B alias (2048 f32)

    __shared__ float Bm_s[1024];
    __shared__ float q_s[8][16];

    const int tid = threadIdx.x, w = tid >> 5, lane = tid & 31;
    const int jb = blockIdx.x * 8;
    const int rq = blockIdx.x & 63;
    const int bh = blockIdx.x >> 6;

    stage_U_frags(Uhi, Ulo, U, jb, tid);
    {
        const float* Bmr = Bm + (size_t)rq * H_;
        for (int i = tid; i < 256; i += 512)
            *(float4*)&Bm_s[i * 4] = __ldg((const float4*)(Bmr + i * 4));
    }
    __syncthreads();
    uint32_t bH[4][4][2];
#pragma unroll
    for (int il = 0; il < 4; il++)
#pragma unroll
        for (int nt = 0; nt < 4; nt++) {
            int kt = (w << 2) + il;
            bH[il][nt][0] = Uhi[((kt * 4 + nt) * 2 + 0) * 32 + lane];
            bH[il][nt][1] = Uhi[((kt * 4 + nt) * 2 + 1) * 32 + lane];
        }

    int gid = blockIdx.x * 512 + tid;
    if (gid < 16384) { g_hfH[0][gid] = 0u; g_hfL[0][gid] = 0u; }
    if (gid < 32768) g_hT[0][gid] = 0.f;
    __threadfence();
    grid_sync();

    const int sj = tid >> 5, sb = tid & 31;
    const int jglob = jb + sj;
    float c = 0.f;
    float bi = 0.f, bf = 0.f, bo = 0.f, bg = 0.f;
    if (tid < 256) {
        bi = __ldg(&bU[jglob]);
        bf = __ldg(&bU[H_ + jglob]);
        bo = __ldg(&bU[2 * H_ + jglob]);
        bg = __ldg(&bU[3 * H_ + jglob]);
    }
    const float* Pj = P + (size_t)jglob * R_;
    const int qb = tid & 15, qk = tid >> 4;          // q threads: tid < 128
    const int mtR   = sb >> 4;
    const int laneR = (sb & 7) * 4 + (sj >> 1);
    const int eR    = (((sb & 15) >= 8) ? 2 : 0) + (sj & 1);

    int p = 0;
    for (int t = 0; t < T_; t++) {
        float xi = 0.f, xf = 0.f, xo = 0.f, xg = 0.f;
        if (tid < 256) {
            const float* xwt = g_xw + (size_t)t * FH * B_;
            xi = __ldg(xwt + (size_t)jglob * B_ + sb);
            xf = __ldg(xwt + (size_t)(H_ + jglob) * B_ + sb);
            xo = __ldg(xwt + (size_t)(2 * H_ + jglob) * B_ + sb);
            xg = __ldg(xwt + (size_t)(3 * H_ + jglob) * B_ + sb);
        }

        // stage h_q: [k][16] from g_hT[p] (this CTA's batch half)
#pragma unroll
        for (int i = 0; i < 8; i++) {
            int idx = tid + i * 512;           // 0..4095
            int k = idx >> 2, q4 = idx & 3;
            float4 v = __ldcg((const float4*)(&g_hT[p][k * 32 + bh * 16 + q4 * 4]));
            *(float4*)(h_q + (size_t)k * 16 + q4 * 4) = v;
        }
        __syncthreads();

        float acc[2][4][4];
#pragma unroll
        for (int mt = 0; mt < 2; mt++)
#pragma unroll
            for (int nt = 0; nt < 4; nt++)
#pragma unroll
                for (int e = 0; e < 4; e++) acc[mt][nt][e] = 0.f;

        SCAN_MMA_BODY(acc, g_hfH[p], g_hfL[p], Ulo, bH, w, lane)

#pragma unroll
        for (int mt = 0; mt < 2; mt++)
#pragma unroll
            for (int nt = 0; nt < 4; nt++)
                *(float4*)(D_s + (size_t)(((w * 2 + mt) * 4 + nt) * 32 + lane) * 4)
                    = *(float4*)acc[mt][nt];

        if (tid < 128) {                       // q partial: rq row over own 128 k
            float qpart = 0.f;
#pragma unroll 4
            for (int k4 = 0; k4 < 128; k4 += 4) {
                int k = qk * 128 + k4;
                float4 bm = *(const float4*)&Bm_s[k];
                qpart = fmaf(bm.x, h_q[(size_t)(k + 0) * 16 + qb], qpart);
                qpart = fmaf(bm.y, h_q[(size_t)(k + 1) * 16 + qb], qpart);
                qpart = fmaf(bm.z, h_q[(size_t)(k + 2) * 16 + qb], qpart);
                qpart = fmaf(bm.w, h_q[(size_t)(k + 3) * 16 + qb], qpart);
            }
            q_s[qk][qb] = qpart;
        }
        __syncthreads();

        float a0 = 0.f, a1 = 0.f, a2 = 0.f, a3 = 0.f;
        if (tid < 256) {
#pragma unroll
            for (int ksv = 0; ksv < 16; ksv++) {
                const float* dd = D_s + (size_t)(((ksv * 2 + mtR) * 4) * 32 + laneR) * 4 + eR;
                a0 += dd[0];
                a1 += dd[32 * 4];
                a2 += dd[64 * 4];
                a3 += dd[96 * 4];
            }
            a0 += xi + bi; a1 += xf + bf; a2 += xo + bo; a3 += xg + bg;
        }
        if (tid < 16) {
            float q = 0.f;
#pragma unroll
            for (int s2 = 0; s2 < 8; s2++) q += q_s[s2][tid];
            int bb = bh * 16 + tid;
            float xav = __ldg(&g_xa[((size_t)t * R_ + rq) * B_ + bb]);
            __stcg(&g_s[rq * B_ + bb], xav * q);
        }
        __threadfence();
        grid_sync();

        // phase B: stage s, compute mix, update state
        ((float4*)s_s)[tid] = __ldcg(((const float4*)g_s) + tid % 512);
        __syncthreads();
        if (tid < 256) {
            float mix = 0.f;
#pragma unroll
            for (int r = 0; r < R_; r += 4) {
                float4 pv = __ldg((const float4*)(Pj + r));
                mix = fmaf(pv.x, s_s[(r + 0) * B_ + sb], mix);
                mix = fmaf(pv.y, s_s[(r + 1) * B_ + sb], mix);
                mix = fmaf(pv.z, s_s[(r + 2) * B_ + sb], mix);
                mix = fmaf(pv.w, s_s[(r + 3) * B_ + sb], mix);
            }
            float iv = sigmoidf_(a0), fv = sigmoidf_(a1);
            float ov = sigmoidf_(a2), gv = tanhf_(a3);
            c = fv * c + iv * gv + 0.1f * mix;
            float h = ov * tanhf_(c);
            store_h_frag(p ^ 1, jglob, sb, h);
            __stcg(&g_hT[p ^ 1][jglob * B_ + sb], h);
            out[((size_t)sb * T_ + t) * H_ + jglob] = h;
        }
        __threadfence();
        grid_sync();
        p ^= 1;
    }
}

// ---------------- launch -----------------------------------------------------
extern "C" void kernel_launch(void* const* d_in, const int* in_sizes, int n_in,
                              void* d_out, int out_size)
{
    (void)in_sizes; (void)n_in; (void)out_size;
    const float* x     = (const float*)d_in[0];
    const float* Ws    = (const float*)d_in[1];
    const float* bWs   = (const float*)d_in[2];
    const float* Us    = (const float*)d_in[3];
    const float* bUs   = (const float*)d_in[4];
    const float* alpha = (const float*)d_in[5];
    const float* Wm    = (const float*)d_in[6];
    const float* bWm   = (const float*)d_in[7];
    const float* Um    = (const float*)d_in[8];
    const float* bUm   = (const float*)d_in[9];
    const float* A     = (const float*)d_in[10];
    const float* Bm    = (const float*)d_in[11];
    const float* P     = (const float*)d_in[12];

    cudaFuncSetAttribute(slstm_scan, cudaFuncAttributeMaxDynamicSharedMemorySize,
                         SMEM_SL_BYTES);
    cudaFuncSetAttribute(mlstm_scan, cudaFuncAttributeMaxDynamicSharedMemorySize,
                         SMEM_ML_BYTES);
    cudaFuncSetAttribute(ffn_gemm_mma, cudaFuncAttributeMaxDynamicSharedMemorySize,
                         SMEM_GEMM_BYTES);

    dim3 gG(FH / 128, (B_ * T_) / 128);
    ffn_gemm_mma<<<gG, 512, SMEM_GEMM_BYTES>>>(x, 0, Ws, bWs);
    slstm_scan<<<NCTA, 512, SMEM_SL_BYTES>>>(Us, bUs, alpha);
    xa_gemm<<<dim3(1, T_), 128>>>(A);
    ffn_gemm_mma<<<gG, 512, SMEM_GEMM_BYTES>>>(nullptr, 1, Wm, bWm);
    mlstm_scan<<<NCTA, 512, SMEM_ML_BYTES>>>(Um, bUm, Bm, P, (float*)d_out);
}

// round 17
// speedup vs baseline: 4.9867x; 1.0891x over previous
#include <cuda_runtime.h>
#include <cuda_bf16.h>
#include <math.h>
#include <stdint.h>

#define B_   32
#define T_   512
#define D_   1024
#define H_   1024
#define R_   64
#define FH   4096
#define NCTA 128

// mma gemm dynamic smem: 2 buffers x 32 KB
#define SMEM_GEMM_BYTES 65536
// scan v6 smem (u32 units): Ulo[16384] | D2[16640 f32] (| h_q[16384 f32])
#define SMEM_SL_BYTES ((16384 + 16640) * 4)
#define SMEM_ML_BYTES ((16384 + 16640 + 16384) * 4)

// ---------------- scratch (device globals: allocation-free) ----------------
__device__ __align__(16) float g_xw[(size_t)T_ * FH * B_];   // [t][k][b]
__device__ __align__(16) float g_hs[(size_t)B_ * T_ * H_];   // [b][t][h]
__device__ __align__(16) float g_xa[(size_t)T_ * R_ * B_];   // [t][r][b]
__device__ __align__(16) float g_hT[2][H_ * B_];             // h fp32 dbl buf [j][b]
__device__ __align__(16) float g_s[R_ * B_];                 // [r][b]
// h as bf16 A-fragments (hi/lo), double buffered
__device__ __align__(16) uint32_t g_hfH[2][16384];
__device__ __align__(16) uint32_t g_hfL[2][16384];
__device__ unsigned g_bar_count = 0;
__device__ unsigned g_bar_gen   = 0;

// ---------------- software grid barrier -------------------------------------
__device__ __forceinline__ void grid_sync() {
    __syncthreads();
    if (threadIdx.x == 0) {
        volatile unsigned* vgen = &g_bar_gen;
        unsigned gen = *vgen;
        __threadfence();
        if (atomicAdd(&g_bar_count, 1u) == (unsigned)(NCTA - 1)) {
            atomicExch(&g_bar_count, 0u);
            __threadfence();
            atomicAdd(&g_bar_gen, 1u);
        } else {
            while (*vgen == gen) { }
        }
        __threadfence();
    }
    __syncthreads();
}

__device__ __forceinline__ float sigmoidf_(float x) {
    return 1.0f / (1.0f + __expf(-x));
}
__device__ __forceinline__ float tanhf_(float x) {
    float e = __expf(2.0f * x);
    return 1.0f - 2.0f / (e + 1.0f);
}

// ---- fp32 -> bf16 hi/lo split ----
__device__ __forceinline__ void split2(float x, float y, uint32_t& hp, uint32_t& lp) {
    uint32_t h;
    asm("cvt.rn.bf16x2.f32 %0, %1, %2;" : "=r"(h) : "f"(y), "f"(x));
    float xh = __uint_as_float(h << 16);
    float yh = __uint_as_float(h & 0xFFFF0000u);
    float xl = x - xh, yl = y - yh;
    uint32_t l;
    asm("cvt.rn.bf16x2.f32 %0, %1, %2;" : "=r"(l) : "f"(yl), "f"(xl));
    hp = h; lp = l;
}

// ---- warp mma m16n8k16 bf16, fp32 accumulate ----
__device__ __forceinline__ void mma_bf16(float* c, const uint32_t* a, const uint32_t* b) {
    asm volatile(
        "mma.sync.aligned.m16n8k16.row.col.f32.bf16.bf16.f32 "
        "{%0,%1,%2,%3}, {%4,%5,%6,%7}, {%8,%9}, {%0,%1,%2,%3};"
        : "+f"(c[0]), "+f"(c[1]), "+f"(c[2]), "+f"(c[3])
        : "r"(a[0]), "r"(a[1]), "r"(a[2]), "r"(a[3]), "r"(b[0]), "r"(b[1]));
}

// ============================================================================
// HMMA feedforward GEMM (R14, passing, unchanged)
// ============================================================================
__global__ void __launch_bounds__(512, 1) ffn_gemm_mma(
    const float* __restrict__ Aext, int a_is_hs,
    const float* __restrict__ W, const float* __restrict__ bias)
{
    extern __shared__ __align__(16) uint32_t smemu[];
    const float* A0 = a_is_hs ? g_hs : Aext;

    const int tid = threadIdx.x;
    const int wid = tid >> 5, lane = tid & 31;
    const int n0 = blockIdx.x * 128;
    const int m0 = blockIdx.y * 128;
    const int wm = wid >> 2, wn = wid & 3;

    const int row  = tid >> 1;
    const int half = tid & 1;
    const int isB  = (row >= 128);
    const int r    = row & 127;
    const float* srow;
    if (isB) {
        srow = W + (size_t)(n0 + r) * 1024;
    } else {
        int m = m0 + r;
        srow = A0 + ((size_t)(m & 31) * T_ + (m >> 5)) * 1024;
    }
    uint32_t sts_off[2];
#pragma unroll
    for (int j = 0; j < 2; j++) {
        int ktile = half, kb = j;
        if (isB) {
            int ntile = r >> 3, g = r & 7;
            sts_off[j] = 4096u + (uint32_t)(((ktile * 16 + ntile) * 2 + kb) * 32 + g * 4);
        } else {
            int mtile = r >> 4, gp = r & 15;
            int rb0 = gp >> 3, g = gp & 7;
            sts_off[j] = (uint32_t)(((ktile * 8 + mtile) * 4 + rb0 + 2 * kb) * 32 + g * 4);
        }
    }
    const float* sbase = srow + half * 16;

    {
#pragma unroll
        for (int j = 0; j < 2; j++) {
            float4 v0 = __ldg((const float4*)(sbase + j * 8));
            float4 v1 = __ldg((const float4*)(sbase + j * 8 + 4));
            uint32_t h0, h1, h2, h3, l0, l1, l2, l3;
            split2(v0.x, v0.y, h0, l0); split2(v0.z, v0.w, h1, l1);
            split2(v1.x, v1.y, h2, l2); split2(v1.z, v1.w, h3, l3);
            uint32_t* q = smemu + sts_off[j];
            *(uint4*)q          = make_uint4(h0, h1, h2, h3);
            *(uint4*)(q + 2048) = make_uint4(l0, l1, l2, l3);
        }
    }
    __syncthreads();

    float acc[2][4][4];
#pragma unroll
    for (int mt = 0; mt < 2; mt++)
#pragma unroll
        for (int nt = 0; nt < 4; nt++)
#pragma unroll
            for (int e = 0; e < 4; e++) acc[mt][nt][e] = 0.f;

    for (int c = 0; c < 32; c++) {
        const uint32_t* buf = smemu + (c & 1) * 8192;
        float4 pend[4];
        if (c < 31) {
            const float* sp = sbase + (c + 1) * 32;
#pragma unroll
            for (int j = 0; j < 2; j++) {
                pend[2 * j]     = __ldg((const float4*)(sp + j * 8));
                pend[2 * j + 1] = __ldg((const float4*)(sp + j * 8 + 4));
            }
        }
#pragma unroll
        for (int kt = 0; kt < 2; kt++) {
            uint32_t aH[2][4], aL[2][4], bH[4][2], bL[4][2];
#pragma unroll
            for (int mt = 0; mt < 2; mt++) {
                const uint32_t* p = buf + ((kt * 8 + wm * 2 + mt) * 4) * 32 + lane;
#pragma unroll
                for (int rr = 0; rr < 4; rr++) {
                    aH[mt][rr] = p[rr * 32];
                    aL[mt][rr] = p[rr * 32 + 2048];
                }
            }
#pragma unroll
            for (int nt = 0; nt < 4; nt++) {
                const uint32_t* p = buf + 4096 + ((kt * 16 + wn * 4 + nt) * 2) * 32 + lane;
                bH[nt][0] = p[0];    bH[nt][1] = p[32];
                bL[nt][0] = p[2048]; bL[nt][1] = p[2080];
            }
#pragma unroll
            for (int mt = 0; mt < 2; mt++)
#pragma unroll
                for (int nt = 0; nt < 4; nt++) {
                    mma_bf16(acc[mt][nt], aH[mt], bH[nt]);
                    mma_bf16(acc[mt][nt], aH[mt], bL[nt]);
                    mma_bf16(acc[mt][nt], aL[mt], bH[nt]);
                }
        }
        if (c < 31) {
            uint32_t* nb = smemu + ((c + 1) & 1) * 8192;
#pragma unroll
            for (int j = 0; j < 2; j++) {
                uint32_t h0, h1, h2, h3, l0, l1, l2, l3;
                split2(pend[2*j].x,   pend[2*j].y,   h0, l0);
                split2(pend[2*j].z,   pend[2*j].w,   h1, l1);
                split2(pend[2*j+1].x, pend[2*j+1].y, h2, l2);
                split2(pend[2*j+1].z, pend[2*j+1].w, h3, l3);
                uint32_t* q = nb + sts_off[j];
                *(uint4*)q          = make_uint4(h0, h1, h2, h3);
                *(uint4*)(q + 2048) = make_uint4(l0, l1, l2, l3);
            }
        }
        __syncthreads();
    }

    const int g = lane >> 2, cc = lane & 3;
#pragma unroll
    for (int mt = 0; mt < 2; mt++) {
#pragma unroll
        for (int nt = 0; nt < 4; nt++) {
            int mA = m0 + wm * 32 + mt * 16 + g;
            int mB = mA + 8;
            int k0 = n0 + wn * 32 + nt * 8 + 2 * cc;
            float b0 = __ldg(&bias[k0]);
            float b1 = __ldg(&bias[k0 + 1]);
            size_t oA = ((size_t)(mA >> 5) * FH) * B_ + (mA & 31);
            size_t oB = ((size_t)(mB >> 5) * FH) * B_ + (mB & 31);
            g_xw[oA + (size_t)k0 * B_]       = acc[mt][nt][0] + b0;
            g_xw[oA + (size_t)(k0 + 1) * B_] = acc[mt][nt][1] + b1;
            g_xw[oB + (size_t)k0 * B_]       = acc[mt][nt][2] + b0;
            g_xw[oB + (size_t)(k0 + 1) * B_] = acc[mt][nt][3] + b1;
        }
    }
}

// ---------------- small GEMM for xa: out[t][r][b] (fp32, unchanged) ---------
__global__ void __launch_bounds__(128) xa_gemm(const float* __restrict__ A)
{
    const float* X = g_hs;
    float* out = g_xa;
    const int t = blockIdx.y;

    __shared__ __align__(16) float sX[32][36];
    __shared__ __align__(16) float sW[32][68];

    const int tid = threadIdx.x;
    const int b4  = (tid & 7) * 4;
    const int k4  = (tid >> 3) * 4;

    float acc[4][4];
#pragma unroll
    for (int i = 0; i < 4; i++)
#pragma unroll
        for (int jx = 0; jx < 4; jx++) acc[i][jx] = 0.f;

    for (int d0 = 0; d0 < 1024; d0 += 32) {
#pragma unroll
        for (int i = 0; i < 2; i++) {
            int qq = tid + i * 128;
            int br = qq >> 3, ds = (qq & 7) * 4;
            float4 v = *(const float4*)(X + ((size_t)br * T_ + t) * 1024 + d0 + ds);
            sX[ds + 0][br] = v.x; sX[ds + 1][br] = v.y;
            sX[ds + 2][br] = v.z; sX[ds + 3][br] = v.w;
        }
#pragma unroll
        for (int i = 0; i < 4; i++) {
            int qq = tid + i * 128;
            int kr = qq >> 3, ds = (qq & 7) * 4;
            float4 v = *(const float4*)(A + (size_t)kr * 1024 + d0 + ds);
            sW[ds + 0][kr] = v.x; sW[ds + 1][kr] = v.y;
            sW[ds + 2][kr] = v.z; sW[ds + 3][kr] = v.w;
        }
        __syncthreads();
#pragma unroll
        for (int d = 0; d < 32; d++) {
            float4 xv = *(const float4*)&sX[d][b4];
            float4 wv = *(const float4*)&sW[d][k4];
            float xs[4] = {xv.x, xv.y, xv.z, xv.w};
            float ws[4] = {wv.x, wv.y, wv.z, wv.w};
#pragma unroll
            for (int i = 0; i < 4; i++)
#pragma unroll
                for (int jx = 0; jx < 4; jx++)
                    acc[i][jx] = fmaf(ws[i], xs[jx], acc[i][jx]);
        }
        __syncthreads();
    }
#pragma unroll
    for (int i = 0; i < 4; i++) {
        float4 r = make_float4(acc[i][0], acc[i][1], acc[i][2], acc[i][3]);
        *(float4*)(out + ((size_t)t * R_ + (k4 + i)) * B_ + b4) = r;
    }
}

// ============================================================================
// Scan v6 common (U frags, mma body, h-frag store: same conventions as v5)
// ============================================================================
__device__ __forceinline__ void stage_U_frags(
    uint32_t* Uhi, uint32_t* Ulo, const float* __restrict__ U, int jb, int tid)
{
#pragma unroll
    for (int i = 0; i < 8; i++) {
        int tk = tid + i * 512;
        int n  = tk & 31;
        int kt = (tk >> 5) & 63;
        int kb = tk >> 11;
        const float* src = U + ((size_t)((n >> 3) * H_ + jb + (n & 7))) * H_
                             + kt * 16 + kb * 8;
        float4 v0 = __ldg((const float4*)src);
        float4 v1 = __ldg((const float4*)(src + 4));
        uint32_t h0, h1, h2, h3, l0, l1, l2, l3;
        split2(v0.x, v0.y, h0, l0); split2(v0.z, v0.w, h1, l1);
        split2(v1.x, v1.y, h2, l2); split2(v1.z, v1.w, h3, l3);
        uint32_t word = (uint32_t)(((kt * 4 + (n >> 3)) * 2 + kb) * 32 + (n & 7) * 4);
        *(uint4*)(Uhi + word) = make_uint4(h0, h1, h2, h3);
        *(uint4*)(Ulo + word) = make_uint4(l0, l1, l2, l3);
    }
}

#define SCAN_MMA_BODY(acc, hfH, hfL, Ulo, bH, w, lane)                         \
    _Pragma("unroll")                                                          \
    for (int il = 0; il < 4; il++) {                                           \
        int kt = (w << 2) + il;                                                \
        uint4 ah0 = __ldcg(((const uint4*)hfH) + (kt * 2 + 0) * 32 + lane);    \
        uint4 ah1 = __ldcg(((const uint4*)hfH) + (kt * 2 + 1) * 32 + lane);    \
        uint4 al0 = __ldcg(((const uint4*)hfL) + (kt * 2 + 0) * 32 + lane);    \
        uint4 al1 = __ldcg(((const uint4*)hfL) + (kt * 2 + 1) * 32 + lane);    \
        _Pragma("unroll")                                                      \
        for (int nt = 0; nt < 4; nt++) {                                       \
            uint32_t bl[2];                                                    \
            bl[0] = Ulo[((kt * 4 + nt) * 2 + 0) * 32 + lane];                  \
            bl[1] = Ulo[((kt * 4 + nt) * 2 + 1) * 32 + lane];                  \
            mma_bf16(acc[0][nt], &ah0.x, bH[il][nt]);                          \
            mma_bf16(acc[0][nt], &ah0.x, bl);                                  \
            mma_bf16(acc[0][nt], &al0.x, bH[il][nt]);                          \
            mma_bf16(acc[1][nt], &ah1.x, bH[il][nt]);                          \
            mma_bf16(acc[1][nt], &ah1.x, bl);                                  \
            mma_bf16(acc[1][nt], &al1.x, bH[il][nt]);                          \
        }                                                                      \
    }

// conflict-free D reduction layout: D2[rid][kcol], rid = jl*32 + b (0..255),
// kcol = w*4 + nt (0..63), row stride 65 floats. Reader thread tid<256 has
// rid == tid -> bank = (tid + kcol) % 32 : lane permutation, conflict-free.
#define SCAN_D2_SCATTER(D2, acc, w, lane)                                      \
    _Pragma("unroll")                                                          \
    for (int mt = 0; mt < 2; mt++)                                             \
        _Pragma("unroll")                                                      \
        for (int nt = 0; nt < 4; nt++)                                         \
            _Pragma("unroll")                                                  \
            for (int e = 0; e < 4; e++) {                                      \
                int jl = 2 * (lane & 3) + (e & 1);                             \
                int bb = mt * 16 + 8 * (e >> 1) + (lane >> 2);                 \
                D2[(jl * 32 + bb) * 65 + w * 4 + nt] = acc[mt][nt][e];         \
            }

__device__ __forceinline__ void store_h_frag(int p_next, int jglob, int sb, float h) {
    int kt = jglob >> 4, kk = jglob & 15;
    int mt = sb >> 4,    mi = sb & 15;
    int reg = ((mi >= 8) ? 1 : 0) + ((kk >= 8) ? 2 : 0);
    int lw  = (mi & 7) * 4 + ((kk & 7) >> 1);
    int word = ((kt * 2 + mt) * 32 + lw) * 4 + reg;
    uint32_t hp, lp;
    split2(h, 0.f, hp, lp);
    ((uint16_t*)g_hfH[p_next])[word * 2 + (kk & 1)] = (uint16_t)(hp & 0xFFFFu);
    ((uint16_t*)g_hfL[p_next])[word * 2 + (kk & 1)] = (uint16_t)(lp & 0xFFFFu);
}

// ============================================================================
// sLSTM scan v6
// ============================================================================
__global__ void __launch_bounds__(512, 1) slstm_scan(
    const float* __restrict__ U, const float* __restrict__ bU,
    const float* __restrict__ alpha)
{
    extern __shared__ __align__(16) uint32_t dyn[];
    uint32_t* Ulo = dyn;                    // 16384 u32
    float*    D2  = (float*)(dyn + 16384);  // 16640 f32 (aliases U-hi staging)
    uint32_t* Uhi = dyn + 16384;

    const int tid = threadIdx.x, w = tid >> 5, lane = tid & 31;
    const int jb = blockIdx.x * 8;

    stage_U_frags(Uhi, Ulo, U, jb, tid);
    __syncthreads();
    uint32_t bH[4][4][2];
#pragma unroll
    for (int il = 0; il < 4; il++)
#pragma unroll
        for (int nt = 0; nt < 4; nt++) {
            int kt = (w << 2) + il;
            bH[il][nt][0] = Uhi[((kt * 4 + nt) * 2 + 0) * 32 + lane];
            bH[il][nt][1] = Uhi[((kt * 4 + nt) * 2 + 1) * 32 + lane];
        }

    int gid = blockIdx.x * 512 + tid;
    if (gid < 16384) { g_hfH[0][gid] = 0u; g_hfL[0][gid] = 0u; }
    __threadfence();
    grid_sync();

    const int sj = tid >> 5, sb = tid & 31;     // gate threads: tid < 256
    const int jglob = jb + sj;
    float c = 0.f;
    float balph = 0.f, bi = 0.f, bf = 0.f, bo = 0.f, bg = 0.f;
    if (tid < 256) {
        balph = __ldg(&alpha[jglob]);
        bi = __ldg(&bU[jglob]);
        bf = __ldg(&bU[H_ + jglob]);
        bo = __ldg(&bU[2 * H_ + jglob]);
        bg = __ldg(&bU[3 * H_ + jglob]);
    }

    // prefetch xw for t=0
    float xi = 0.f, xf = 0.f, xo = 0.f, xg = 0.f;
    if (tid < 256) {
        xi = __ldg(g_xw + (size_t)jglob * B_ + sb);
        xf = __ldg(g_xw + (size_t)(H_ + jglob) * B_ + sb);
        xo = __ldg(g_xw + (size_t)(2 * H_ + jglob) * B_ + sb);
        xg = __ldg(g_xw + (size_t)(3 * H_ + jglob) * B_ + sb);
    }

    int p = 0;
    for (int t = 0; t < T_; t++) {
        float acc[2][4][4];
#pragma unroll
        for (int mt = 0; mt < 2; mt++)
#pragma unroll
            for (int nt = 0; nt < 4; nt++)
#pragma unroll
                for (int e = 0; e < 4; e++) acc[mt][nt][e] = 0.f;

        SCAN_MMA_BODY(acc, g_hfH[p], g_hfL[p], Ulo, bH, w, lane)
        SCAN_D2_SCATTER(D2, acc, w, lane)
        __syncthreads();

        float nxi = 0.f, nxf = 0.f, nxo = 0.f, nxg = 0.f;
        if (tid < 256) {
            float a[4] = {0.f, 0.f, 0.f, 0.f};
            const float* rrow = D2 + (size_t)tid * 65;
#pragma unroll
            for (int j4 = 0; j4 < 64; j4 += 4) {
                a[0] += rrow[j4 + 0];
                a[1] += rrow[j4 + 1];
                a[2] += rrow[j4 + 2];
                a[3] += rrow[j4 + 3];
            }
            float iv = sigmoidf_(xi + bi + a[0]);
            float fv = sigmoidf_(xf + bf + a[1]);
            float ov = sigmoidf_(xo + bo + a[2]);
            float gv = tanhf_(xg + bg + a[3]);
            c = balph * (fv * c + iv * gv);
            float h = ov * tanhf_(c);
            store_h_frag(p ^ 1, jglob, sb, h);
            g_hs[((size_t)sb * T_ + t) * H_ + jglob] = h;
            if (t + 1 < T_) {                    // prefetch next xw behind barrier
                const float* xwt = g_xw + (size_t)(t + 1) * FH * B_;
                nxi = __ldg(xwt + (size_t)jglob * B_ + sb);
                nxf = __ldg(xwt + (size_t)(H_ + jglob) * B_ + sb);
                nxo = __ldg(xwt + (size_t)(2 * H_ + jglob) * B_ + sb);
                nxg = __ldg(xwt + (size_t)(3 * H_ + jglob) * B_ + sb);
            }
        }
        __threadfence();
        grid_sync();
        xi = nxi; xf = nxf; xo = nxo; xg = nxg;
        p ^= 1;
    }
}

// ============================================================================
// mLSTM scan v6
// ============================================================================
__global__ void __launch_bounds__(512, 1) mlstm_scan(
    const float* __restrict__ U, const float* __restrict__ bU,
    const float* __restrict__ Bm, const float* __restrict__ P,
    float* __restrict__ out)
{
    extern __shared__ __align__(16) uint32_t dyn[];
    uint32_t* Ulo = dyn;                          // 16384 u32
    float*    D2  = (float*)(dyn + 16384);        // 16640 f32 (aliases U-hi)
    uint32_t* Uhi = dyn + 16384;
    float*    h_q = (float*)(dyn + 16384 + 16640);// 16384 f32 [k][16]
    float*    s_s = h_q;                          // phase-B alias (2048 f32)

    __shared__ float Bm_s[1024];
    __shared__ float q_s[8][16];

    const int tid = threadIdx.x, w = tid >> 5, lane = tid & 31;
    const int jb = blockIdx.x * 8;
    const int rq = blockIdx.x & 63;
    const int bh = blockIdx.x >> 6;

    stage_U_frags(Uhi, Ulo, U, jb, tid);
    {
        const float* Bmr = Bm + (size_t)rq * H_;
        for (int i = tid; i < 256; i += 512)
            *(float4*)&Bm_s[i * 4] = __ldg((const float4*)(Bmr + i * 4));
    }
    __syncthreads();
    uint32_t bH[4][4][2];
#pragma unroll
    for (int il = 0; il < 4; il++)
#pragma unroll
        for (int nt = 0; nt < 4; nt++) {
            int kt = (w << 2) + il;
            bH[il][nt][0] = Uhi[((kt * 4 + nt) * 2 + 0) * 32 + lane];
            bH[il][nt][1] = Uhi[((kt * 4 + nt) * 2 + 1) * 32 + lane];
        }

    int gid = blockIdx.x * 512 + tid;
    if (gid < 16384) { g_hfH[0][gid] = 0u; g_hfL[0][gid] = 0u; }
    if (gid < 32768) g_hT[0][gid] = 0.f;
    __threadfence();
    grid_sync();

    const int sj = tid >> 5, sb = tid & 31;
    const int jglob = jb + sj;
    float c = 0.f;
    float bi = 0.f, bf = 0.f, bo = 0.f, bg = 0.f;
    if (tid < 256) {
        bi = __ldg(&bU[jglob]);
        bf = __ldg(&bU[H_ + jglob]);
        bo = __ldg(&bU[2 * H_ + jglob]);
        bg = __ldg(&bU[3 * H_ + jglob]);
    }
    const float* Pj = P + (size_t)jglob * R_;
    const int qb = tid & 15, qk = tid >> 4;          // q threads: tid < 128

    float xi = 0.f, xf = 0.f, xo = 0.f, xg = 0.f;
    if (tid < 256) {
        xi = __ldg(g_xw + (size_t)jglob * B_ + sb);
        xf = __ldg(g_xw + (size_t)(H_ + jglob) * B_ + sb);
        xo = __ldg(g_xw + (size_t)(2 * H_ + jglob) * B_ + sb);
        xg = __ldg(g_xw + (size_t)(3 * H_ + jglob) * B_ + sb);
    }

    int p = 0;
    for (int t = 0; t < T_; t++) {
        // stage h_q: [k][16] from g_hT[p] (this CTA's batch half)
#pragma unroll
        for (int i = 0; i < 8; i++) {
            int idx = tid + i * 512;
            int k = idx >> 2, q4 = idx & 3;
            float4 v = __ldcg((const float4*)(&g_hT[p][k * 32 + bh * 16 + q4 * 4]));
            *(float4*)(h_q + (size_t)k * 16 + q4 * 4) = v;
        }
        __syncthreads();

        float acc[2][4][4];
#pragma unroll
        for (int mt = 0; mt < 2; mt++)
#pragma unroll
            for (int nt = 0; nt < 4; nt++)
#pragma unroll
                for (int e = 0; e < 4; e++) acc[mt][nt][e] = 0.f;

        SCAN_MMA_BODY(acc, g_hfH[p], g_hfL[p], Ulo, bH, w, lane)
        SCAN_D2_SCATTER(D2, acc, w, lane)

        if (tid < 128) {                        // q partial: rq row, own 128 k
            float qpart = 0.f;
#pragma unroll 4
            for (int k4 = 0; k4 < 128; k4 += 4) {
                int k = qk * 128 + k4;
                float4 bm = *(const float4*)&Bm_s[k];
                qpart = fmaf(bm.x, h_q[(size_t)(k + 0) * 16 + qb], qpart);
                qpart = fmaf(bm.y, h_q[(size_t)(k + 1) * 16 + qb], qpart);
                qpart = fmaf(bm.z, h_q[(size_t)(k + 2) * 16 + qb], qpart);
                qpart = fmaf(bm.w, h_q[(size_t)(k + 3) * 16 + qb], qpart);
            }
            q_s[qk][qb] = qpart;
        }
        __syncthreads();

        float a0 = 0.f, a1 = 0.f, a2 = 0.f, a3 = 0.f;
        if (tid < 256) {
            const float* rrow = D2 + (size_t)tid * 65;
#pragma unroll
            for (int j4 = 0; j4 < 64; j4 += 4) {
                a0 += rrow[j4 + 0];
                a1 += rrow[j4 + 1];
                a2 += rrow[j4 + 2];
                a3 += rrow[j4 + 3];
            }
            a0 += xi + bi; a1 += xf + bf; a2 += xo + bo; a3 += xg + bg;
        }
        if (tid < 16) {
            float q = 0.f;
#pragma unroll
            for (int s2 = 0; s2 < 8; s2++) q += q_s[s2][tid];
            int bb = bh * 16 + tid;
            float xav = __ldg(&g_xa[((size_t)t * R_ + rq) * B_ + bb]);
            __stcg(&g_s[rq * B_ + bb], xav * q);
        }
        __threadfence();
        grid_sync();

        // phase B: stage s, compute mix, update state
        ((float4*)s_s)[tid] = __ldcg(((const float4*)g_s) + (tid & 511));
        __syncthreads();
        float nxi = 0.f, nxf = 0.f, nxo = 0.f, nxg = 0.f;
        if (tid < 256) {
            float mix = 0.f;
#pragma unroll
            for (int r = 0; r < R_; r += 4) {
                float4 pv = __ldg((const float4*)(Pj + r));
                mix = fmaf(pv.x, s_s[(r + 0) * B_ + sb], mix);
                mix = fmaf(pv.y, s_s[(r + 1) * B_ + sb], mix);
                mix = fmaf(pv.z, s_s[(r + 2) * B_ + sb], mix);
                mix = fmaf(pv.w, s_s[(r + 3) * B_ + sb], mix);
            }
            float iv = sigmoidf_(a0), fv = sigmoidf_(a1);
            float ov = sigmoidf_(a2), gv = tanhf_(a3);
            c = fv * c + iv * gv + 0.1f * mix;
            float h = ov * tanhf_(c);
            store_h_frag(p ^ 1, jglob, sb, h);
            __stcg(&g_hT[p ^ 1][jglob * B_ + sb], h);
            out[((size_t)sb * T_ + t) * H_ + jglob] = h;
            if (t + 1 < T_) {
                const float* xwt = g_xw + (size_t)(t + 1) * FH * B_;
                nxi = __ldg(xwt + (size_t)jglob * B_ + sb);
                nxf = __ldg(xwt + (size_t)(H_ + jglob) * B_ + sb);
                nxo = __ldg(xwt + (size_t)(2 * H_ + jglob) * B_ + sb);
                nxg = __ldg(xwt + (size_t)(3 * H_ + jglob) * B_ + sb);
            }
        }
        __threadfence();
        grid_sync();
        xi = nxi; xf = nxf; xo = nxo; xg = nxg;
        p ^= 1;
    }
}

// ---------------- launch -----------------------------------------------------
extern "C" void kernel_launch(void* const* d_in, const int* in_sizes, int n_in,
                              void* d_out, int out_size)
{
    (void)in_sizes; (void)n_in; (void)out_size;
    const float* x     = (const float*)d_in[0];
    const float* Ws    = (const float*)d_in[1];
    const float* bWs   = (const float*)d_in[2];
    const float* Us    = (const float*)d_in[3];
    const float* bUs   = (const float*)d_in[4];
    const float* alpha = (const float*)d_in[5];
    const float* Wm    = (const float*)d_in[6];
    const float* bWm   = (const float*)d_in[7];
    const float* Um    = (const float*)d_in[8];
    const float* bUm   = (const float*)d_in[9];
    const float* A     = (const float*)d_in[10];
    const float* Bm    = (const float*)d_in[11];
    const float* P     = (const float*)d_in[12];

    cudaFuncSetAttribute(slstm_scan, cudaFuncAttributeMaxDynamicSharedMemorySize,
                         SMEM_SL_BYTES);
    cudaFuncSetAttribute(mlstm_scan, cudaFuncAttributeMaxDynamicSharedMemorySize,
                         SMEM_ML_BYTES);
    cudaFuncSetAttribute(ffn_gemm_mma, cudaFuncAttributeMaxDynamicSharedMemorySize,
                         SMEM_GEMM_BYTES);

    dim3 gG(FH / 128, (B_ * T_) / 128);
    ffn_gemm_mma<<<gG, 512, SMEM_GEMM_BYTES>>>(x, 0, Ws, bWs);
    slstm_scan<<<NCTA, 512, SMEM_SL_BYTES>>>(Us, bUs, alpha);
    xa_gemm<<<dim3(1, T_), 128>>>(A);
    ffn_gemm_mma<<<gG, 512, SMEM_GEMM_BYTES>>>(nullptr, 1, Wm, bWm);
    mlstm_scan<<<NCTA, 512, SMEM_ML_BYTES>>>(Um, bUm, Bm, P, (float*)d_out);
}